// round 1
// baseline (speedup 1.0000x reference)
#include <cuda_runtime.h>
#include <math.h>

// ---------------- problem constants ----------------
#define BB 4
#define SS 2048
#define DIMC 128
#define HH 8
#define DHD 128
#define DEPTH 2
#define NCLS 10
#define MF 128           // FAVOR features
#define CHUNK 128
#define NC (SS/CHUNK)    // 16
#define INNER (HH*DHD)   // 1024
#define FFD 512
#define BSR (BB*SS)      // 8192 rows
#define BHS (BB*HH*SS)   // 65536
#define NBH (BB*HH)      // 32

#define NORMC 0.29730177875068026f   // 128^-0.25
#define RATIOC 0.08838834764831845f  // 128^-0.5

// ---------------- device scratch (no allocs allowed) ----------------
__device__ float g_h  [BSR*DIMC];
__device__ float g_y  [BSR*DIMC];
__device__ float g_q  [BSR*INNER];
__device__ float g_k  [BSR*INNER];
__device__ float g_v  [BSR*INNER];
__device__ float g_qp [(size_t)NBH*SS*MF];   // dd then qp  [B,H,S,M]
__device__ float g_kp [(size_t)NBH*SS*MF];   // dd then kp
__device__ float g_diagq[BHS];
__device__ float g_diagk[BHS];
__device__ float g_stab[NBH];
__device__ float g_o  [BSR*INNER];           // [B,S,H,DH]
__device__ float g_den[BHS];
__device__ float g_kvc[(size_t)NBH*NC*MF*DHD];
__device__ float g_kvp[(size_t)NBH*NC*MF*DHD];
__device__ float g_ksc[NBH*NC*MF];
__device__ float g_ksp[NBH*NC*MF];
__device__ float g_ff [BSR*FFD];
__device__ float g_pool[BB*DIMC];

// ---------------- embed: h = x*lin_w + lin_b + pe ----------------
__global__ void k_embed(const float* __restrict__ x, const float* __restrict__ lw,
                        const float* __restrict__ lb, const float* __restrict__ pe)
{
    int r = blockIdx.x;            // 0..BSR-1  (b*S+s)
    int t = threadIdx.x;           // 0..127
    int s = r % SS;
    g_h[(size_t)r*DIMC + t] = x[r]*lw[t] + lb[t] + pe[(size_t)s*DIMC + t];
}

// ---------------- layernorm: y = LN(h)*g + b ----------------
__global__ void k_ln(const float* __restrict__ in, const float* __restrict__ g,
                     const float* __restrict__ b, float* __restrict__ out)
{
    __shared__ float red[128];
    int r = blockIdx.x, t = threadIdx.x;
    float v = in[(size_t)r*DIMC + t];
    red[t] = v; __syncthreads();
    #pragma unroll
    for (int o = 64; o > 0; o >>= 1) { if (t < o) red[t] += red[t+o]; __syncthreads(); }
    float mu = red[0] * (1.0f/DIMC);
    __syncthreads();
    float d = v - mu;
    red[t] = d*d; __syncthreads();
    #pragma unroll
    for (int o = 64; o > 0; o >>= 1) { if (t < o) red[t] += red[t+o]; __syncthreads(); }
    float var = red[0] * (1.0f/DIMC);
    out[(size_t)r*DIMC + t] = d * rsqrtf(var + 1e-5f) * g[t] + b[t];
}

// ---------------- generic SGEMM  C[M,N] (+)= A[M,K] @ W[K,N] (+bias)(+gelu/resid)
// MODE 0: C = acc (+bias)   MODE 1: C = gelu(acc+bias)   MODE 2: C = C + acc + bias
template<int MODE>
__global__ __launch_bounds__(256) void k_sgemm(const float* __restrict__ A,
                                               const float* __restrict__ W,
                                               const float* __restrict__ bias,
                                               float* __restrict__ C,
                                               int Mrows, int K, int N)
{
    __shared__ __align__(16) float As[16][65];
    __shared__ __align__(16) float Bs[16][68];
    int t  = threadIdx.x;
    int tx = t & 15, ty = t >> 4;
    int row0 = blockIdx.y * 64, col0 = blockIdx.x * 64;
    float acc[4][4] = {};
    int la_m = t >> 2, la_k = (t & 3) << 2;
    int lb_k = t >> 4, lb_n = (t & 15) << 2;
    const float* Aptr = A + (size_t)(row0 + la_m)*K + la_k;
    const float* Bptr = W + (size_t)lb_k*N + col0 + lb_n;
    for (int k0 = 0; k0 < K; k0 += 16) {
        float4 av = *(const float4*)(Aptr + k0);
        As[la_k+0][la_m] = av.x; As[la_k+1][la_m] = av.y;
        As[la_k+2][la_m] = av.z; As[la_k+3][la_m] = av.w;
        float4 bv = *(const float4*)(Bptr + (size_t)k0*N);
        *(float4*)&Bs[lb_k][lb_n] = bv;
        __syncthreads();
        #pragma unroll
        for (int kk = 0; kk < 16; kk++) {
            float a[4], bvv[4];
            #pragma unroll
            for (int i = 0; i < 4; i++) a[i]   = As[kk][ty*4+i];
            #pragma unroll
            for (int j = 0; j < 4; j++) bvv[j] = Bs[kk][tx*4+j];
            #pragma unroll
            for (int i = 0; i < 4; i++)
                #pragma unroll
                for (int j = 0; j < 4; j++) acc[i][j] += a[i]*bvv[j];
        }
        __syncthreads();
    }
    #pragma unroll
    for (int i = 0; i < 4; i++) {
        int r = row0 + ty*4 + i;
        #pragma unroll
        for (int j = 0; j < 4; j++) {
            int c = col0 + tx*4 + j;
            float val = acc[i][j];
            if (bias) val += bias[c];
            if (MODE == 1) {
                float xx = val;
                val = 0.5f*xx*(1.0f + tanhf(0.7978845608028654f*(xx + 0.044715f*xx*xx*xx)));
            }
            size_t idx = (size_t)r*N + c;
            if (MODE == 2) val += C[idx];
            C[idx] = val;
        }
    }
}

// ---------------- FAVOR features pass 1: dd = (q*norm) @ proj^T, diag = 0.5*||q*norm||^2
// src layout [B,S,H,DH]; dd out layout [B,H,S,M]
__global__ __launch_bounds__(256) void k_features(const float* __restrict__ src,
                                                  const float* __restrict__ proj,
                                                  float* __restrict__ dd,
                                                  float* __restrict__ diag)
{
    __shared__ __align__(16) float As[16][65];
    __shared__ __align__(16) float Ps[16][132];
    int bh = blockIdx.y;
    int s0 = blockIdx.x * 64;
    int b = bh / HH, hh = bh % HH;
    int t = threadIdx.x;
    int tx = t & 15, ty = t >> 4;
    float acc[4][8] = {};
    float dacc = 0.f;
    int la_i = t >> 2, la_k = (t & 3) << 2;
    int lp_m = t >> 1, lp_k = (t & 1) << 3;
    const float* srow = src + ((size_t)(b*SS + s0 + la_i)*HH + hh)*DHD + la_k;
    const float* prow = proj + (size_t)lp_m*DHD + lp_k;
    for (int d0 = 0; d0 < DHD; d0 += 16) {
        float4 av = *(const float4*)(srow + d0);
        As[la_k+0][la_i] = av.x*NORMC; As[la_k+1][la_i] = av.y*NORMC;
        As[la_k+2][la_i] = av.z*NORMC; As[la_k+3][la_i] = av.w*NORMC;
        float4 p0 = *(const float4*)(prow + d0);
        float4 p1 = *(const float4*)(prow + d0 + 4);
        Ps[lp_k+0][lp_m]=p0.x; Ps[lp_k+1][lp_m]=p0.y; Ps[lp_k+2][lp_m]=p0.z; Ps[lp_k+3][lp_m]=p0.w;
        Ps[lp_k+4][lp_m]=p1.x; Ps[lp_k+5][lp_m]=p1.y; Ps[lp_k+6][lp_m]=p1.z; Ps[lp_k+7][lp_m]=p1.w;
        __syncthreads();
        if (t < 64) {
            #pragma unroll
            for (int kk = 0; kk < 16; kk++) { float v = As[kk][t]; dacc += v*v; }
        }
        #pragma unroll
        for (int kk = 0; kk < 16; kk++) {
            float a[4], p[8];
            #pragma unroll
            for (int i = 0; i < 4; i++) a[i] = As[kk][ty*4+i];
            #pragma unroll
            for (int j = 0; j < 8; j++) p[j] = Ps[kk][tx*8+j];
            #pragma unroll
            for (int i = 0; i < 4; i++)
                #pragma unroll
                for (int j = 0; j < 8; j++) acc[i][j] += a[i]*p[j];
        }
        __syncthreads();
    }
    #pragma unroll
    for (int i = 0; i < 4; i++) {
        size_t base = ((size_t)bh*SS + s0 + ty*4 + i)*MF + tx*8;
        #pragma unroll
        for (int j = 0; j < 8; j++) dd[base + j] = acc[i][j];
    }
    if (t < 64) diag[(size_t)bh*SS + s0 + t] = 0.5f*dacc;
}

// ---------------- key stabilizer: max over (s,m) per (b,h) ----------------
__global__ void k_stab(const float* __restrict__ dd, float* __restrict__ stab)
{
    __shared__ float red[256];
    int bh = blockIdx.x, t = threadIdx.x;
    const float* p = dd + (size_t)bh*SS*MF;
    float m = -1e30f;
    for (int i = t; i < SS*MF; i += 256) m = fmaxf(m, p[i]);
    red[t] = m; __syncthreads();
    #pragma unroll
    for (int o = 128; o > 0; o >>= 1) { if (t < o) red[t] = fmaxf(red[t], red[t+o]); __syncthreads(); }
    if (t == 0) stab[bh] = red[0];
}

// ---------------- feature exponentiation (in place over dd) ----------------
__global__ void k_featexp(float* __restrict__ dd, const float* __restrict__ diag,
                          const float* __restrict__ stab, int is_query)
{
    __shared__ float red[128];
    int r = blockIdx.x, t = threadIdx.x;
    float v = dd[(size_t)r*MF + t];
    float st;
    if (is_query) {
        red[t] = v; __syncthreads();
        #pragma unroll
        for (int o = 64; o > 0; o >>= 1) { if (t < o) red[t] = fmaxf(red[t], red[t+o]); __syncthreads(); }
        st = red[0];
    } else {
        st = stab[r / SS];
    }
    dd[(size_t)r*MF + t] = RATIOC*(expf(v - diag[r] - st) + 1e-4f);
}

// ---------------- chunk-local attention (phase A) ----------------
// per block = one (b,h,chunk): attn = tril(qi@ki^T); num_local = attn@vi -> g_o;
// den_local = rowsum(attn); kv_c = ki^T@vi; ks_c = colsum(ki)
__global__ __launch_bounds__(256) void k_chunk(const float* __restrict__ qp,
                                               const float* __restrict__ kp,
                                               const float* __restrict__ v)
{
    extern __shared__ __align__(16) float sm[];
    float* sQ = sm;                    // [128][132]  (transposed qi; later attn^T)
    float* sK = sm + 128*132;          // [128][132]  (transposed ki)
    float* sV = sK + 128*132;          // [128][64]
    int blk = blockIdx.x;
    int bh = blk / NC, c = blk % NC;
    int b = bh / HH, hh = bh % HH;
    int t = threadIdx.x;
    int tx = t & 15, ty = t >> 4;
    int i0 = ty*8, j0 = tx*8;
    const float* qbase = qp + ((size_t)bh*SS + c*CHUNK)*MF;
    const float* kbase = kp + ((size_t)bh*SS + c*CHUNK)*MF;

    #pragma unroll
    for (int rr = 0; rr < 16; rr++) {
        int f  = rr*256 + t;
        int i  = f >> 5;
        int m4 = (f & 31) << 2;
        float4 qv = *(const float4*)(qbase + (size_t)i*MF + m4);
        sQ[(m4+0)*132+i]=qv.x; sQ[(m4+1)*132+i]=qv.y; sQ[(m4+2)*132+i]=qv.z; sQ[(m4+3)*132+i]=qv.w;
        float4 kv = *(const float4*)(kbase + (size_t)i*MF + m4);
        sK[(m4+0)*132+i]=kv.x; sK[(m4+1)*132+i]=kv.y; sK[(m4+2)*132+i]=kv.z; sK[(m4+3)*132+i]=kv.w;
    }
    __syncthreads();

    float acc[8][8] = {};
    for (int m = 0; m < 128; m++) {
        float a[8], bb[8];
        #pragma unroll
        for (int ii = 0; ii < 8; ii++) a[ii]  = sQ[m*132 + i0 + ii];
        #pragma unroll
        for (int jj = 0; jj < 8; jj++) bb[jj] = sK[m*132 + j0 + jj];
        #pragma unroll
        for (int ii = 0; ii < 8; ii++)
            #pragma unroll
            for (int jj = 0; jj < 8; jj++) acc[ii][jj] += a[ii]*bb[jj];
    }
    __syncthreads();            // done reading sQ (qi)
    // store masked attn transposed into sQ space: sA[j][i]
    #pragma unroll
    for (int ii = 0; ii < 8; ii++)
        #pragma unroll
        for (int jj = 0; jj < 8; jj++)
            sQ[(j0+jj)*132 + (i0+ii)] = (j0+jj <= i0+ii) ? acc[ii][jj] : 0.f;
    __syncthreads();
    float* sA = sQ;

    if (t < 128) {
        float dsum = 0.f;
        for (int j = 0; j < 128; j++) dsum += sA[j*132 + t];
        g_den[(size_t)bh*SS + c*CHUNK + t] = dsum;
    } else {
        int m = t - 128;
        float ks = 0.f;
        for (int j = 0; j < 128; j++) ks += sK[m*132 + j];
        g_ksc[((size_t)bh*NC + c)*MF + m] = ks;
    }

    for (int tile = 0; tile < 2; tile++) {
        int d0 = tile*64;
        __syncthreads();        // protect sV across tiles
        #pragma unroll
        for (int rr = 0; rr < 8; rr++) {
            int f  = rr*256 + t;
            int j  = f >> 4;
            int d4 = (f & 15) << 2;
            *(float4*)(sV + j*64 + d4) =
                *(const float4*)(v + ((size_t)(b*SS + c*CHUNK + j)*HH + hh)*DHD + d0 + d4);
        }
        __syncthreads();
        // num_local tile
        {
            float an[8][4] = {};
            for (int j = 0; j < 128; j++) {
                float a[8], bb[4];
                #pragma unroll
                for (int ii = 0; ii < 8; ii++) a[ii] = sA[j*132 + i0 + ii];
                #pragma unroll
                for (int dd = 0; dd < 4; dd++) bb[dd] = sV[j*64 + tx*4 + dd];
                #pragma unroll
                for (int ii = 0; ii < 8; ii++)
                    #pragma unroll
                    for (int dd = 0; dd < 4; dd++) an[ii][dd] += a[ii]*bb[dd];
            }
            #pragma unroll
            for (int ii = 0; ii < 8; ii++) {
                size_t base = ((size_t)(b*SS + c*CHUNK + i0 + ii)*HH + hh)*DHD + d0 + tx*4;
                #pragma unroll
                for (int dd = 0; dd < 4; dd++) g_o[base + dd] = an[ii][dd];
            }
        }
        // kv_c tile
        {
            float ak[8][4] = {};
            int m0 = ty*8;
            for (int j = 0; j < 128; j++) {
                float a[8], bb[4];
                #pragma unroll
                for (int mm = 0; mm < 8; mm++) a[mm] = sK[(m0+mm)*132 + j];
                #pragma unroll
                for (int dd = 0; dd < 4; dd++) bb[dd] = sV[j*64 + tx*4 + dd];
                #pragma unroll
                for (int mm = 0; mm < 8; mm++)
                    #pragma unroll
                    for (int dd = 0; dd < 4; dd++) ak[mm][dd] += a[mm]*bb[dd];
            }
            #pragma unroll
            for (int mm = 0; mm < 8; mm++) {
                size_t base = ((size_t)bh*NC + c)*(MF*DHD) + (size_t)(m0+mm)*DHD + d0 + tx*4;
                #pragma unroll
                for (int dd = 0; dd < 4; dd++) g_kvc[base + dd] = ak[mm][dd];
            }
        }
    }
}

// ---------------- exclusive prefix over chunks (phase B) ----------------
__global__ void k_prefix()
{
    int bh = blockIdx.x, seg = blockIdx.y, t = threadIdx.x;
    for (int e = seg*2048 + t; e < (seg+1)*2048; e += 256) {
        float run = 0.f;
        #pragma unroll
        for (int c = 0; c < NC; c++) {
            size_t idx = ((size_t)bh*NC + c)*(MF*DHD) + e;
            g_kvp[idx] = run; run += g_kvc[idx];
        }
    }
    if (seg == 0) {
        for (int e = t; e < MF; e += 256) {
            float run = 0.f;
            #pragma unroll
            for (int c = 0; c < NC; c++) {
                size_t idx = ((size_t)bh*NC + c)*MF + e;
                g_ksp[idx] = run; run += g_ksc[idx];
            }
        }
    }
}

// ---------------- cross terms + normalization (phase C) ----------------
__global__ __launch_bounds__(256) void k_cross(const float* __restrict__ qp)
{
    extern __shared__ __align__(16) float sm[];
    float* sQ = sm;              // [128][132] transposed qi
    float* sP = sQ + 128*132;    // [128][64] kv-prefix tile
    float* sS = sP + 128*64;     // ksp [128]
    float* sD = sS + 128;        // den [128]
    int blk = blockIdx.x;
    int bh = blk / NC, c = blk % NC;
    int b = bh / HH, hh = bh % HH;
    int t = threadIdx.x;
    int tx = t & 15, ty = t >> 4;
    int i0 = ty*8;
    const float* qbase = qp + ((size_t)bh*SS + c*CHUNK)*MF;

    #pragma unroll
    for (int rr = 0; rr < 16; rr++) {
        int f  = rr*256 + t;
        int i  = f >> 5;
        int m4 = (f & 31) << 2;
        float4 qv = *(const float4*)(qbase + (size_t)i*MF + m4);
        sQ[(m4+0)*132+i]=qv.x; sQ[(m4+1)*132+i]=qv.y; sQ[(m4+2)*132+i]=qv.z; sQ[(m4+3)*132+i]=qv.w;
    }
    if (t < 128) sS[t] = g_ksp[((size_t)bh*NC + c)*MF + t];
    __syncthreads();
    if (t < 128) {
        float dc = 0.f;
        for (int m = 0; m < 128; m++) dc += sQ[m*132 + t]*sS[m];
        sD[t] = g_den[(size_t)bh*SS + c*CHUNK + t] + dc + 1e-6f;
    }
    __syncthreads();

    for (int tile = 0; tile < 2; tile++) {
        int d0 = tile*64;
        #pragma unroll
        for (int rr = 0; rr < 8; rr++) {
            int f  = rr*256 + t;
            int m  = f >> 4;
            int d4 = (f & 15) << 2;
            *(float4*)(sP + m*64 + d4) =
                *(const float4*)(g_kvp + ((size_t)bh*NC + c)*(MF*DHD) + (size_t)m*DHD + d0 + d4);
        }
        __syncthreads();
        float ac[8][4] = {};
        for (int m = 0; m < 128; m++) {
            float a[8], bb[4];
            #pragma unroll
            for (int ii = 0; ii < 8; ii++) a[ii] = sQ[m*132 + i0 + ii];
            #pragma unroll
            for (int dd = 0; dd < 4; dd++) bb[dd] = sP[m*64 + tx*4 + dd];
            #pragma unroll
            for (int ii = 0; ii < 8; ii++)
                #pragma unroll
                for (int dd = 0; dd < 4; dd++) ac[ii][dd] += a[ii]*bb[dd];
        }
        #pragma unroll
        for (int ii = 0; ii < 8; ii++) {
            float inv = 1.0f / sD[i0 + ii];
            size_t base = ((size_t)(b*SS + c*CHUNK + i0 + ii)*HH + hh)*DHD + d0 + tx*4;
            #pragma unroll
            for (int dd = 0; dd < 4; dd++)
                g_o[base + dd] = (g_o[base + dd] + ac[ii][dd]) * inv;
        }
        __syncthreads();
    }
}

// ---------------- mean pool over S ----------------
__global__ void k_pool()
{
    int b = blockIdx.x, t = threadIdx.x;
    float acc = 0.f;
    for (int s = 0; s < SS; s++) acc += g_h[((size_t)b*SS + s)*DIMC + t];
    g_pool[b*DIMC + t] = acc * (1.0f/SS);
}

// ---------------- final head [4,128]@[128,10] ----------------
__global__ void k_final(const float* __restrict__ fw, const float* __restrict__ fb,
                        float* __restrict__ out)
{
    int idx = threadIdx.x;
    if (idx < BB*NCLS) {
        int b = idx / NCLS, c = idx % NCLS;
        float acc = fb[c];
        for (int d = 0; d < DIMC; d++) acc += g_pool[b*DIMC + d]*fw[d*NCLS + c];
        out[idx] = acc;
    }
}

// ---------------- host driver ----------------
static void* sym(const void* s) { void* p = nullptr; cudaGetSymbolAddress(&p, s); return p; }

extern "C" void kernel_launch(void* const* d_in, const int* in_sizes, int n_in,
                              void* d_out, int out_size)
{
    const float* x     = (const float*)d_in[0];
    const float* lin_w = (const float*)d_in[1];
    const float* lin_b = (const float*)d_in[2];
    const float* pe    = (const float*)d_in[3];
    const float* proj  = (const float*)d_in[4];
    const float* ln1_g = (const float*)d_in[5];
    const float* ln1_b = (const float*)d_in[6];
    const float* wq    = (const float*)d_in[7];
    const float* wk    = (const float*)d_in[8];
    const float* wv    = (const float*)d_in[9];
    const float* wo    = (const float*)d_in[10];
    const float* wo_b  = (const float*)d_in[11];
    const float* ln2_g = (const float*)d_in[12];
    const float* ln2_b = (const float*)d_in[13];
    const float* ff1_w = (const float*)d_in[14];
    const float* ff1_b = (const float*)d_in[15];
    const float* ff2_w = (const float*)d_in[16];
    const float* ff2_b = (const float*)d_in[17];
    const float* fin_w = (const float*)d_in[18];
    const float* fin_b = (const float*)d_in[19];
    float* out = (float*)d_out;

    float* ph  = (float*)sym(g_h);
    float* py  = (float*)sym(g_y);
    float* pq  = (float*)sym(g_q);
    float* pk  = (float*)sym(g_k);
    float* pv  = (float*)sym(g_v);
    float* pqp = (float*)sym(g_qp);
    float* pkp = (float*)sym(g_kp);
    float* pdq = (float*)sym(g_diagq);
    float* pdk = (float*)sym(g_diagk);
    float* pst = (float*)sym(g_stab);
    float* pff = (float*)sym(g_ff);

    const int SMEM_CHUNK = (128*132*2 + 128*64) * 4;        // 167936 B
    const int SMEM_CROSS = (128*132 + 128*64 + 256) * 4;    // 101376 B
    cudaFuncSetAttribute(k_chunk, cudaFuncAttributeMaxDynamicSharedMemorySize, SMEM_CHUNK);
    cudaFuncSetAttribute(k_cross, cudaFuncAttributeMaxDynamicSharedMemorySize, SMEM_CROSS);

    k_embed<<<BSR, 128>>>(x, lin_w, lin_b, pe);

    for (int l = 0; l < DEPTH; l++) {
        const float* prj = proj + (size_t)l*MF*DHD;

        k_ln<<<BSR, 128>>>(ph, ln1_g + l*DIMC, ln1_b + l*DIMC, py);

        // QKV projections
        k_sgemm<0><<<dim3(INNER/64, BSR/64), 256>>>(py, wq + (size_t)l*DIMC*INNER, nullptr, pq, BSR, DIMC, INNER);
        k_sgemm<0><<<dim3(INNER/64, BSR/64), 256>>>(py, wk + (size_t)l*DIMC*INNER, nullptr, pk, BSR, DIMC, INNER);
        k_sgemm<0><<<dim3(INNER/64, BSR/64), 256>>>(py, wv + (size_t)l*DIMC*INNER, nullptr, pv, BSR, DIMC, INNER);

        // FAVOR+ features
        k_features<<<dim3(SS/64, NBH), 256>>>(pq, prj, pqp, pdq);
        k_features<<<dim3(SS/64, NBH), 256>>>(pk, prj, pkp, pdk);
        k_stab<<<NBH, 256>>>(pkp, pst);
        k_featexp<<<BHS, 128>>>(pqp, pdq, pst, 1);
        k_featexp<<<BHS, 128>>>(pkp, pdk, pst, 0);

        // chunked causal linear attention
        k_chunk<<<NBH*NC, 256, SMEM_CHUNK>>>(pqp, pkp, pv);
        k_prefix<<<dim3(NBH, 8), 256>>>();
        k_cross<<<NBH*NC, 256, SMEM_CROSS>>>(pqp);

        // output projection + residual
        k_sgemm<2><<<dim3(DIMC/64, BSR/64), 256>>>((float*)sym(g_o), wo + (size_t)l*INNER*DIMC,
                                                   wo_b + l*DIMC, ph, BSR, INNER, DIMC);
        // FFN
        k_ln<<<BSR, 128>>>(ph, ln2_g + l*DIMC, ln2_b + l*DIMC, py);
        k_sgemm<1><<<dim3(FFD/64, BSR/64), 256>>>(py, ff1_w + (size_t)l*DIMC*FFD, ff1_b + l*FFD, pff, BSR, DIMC, FFD);
        k_sgemm<2><<<dim3(DIMC/64, BSR/64), 256>>>(pff, ff2_w + (size_t)l*FFD*DIMC, ff2_b + l*DIMC, ph, BSR, FFD, DIMC);
    }

    k_pool<<<BB, 128>>>();
    k_final<<<1, 64>>>(fin_w, fin_b, out);
}

// round 2
// speedup vs baseline: 1.1411x; 1.1411x over previous
#include <cuda_runtime.h>
#include <math.h>

// ---------------- problem constants ----------------
#define BB 4
#define SS 2048
#define DIMC 128
#define HH 8
#define DHD 128
#define DEPTH 2
#define NCLS 10
#define MF 128
#define CHUNK 128
#define NC 16
#define INNER 1024
#define FFD 512
#define BSR 8192
#define BHS 65536
#define NBH 32

#define NORMC 0.29730177875068026f
#define RATIOC 0.08838834764831845f

// ---------------- device scratch ----------------
__device__ float g_h  [BSR*DIMC];
__device__ float g_y  [BSR*DIMC];
__device__ float g_q  [BSR*INNER];
__device__ float g_k  [BSR*INNER];
__device__ float g_v  [BSR*INNER];
__device__ float g_qp [(size_t)NBH*SS*MF];
__device__ float g_kp [(size_t)NBH*SS*MF];
__device__ float g_diagk[BHS];
__device__ float g_bmax[NBH*16];
__device__ float g_stab[NBH];
__device__ float g_o  [BSR*INNER];
__device__ float g_den[BHS];
__device__ float g_kvc[(size_t)NBH*NC*MF*DHD];
__device__ float g_kvp[(size_t)NBH*NC*MF*DHD];
__device__ float g_ksc[NBH*NC*MF];
__device__ float g_ksp[NBH*NC*MF];
__device__ float g_ff [BSR*FFD];
__device__ float g_pp [BB*16*DIMC];

// ---------------- embed: h = x*lin_w + lin_b + pe ----------------
__global__ void k_embed(const float* __restrict__ x, const float* __restrict__ lw,
                        const float* __restrict__ lb, const float* __restrict__ pe)
{
    int warp = threadIdx.x >> 5, lane = threadIdx.x & 31;
    int r = blockIdx.x*8 + warp;
    float xv = x[r];
    float4 l4 = ((const float4*)lw)[lane];
    float4 b4 = ((const float4*)lb)[lane];
    float4 p4 = ((const float4*)(pe + (size_t)(r % SS)*DIMC))[lane];
    float4 o4 = { xv*l4.x + b4.x + p4.x, xv*l4.y + b4.y + p4.y,
                  xv*l4.z + b4.z + p4.z, xv*l4.w + b4.w + p4.w };
    ((float4*)(g_h + (size_t)r*DIMC))[lane] = o4;
}

// ---------------- warp-per-row layernorm ----------------
__global__ void k_ln(const float* __restrict__ in, const float* __restrict__ g,
                     const float* __restrict__ b, float* __restrict__ out)
{
    int warp = threadIdx.x >> 5, lane = threadIdx.x & 31;
    int r = blockIdx.x*8 + warp;
    float4 v = ((const float4*)(in + (size_t)r*DIMC))[lane];
    float s = v.x + v.y + v.z + v.w;
    #pragma unroll
    for (int o = 16; o > 0; o >>= 1) s += __shfl_xor_sync(0xffffffffu, s, o);
    float mu = s * (1.0f/DIMC);
    float dx = v.x-mu, dy = v.y-mu, dz = v.z-mu, dw = v.w-mu;
    float q = dx*dx + dy*dy + dz*dz + dw*dw;
    #pragma unroll
    for (int o = 16; o > 0; o >>= 1) q += __shfl_xor_sync(0xffffffffu, q, o);
    float inv = rsqrtf(q*(1.0f/DIMC) + 1e-5f);
    float4 gv = ((const float4*)g)[lane];
    float4 bv = ((const float4*)b)[lane];
    float4 o4 = { dx*inv*gv.x + bv.x, dy*inv*gv.y + bv.y,
                  dz*inv*gv.z + bv.z, dw*inv*gv.w + bv.w };
    ((float4*)(out + (size_t)r*DIMC))[lane] = o4;
}

// ---------------- 128x128x16 double-buffered SGEMM, 8x8 micro ----------------
// MODE 0: C=acc(+bias)  MODE 1: C=gelu(acc+bias)  MODE 2: C+=acc+bias
template<int MODE>
__global__ __launch_bounds__(256) void k_gemm128(const float* __restrict__ A,
                                                 const float* __restrict__ W,
                                                 const float* __restrict__ bias,
                                                 float* __restrict__ C,
                                                 int K, int N)
{
    __shared__ float As[2][16*132];
    __shared__ float Bs[2][16*132];
    const int t = threadIdx.x, tx = t & 15, ty = t >> 4;
    const int row0 = blockIdx.y*128, col0 = blockIdx.x*128;
    const int am = t >> 2, ak = (t & 3) << 2;
    const int bk = t >> 5, bn = (t & 31) << 2;
    const float* Ap = A + (size_t)(row0 + am)*K + ak;
    const float* Bp = W + (size_t)bk*N + col0 + bn;
    float acc[8][8] = {};
    float4 a0, a1, b0, b1;
    a0 = *(const float4*)Ap;
    a1 = *(const float4*)(Ap + (size_t)64*K);
    b0 = *(const float4*)Bp;
    b1 = *(const float4*)(Bp + (size_t)8*N);
    int buf = 0;
    As[0][(ak+0)*132+am]=a0.x; As[0][(ak+1)*132+am]=a0.y; As[0][(ak+2)*132+am]=a0.z; As[0][(ak+3)*132+am]=a0.w;
    As[0][(ak+0)*132+am+64]=a1.x; As[0][(ak+1)*132+am+64]=a1.y; As[0][(ak+2)*132+am+64]=a1.z; As[0][(ak+3)*132+am+64]=a1.w;
    *(float4*)&Bs[0][bk*132+bn] = b0;
    *(float4*)&Bs[0][(bk+8)*132+bn] = b1;
    __syncthreads();
    for (int k0 = 16; k0 < K; k0 += 16) {
        a0 = *(const float4*)(Ap + k0);
        a1 = *(const float4*)(Ap + (size_t)64*K + k0);
        b0 = *(const float4*)(Bp + (size_t)k0*N);
        b1 = *(const float4*)(Bp + (size_t)(k0+8)*N);
        #pragma unroll
        for (int kk = 0; kk < 16; kk++) {
            float4 x0 = *(const float4*)&As[buf][kk*132 + ty*8];
            float4 x1 = *(const float4*)&As[buf][kk*132 + ty*8 + 4];
            float4 y0 = *(const float4*)&Bs[buf][kk*132 + tx*8];
            float4 y1 = *(const float4*)&Bs[buf][kk*132 + tx*8 + 4];
            float av[8] = {x0.x,x0.y,x0.z,x0.w,x1.x,x1.y,x1.z,x1.w};
            float bv[8] = {y0.x,y0.y,y0.z,y0.w,y1.x,y1.y,y1.z,y1.w};
            #pragma unroll
            for (int i = 0; i < 8; i++)
                #pragma unroll
                for (int j = 0; j < 8; j++) acc[i][j] += av[i]*bv[j];
        }
        buf ^= 1;
        As[buf][(ak+0)*132+am]=a0.x; As[buf][(ak+1)*132+am]=a0.y; As[buf][(ak+2)*132+am]=a0.z; As[buf][(ak+3)*132+am]=a0.w;
        As[buf][(ak+0)*132+am+64]=a1.x; As[buf][(ak+1)*132+am+64]=a1.y; As[buf][(ak+2)*132+am+64]=a1.z; As[buf][(ak+3)*132+am+64]=a1.w;
        *(float4*)&Bs[buf][bk*132+bn] = b0;
        *(float4*)&Bs[buf][(bk+8)*132+bn] = b1;
        __syncthreads();
    }
    #pragma unroll
    for (int kk = 0; kk < 16; kk++) {
        float4 x0 = *(const float4*)&As[buf][kk*132 + ty*8];
        float4 x1 = *(const float4*)&As[buf][kk*132 + ty*8 + 4];
        float4 y0 = *(const float4*)&Bs[buf][kk*132 + tx*8];
        float4 y1 = *(const float4*)&Bs[buf][kk*132 + tx*8 + 4];
        float av[8] = {x0.x,x0.y,x0.z,x0.w,x1.x,x1.y,x1.z,x1.w};
        float bv[8] = {y0.x,y0.y,y0.z,y0.w,y1.x,y1.y,y1.z,y1.w};
        #pragma unroll
        for (int i = 0; i < 8; i++)
            #pragma unroll
            for (int j = 0; j < 8; j++) acc[i][j] += av[i]*bv[j];
    }
    #pragma unroll
    for (int i = 0; i < 8; i++) {
        int r = row0 + ty*8 + i;
        #pragma unroll
        for (int j = 0; j < 8; j++) {
            int c = col0 + tx*8 + j;
            float val = acc[i][j];
            if (bias) val += bias[c];
            if (MODE == 1) {
                float xx = val;
                val = 0.5f*xx*(1.0f + tanhf(0.7978845608028654f*(xx + 0.044715f*xx*xx*xx)));
            }
            size_t idx = (size_t)r*N + c;
            if (MODE == 2) val += C[idx];
            C[idx] = val;
        }
    }
}

// ---------------- 64x128x16 double-buffered SGEMM (for N=128 outputs) ----------
template<int MODE>
__global__ __launch_bounds__(256) void k_gemm64(const float* __restrict__ A,
                                                const float* __restrict__ W,
                                                const float* __restrict__ bias,
                                                float* __restrict__ C,
                                                int K, int N)
{
    __shared__ float As[2][16*132];
    __shared__ float Bs[2][16*132];
    const int t = threadIdx.x, tx = t & 15, ty = t >> 4;
    const int row0 = blockIdx.y*64, col0 = blockIdx.x*128;
    const int am = t >> 2, ak = (t & 3) << 2;
    const int bk = t >> 5, bn = (t & 31) << 2;
    const float* Ap = A + (size_t)(row0 + am)*K + ak;
    const float* Bp = W + (size_t)bk*N + col0 + bn;
    float acc[4][8] = {};
    float4 a0, b0, b1;
    a0 = *(const float4*)Ap;
    b0 = *(const float4*)Bp;
    b1 = *(const float4*)(Bp + (size_t)8*N);
    int buf = 0;
    As[0][(ak+0)*132+am]=a0.x; As[0][(ak+1)*132+am]=a0.y; As[0][(ak+2)*132+am]=a0.z; As[0][(ak+3)*132+am]=a0.w;
    *(float4*)&Bs[0][bk*132+bn] = b0;
    *(float4*)&Bs[0][(bk+8)*132+bn] = b1;
    __syncthreads();
    for (int k0 = 16; k0 < K; k0 += 16) {
        a0 = *(const float4*)(Ap + k0);
        b0 = *(const float4*)(Bp + (size_t)k0*N);
        b1 = *(const float4*)(Bp + (size_t)(k0+8)*N);
        #pragma unroll
        for (int kk = 0; kk < 16; kk++) {
            float4 x0 = *(const float4*)&As[buf][kk*132 + ty*4];
            float4 y0 = *(const float4*)&Bs[buf][kk*132 + tx*8];
            float4 y1 = *(const float4*)&Bs[buf][kk*132 + tx*8 + 4];
            float av[4] = {x0.x,x0.y,x0.z,x0.w};
            float bv[8] = {y0.x,y0.y,y0.z,y0.w,y1.x,y1.y,y1.z,y1.w};
            #pragma unroll
            for (int i = 0; i < 4; i++)
                #pragma unroll
                for (int j = 0; j < 8; j++) acc[i][j] += av[i]*bv[j];
        }
        buf ^= 1;
        As[buf][(ak+0)*132+am]=a0.x; As[buf][(ak+1)*132+am]=a0.y; As[buf][(ak+2)*132+am]=a0.z; As[buf][(ak+3)*132+am]=a0.w;
        *(float4*)&Bs[buf][bk*132+bn] = b0;
        *(float4*)&Bs[buf][(bk+8)*132+bn] = b1;
        __syncthreads();
    }
    #pragma unroll
    for (int kk = 0; kk < 16; kk++) {
        float4 x0 = *(const float4*)&As[buf][kk*132 + ty*4];
        float4 y0 = *(const float4*)&Bs[buf][kk*132 + tx*8];
        float4 y1 = *(const float4*)&Bs[buf][kk*132 + tx*8 + 4];
        float av[4] = {x0.x,x0.y,x0.z,x0.w};
        float bv[8] = {y0.x,y0.y,y0.z,y0.w,y1.x,y1.y,y1.z,y1.w};
        #pragma unroll
        for (int i = 0; i < 4; i++)
            #pragma unroll
            for (int j = 0; j < 8; j++) acc[i][j] += av[i]*bv[j];
    }
    #pragma unroll
    for (int i = 0; i < 4; i++) {
        int r = row0 + ty*4 + i;
        #pragma unroll
        for (int j = 0; j < 8; j++) {
            int c = col0 + tx*8 + j;
            float val = acc[i][j];
            if (bias) val += bias[c];
            if (MODE == 1) {
                float xx = val;
                val = 0.5f*xx*(1.0f + tanhf(0.7978845608028654f*(xx + 0.044715f*xx*xx*xx)));
            }
            size_t idx = (size_t)r*N + c;
            if (MODE == 2) val += C[idx];
            C[idx] = val;
        }
    }
}

// ---------------- FAVOR features (128 rows x 128 feats, K=128) ----------------
// ISQ=1: fully fused (diag + rowmax + exp) -> qp.  ISQ=0: writes dd, diag, blockmax.
template<int ISQ>
__global__ __launch_bounds__(256) void k_feat(const float* __restrict__ src,
                                              const float* __restrict__ proj,
                                              float* __restrict__ outp,
                                              float* __restrict__ diag,
                                              float* __restrict__ bmax)
{
    __shared__ float As[2][16*132];
    __shared__ float Ps[2][16*132];
    __shared__ float sD[128];
    __shared__ float sred[256];
    const int t = threadIdx.x, tx = t & 15, ty = t >> 4;
    const int bh = blockIdx.y, b = bh >> 3, hh = bh & 7;
    const int s0 = blockIdx.x*128;
    const int am = t >> 2, ak = (t & 3) << 2;
    const float* Ap = src + ((size_t)(b*SS + s0 + am)*HH + hh)*DHD + ak;
    const size_t arow2 = (size_t)64*HH*DHD;
    const float* Pp = proj + (size_t)am*DHD + ak;
    float acc[8][8] = {};
    float dacc = 0.f;
    float4 a0, a1, p0, p1;
    a0 = *(const float4*)Ap;
    a1 = *(const float4*)(Ap + arow2);
    p0 = *(const float4*)Pp;
    p1 = *(const float4*)(Pp + (size_t)64*DHD);
    int buf = 0;
    As[0][(ak+0)*132+am]=a0.x*NORMC; As[0][(ak+1)*132+am]=a0.y*NORMC; As[0][(ak+2)*132+am]=a0.z*NORMC; As[0][(ak+3)*132+am]=a0.w*NORMC;
    As[0][(ak+0)*132+am+64]=a1.x*NORMC; As[0][(ak+1)*132+am+64]=a1.y*NORMC; As[0][(ak+2)*132+am+64]=a1.z*NORMC; As[0][(ak+3)*132+am+64]=a1.w*NORMC;
    Ps[0][(ak+0)*132+am]=p0.x; Ps[0][(ak+1)*132+am]=p0.y; Ps[0][(ak+2)*132+am]=p0.z; Ps[0][(ak+3)*132+am]=p0.w;
    Ps[0][(ak+0)*132+am+64]=p1.x; Ps[0][(ak+1)*132+am+64]=p1.y; Ps[0][(ak+2)*132+am+64]=p1.z; Ps[0][(ak+3)*132+am+64]=p1.w;
    __syncthreads();
    for (int k0 = 16; k0 < DHD; k0 += 16) {
        a0 = *(const float4*)(Ap + k0);
        a1 = *(const float4*)(Ap + arow2 + k0);
        p0 = *(const float4*)(Pp + k0);
        p1 = *(const float4*)(Pp + (size_t)64*DHD + k0);
        if (t < 128) {
            #pragma unroll
            for (int kk = 0; kk < 16; kk++) { float v = As[buf][kk*132 + t]; dacc += v*v; }
        }
        #pragma unroll
        for (int kk = 0; kk < 16; kk++) {
            float4 x0 = *(const float4*)&As[buf][kk*132 + ty*8];
            float4 x1 = *(const float4*)&As[buf][kk*132 + ty*8 + 4];
            float4 y0 = *(const float4*)&Ps[buf][kk*132 + tx*8];
            float4 y1 = *(const float4*)&Ps[buf][kk*132 + tx*8 + 4];
            float av[8] = {x0.x,x0.y,x0.z,x0.w,x1.x,x1.y,x1.z,x1.w};
            float bv[8] = {y0.x,y0.y,y0.z,y0.w,y1.x,y1.y,y1.z,y1.w};
            #pragma unroll
            for (int i = 0; i < 8; i++)
                #pragma unroll
                for (int j = 0; j < 8; j++) acc[i][j] += av[i]*bv[j];
        }
        buf ^= 1;
        As[buf][(ak+0)*132+am]=a0.x*NORMC; As[buf][(ak+1)*132+am]=a0.y*NORMC; As[buf][(ak+2)*132+am]=a0.z*NORMC; As[buf][(ak+3)*132+am]=a0.w*NORMC;
        As[buf][(ak+0)*132+am+64]=a1.x*NORMC; As[buf][(ak+1)*132+am+64]=a1.y*NORMC; As[buf][(ak+2)*132+am+64]=a1.z*NORMC; As[buf][(ak+3)*132+am+64]=a1.w*NORMC;
        Ps[buf][(ak+0)*132+am]=p0.x; Ps[buf][(ak+1)*132+am]=p0.y; Ps[buf][(ak+2)*132+am]=p0.z; Ps[buf][(ak+3)*132+am]=p0.w;
        Ps[buf][(ak+0)*132+am+64]=p1.x; Ps[buf][(ak+1)*132+am+64]=p1.y; Ps[buf][(ak+2)*132+am+64]=p1.z; Ps[buf][(ak+3)*132+am+64]=p1.w;
        __syncthreads();
    }
    if (t < 128) {
        #pragma unroll
        for (int kk = 0; kk < 16; kk++) { float v = As[buf][kk*132 + t]; dacc += v*v; }
        sD[t] = 0.5f*dacc;
    }
    #pragma unroll
    for (int kk = 0; kk < 16; kk++) {
        float4 x0 = *(const float4*)&As[buf][kk*132 + ty*8];
        float4 x1 = *(const float4*)&As[buf][kk*132 + ty*8 + 4];
        float4 y0 = *(const float4*)&Ps[buf][kk*132 + tx*8];
        float4 y1 = *(const float4*)&Ps[buf][kk*132 + tx*8 + 4];
        float av[8] = {x0.x,x0.y,x0.z,x0.w,x1.x,x1.y,x1.z,x1.w};
        float bv[8] = {y0.x,y0.y,y0.z,y0.w,y1.x,y1.y,y1.z,y1.w};
        #pragma unroll
        for (int i = 0; i < 8; i++)
            #pragma unroll
            for (int j = 0; j < 8; j++) acc[i][j] += av[i]*bv[j];
    }
    __syncthreads();

    if (ISQ) {
        float rm[8];
        #pragma unroll
        for (int i = 0; i < 8; i++) {
            float m = acc[i][0];
            #pragma unroll
            for (int j = 1; j < 8; j++) m = fmaxf(m, acc[i][j]);
            rm[i] = m;
        }
        #pragma unroll
        for (int o = 1; o < 16; o <<= 1)
            #pragma unroll
            for (int i = 0; i < 8; i++) rm[i] = fmaxf(rm[i], __shfl_xor_sync(0xffffffffu, rm[i], o));
        #pragma unroll
        for (int i = 0; i < 8; i++) {
            int row = ty*8 + i;
            float dg = sD[row];
            float4 o0, o1;
            o0.x = RATIOC*(expf(acc[i][0]-dg-rm[i]) + 1e-4f);
            o0.y = RATIOC*(expf(acc[i][1]-dg-rm[i]) + 1e-4f);
            o0.z = RATIOC*(expf(acc[i][2]-dg-rm[i]) + 1e-4f);
            o0.w = RATIOC*(expf(acc[i][3]-dg-rm[i]) + 1e-4f);
            o1.x = RATIOC*(expf(acc[i][4]-dg-rm[i]) + 1e-4f);
            o1.y = RATIOC*(expf(acc[i][5]-dg-rm[i]) + 1e-4f);
            o1.z = RATIOC*(expf(acc[i][6]-dg-rm[i]) + 1e-4f);
            o1.w = RATIOC*(expf(acc[i][7]-dg-rm[i]) + 1e-4f);
            size_t base = ((size_t)bh*SS + s0 + row)*MF + tx*8;
            *(float4*)(outp + base) = o0;
            *(float4*)(outp + base + 4) = o1;
        }
    } else {
        float bm = -1e30f;
        #pragma unroll
        for (int i = 0; i < 8; i++) {
            size_t base = ((size_t)bh*SS + s0 + ty*8 + i)*MF + tx*8;
            float4 o0 = {acc[i][0],acc[i][1],acc[i][2],acc[i][3]};
            float4 o1 = {acc[i][4],acc[i][5],acc[i][6],acc[i][7]};
            *(float4*)(outp + base) = o0;
            *(float4*)(outp + base + 4) = o1;
            #pragma unroll
            for (int j = 0; j < 8; j++) bm = fmaxf(bm, acc[i][j]);
        }
        if (t < 128) diag[(size_t)bh*SS + s0 + t] = sD[t];
        sred[t] = bm; __syncthreads();
        #pragma unroll
        for (int o = 128; o > 0; o >>= 1) { if (t < o) sred[t] = fmaxf(sred[t], sred[t+o]); __syncthreads(); }
        if (t == 0) bmax[bh*16 + blockIdx.x] = sred[0];
    }
}

// ---------------- stab reduce (16 blockmaxes -> 1 per bh) ----------------
__global__ void k_stab2()
{
    int bh = threadIdx.x;
    if (bh < NBH) {
        float m = -1e30f;
        #pragma unroll
        for (int i = 0; i < 16; i++) m = fmaxf(m, g_bmax[bh*16 + i]);
        g_stab[bh] = m;
    }
}

// ---------------- key feature exp ----------------
__global__ void k_fek(float* __restrict__ dd, const float* __restrict__ diag)
{
    int r = blockIdx.x*8 + (threadIdx.x >> 5);
    int lane = threadIdx.x & 31;
    float st = g_stab[r >> 11];
    float dg = diag[r];
    float4* p = (float4*)(dd + (size_t)r*MF);
    float4 v = p[lane];
    v.x = RATIOC*(expf(v.x-dg-st) + 1e-4f);
    v.y = RATIOC*(expf(v.y-dg-st) + 1e-4f);
    v.z = RATIOC*(expf(v.z-dg-st) + 1e-4f);
    v.w = RATIOC*(expf(v.w-dg-st) + 1e-4f);
    p[lane] = v;
}

// ---------------- chunk-local attention (phase A), 512 threads ----------------
__global__ __launch_bounds__(512) void k_chunk(const float* __restrict__ qp,
                                               const float* __restrict__ kp,
                                               const float* __restrict__ v)
{
    extern __shared__ float sm[];
    float* s0 = sm;             // Q^T then attn^T (masked)
    float* s1 = sm + 128*132;   // K^T then K natural
    float* s2 = s1 + 128*132;   // V
    int blk = blockIdx.x, bh = blk >> 4, c = blk & 15;
    int b = bh >> 3, hh = bh & 7;
    int t = threadIdx.x;
    int ty = t >> 5, tx = t & 31;
    int i0 = ty*8, j0 = tx*4;
    const float* qb = qp + ((size_t)bh*SS + c*CHUNK)*MF;
    const float* kb = kp + ((size_t)bh*SS + c*CHUNK)*MF;

    #pragma unroll
    for (int rr = 0; rr < 8; rr++) {
        int f = rr*512 + t;
        int i = f >> 5;
        int m4 = (f & 31) << 2;
        float4 qv = *(const float4*)(qb + (size_t)i*MF + m4);
        s0[(m4+0)*132+i]=qv.x; s0[(m4+1)*132+i]=qv.y; s0[(m4+2)*132+i]=qv.z; s0[(m4+3)*132+i]=qv.w;
        float4 kv = *(const float4*)(kb + (size_t)i*MF + m4);
        s1[(m4+0)*132+i]=kv.x; s1[(m4+1)*132+i]=kv.y; s1[(m4+2)*132+i]=kv.z; s1[(m4+3)*132+i]=kv.w;
    }
    __syncthreads();

    float acc[8][4] = {};
    for (int m = 0; m < 128; m++) {
        float4 x0 = *(const float4*)&s0[m*132 + i0];
        float4 x1 = *(const float4*)&s0[m*132 + i0 + 4];
        float4 y  = *(const float4*)&s1[m*132 + j0];
        float av[8] = {x0.x,x0.y,x0.z,x0.w,x1.x,x1.y,x1.z,x1.w};
        float bv[4] = {y.x,y.y,y.z,y.w};
        #pragma unroll
        for (int ii = 0; ii < 8; ii++)
            #pragma unroll
            for (int jj = 0; jj < 4; jj++) acc[ii][jj] += av[ii]*bv[jj];
    }
    // den partials (with causal mask) + warp reduce (warp == fixed ty)
    float den[8];
    #pragma unroll
    for (int ii = 0; ii < 8; ii++) {
        float s = 0.f;
        #pragma unroll
        for (int jj = 0; jj < 4; jj++) if (j0+jj <= i0+ii) s += acc[ii][jj];
        den[ii] = s;
    }
    #pragma unroll
    for (int o = 16; o > 0; o >>= 1)
        #pragma unroll
        for (int ii = 0; ii < 8; ii++) den[ii] += __shfl_xor_sync(0xffffffffu, den[ii], o);
    if (tx == 0) {
        #pragma unroll
        for (int ii = 0; ii < 8; ii++) g_den[(size_t)bh*SS + c*CHUNK + i0 + ii] = den[ii];
    }
    // ks_c (column sums of K == row sums of K^T)
    if (t < 128) {
        float ks = 0.f;
        #pragma unroll
        for (int j = 0; j < 128; j += 4) {
            float4 kv = *(const float4*)&s1[t*132 + j];
            ks += kv.x + kv.y + kv.z + kv.w;
        }
        g_ksc[((size_t)bh*NC + c)*MF + t] = ks;
    }
    __syncthreads();

    // overwrite: s0 <- attn^T masked, s1 <- K natural, s2 <- V
    #pragma unroll
    for (int ii = 0; ii < 8; ii++)
        #pragma unroll
        for (int jj = 0; jj < 4; jj++)
            s0[(j0+jj)*132 + (i0+ii)] = (j0+jj <= i0+ii) ? acc[ii][jj] : 0.f;
    #pragma unroll
    for (int rr = 0; rr < 8; rr++) {
        int f = rr*512 + t;
        int j = f >> 5;
        int m4 = (f & 31) << 2;
        *(float4*)&s1[j*132 + m4] = *(const float4*)(kb + (size_t)j*MF + m4);
        *(float4*)&s2[j*132 + m4] = *(const float4*)(v + ((size_t)(b*SS + c*CHUNK + j)*HH + hh)*DHD + m4);
    }
    __syncthreads();

    // num[i][d]
    {
        float an[8][4] = {};
        for (int j = 0; j < 128; j++) {
            float4 x0 = *(const float4*)&s0[j*132 + i0];
            float4 x1 = *(const float4*)&s0[j*132 + i0 + 4];
            float4 y  = *(const float4*)&s2[j*132 + j0];
            float av[8] = {x0.x,x0.y,x0.z,x0.w,x1.x,x1.y,x1.z,x1.w};
            float bv[4] = {y.x,y.y,y.z,y.w};
            #pragma unroll
            for (int ii = 0; ii < 8; ii++)
                #pragma unroll
                for (int dd = 0; dd < 4; dd++) an[ii][dd] += av[ii]*bv[dd];
        }
        #pragma unroll
        for (int ii = 0; ii < 8; ii++) {
            float4 o4 = {an[ii][0], an[ii][1], an[ii][2], an[ii][3]};
            *(float4*)(g_o + ((size_t)(b*SS + c*CHUNK + i0 + ii)*HH + hh)*DHD + j0) = o4;
        }
    }
    // kv_c[m][d]
    {
        float ak[8][4] = {};
        for (int j = 0; j < 128; j++) {
            float4 x0 = *(const float4*)&s1[j*132 + i0];
            float4 x1 = *(const float4*)&s1[j*132 + i0 + 4];
            float4 y  = *(const float4*)&s2[j*132 + j0];
            float av[8] = {x0.x,x0.y,x0.z,x0.w,x1.x,x1.y,x1.z,x1.w};
            float bv[4] = {y.x,y.y,y.z,y.w};
            #pragma unroll
            for (int mm = 0; mm < 8; mm++)
                #pragma unroll
                for (int dd = 0; dd < 4; dd++) ak[mm][dd] += av[mm]*bv[dd];
        }
        #pragma unroll
        for (int mm = 0; mm < 8; mm++) {
            float4 o4 = {ak[mm][0], ak[mm][1], ak[mm][2], ak[mm][3]};
            *(float4*)(g_kvc + ((size_t)bh*NC + c)*(MF*DHD) + (size_t)(i0+mm)*DHD + j0) = o4;
        }
    }
}

// ---------------- exclusive prefix over chunks (phase B) ----------------
__global__ void k_prefix()
{
    int bh = blockIdx.x, seg = blockIdx.y, t = threadIdx.x;
    for (int e = seg*2048 + t; e < (seg+1)*2048; e += 256) {
        float run = 0.f;
        #pragma unroll
        for (int c = 0; c < NC; c++) {
            size_t idx = ((size_t)bh*NC + c)*(MF*DHD) + e;
            g_kvp[idx] = run; run += g_kvc[idx];
        }
    }
    if (seg == 0) {
        for (int e = t; e < MF; e += 256) {
            float run = 0.f;
            #pragma unroll
            for (int c = 0; c < NC; c++) {
                size_t idx = ((size_t)bh*NC + c)*MF + e;
                g_ksp[idx] = run; run += g_ksc[idx];
            }
        }
    }
}

// ---------------- cross terms + normalization (phase C), 512 threads --------
__global__ __launch_bounds__(512) void k_cross(const float* __restrict__ qp)
{
    extern __shared__ float sm[];
    float* sQ = sm;              // Q^T
    float* sP = sm + 128*132;    // kv prefix, natural [m][d]
    float* sS = sP + 128*132;    // ksp [128]
    float* sD = sS + 128;        // den [128]
    int blk = blockIdx.x, bh = blk >> 4, c = blk & 15;
    int b = bh >> 3, hh = bh & 7;
    int t = threadIdx.x;
    int ty = t >> 5, tx = t & 31;
    int i0 = ty*8, j0 = tx*4;
    const float* qb = qp + ((size_t)bh*SS + c*CHUNK)*MF;

    #pragma unroll
    for (int rr = 0; rr < 8; rr++) {
        int f = rr*512 + t;
        int i = f >> 5;
        int m4 = (f & 31) << 2;
        float4 qv = *(const float4*)(qb + (size_t)i*MF + m4);
        sQ[(m4+0)*132+i]=qv.x; sQ[(m4+1)*132+i]=qv.y; sQ[(m4+2)*132+i]=qv.z; sQ[(m4+3)*132+i]=qv.w;
        *(float4*)&sP[i*132 + m4] =
            *(const float4*)(g_kvp + ((size_t)bh*NC + c)*(MF*DHD) + (size_t)i*DHD + m4);
    }
    if (t < 128) sS[t] = g_ksp[((size_t)bh*NC + c)*MF + t];
    __syncthreads();
    if (t < 128) {
        float dc = 0.f;
        for (int m = 0; m < 128; m++) dc += sQ[m*132 + t]*sS[m];
        sD[t] = g_den[(size_t)bh*SS + c*CHUNK + t] + dc + 1e-6f;
    }
    __syncthreads();

    float ac[8][4] = {};
    for (int m = 0; m < 128; m++) {
        float4 x0 = *(const float4*)&sQ[m*132 + i0];
        float4 x1 = *(const float4*)&sQ[m*132 + i0 + 4];
        float4 y  = *(const float4*)&sP[m*132 + j0];
        float av[8] = {x0.x,x0.y,x0.z,x0.w,x1.x,x1.y,x1.z,x1.w};
        float bv[4] = {y.x,y.y,y.z,y.w};
        #pragma unroll
        for (int ii = 0; ii < 8; ii++)
            #pragma unroll
            for (int dd = 0; dd < 4; dd++) ac[ii][dd] += av[ii]*bv[dd];
    }
    #pragma unroll
    for (int ii = 0; ii < 8; ii++) {
        float inv = 1.0f / sD[i0 + ii];
        float* op = g_o + ((size_t)(b*SS + c*CHUNK + i0 + ii)*HH + hh)*DHD + j0;
        float4 o4 = *(float4*)op;
        o4.x = (o4.x + ac[ii][0])*inv;
        o4.y = (o4.y + ac[ii][1])*inv;
        o4.z = (o4.z + ac[ii][2])*inv;
        o4.w = (o4.w + ac[ii][3])*inv;
        *(float4*)op = o4;
    }
}

// ---------------- pooling ----------------
__global__ void k_pool()
{
    int b = blockIdx.x, seg = blockIdx.y, t = threadIdx.x;
    float acc = 0.f;
    for (int s = seg*128; s < (seg+1)*128; s++) acc += g_h[((size_t)b*SS + s)*DIMC + t];
    g_pp[(b*16 + seg)*DIMC + t] = acc;
}

__global__ void k_final(const float* __restrict__ fw, const float* __restrict__ fb,
                        float* __restrict__ out)
{
    __shared__ float pooled[BB*DIMC];
    int t = threadIdx.x;
    for (int b = 0; b < BB; b++) {
        float a = 0.f;
        #pragma unroll
        for (int s = 0; s < 16; s++) a += g_pp[(b*16 + s)*DIMC + t];
        pooled[b*DIMC + t] = a * (1.0f/SS);
    }
    __syncthreads();
    if (t < BB*NCLS) {
        int b = t / NCLS, c = t % NCLS;
        float acc = fb[c];
        for (int d = 0; d < DIMC; d++) acc += pooled[b*DIMC + d]*fw[d*NCLS + c];
        out[t] = acc;
    }
}

// ---------------- host driver ----------------
static void* sym(const void* s) { void* p = nullptr; cudaGetSymbolAddress(&p, s); return p; }

extern "C" void kernel_launch(void* const* d_in, const int* in_sizes, int n_in,
                              void* d_out, int out_size)
{
    const float* x     = (const float*)d_in[0];
    const float* lin_w = (const float*)d_in[1];
    const float* lin_b = (const float*)d_in[2];
    const float* pe    = (const float*)d_in[3];
    const float* proj  = (const float*)d_in[4];
    const float* ln1_g = (const float*)d_in[5];
    const float* ln1_b = (const float*)d_in[6];
    const float* wq    = (const float*)d_in[7];
    const float* wk    = (const float*)d_in[8];
    const float* wv    = (const float*)d_in[9];
    const float* wo    = (const float*)d_in[10];
    const float* wo_b  = (const float*)d_in[11];
    const float* ln2_g = (const float*)d_in[12];
    const float* ln2_b = (const float*)d_in[13];
    const float* ff1_w = (const float*)d_in[14];
    const float* ff1_b = (const float*)d_in[15];
    const float* ff2_w = (const float*)d_in[16];
    const float* ff2_b = (const float*)d_in[17];
    const float* fin_w = (const float*)d_in[18];
    const float* fin_b = (const float*)d_in[19];
    float* out = (float*)d_out;

    float* ph  = (float*)sym(g_h);
    float* py  = (float*)sym(g_y);
    float* pq  = (float*)sym(g_q);
    float* pk  = (float*)sym(g_k);
    float* pv  = (float*)sym(g_v);
    float* pqp = (float*)sym(g_qp);
    float* pkp = (float*)sym(g_kp);
    float* pdk = (float*)sym(g_diagk);
    float* pbm = (float*)sym(g_bmax);
    float* pff = (float*)sym(g_ff);
    float* po  = (float*)sym(g_o);

    const int SMEM_CHUNK = 3*128*132*4;             // 202752
    const int SMEM_CROSS = (2*128*132 + 256)*4;     // 136192
    cudaFuncSetAttribute(k_chunk, cudaFuncAttributeMaxDynamicSharedMemorySize, SMEM_CHUNK);
    cudaFuncSetAttribute(k_cross, cudaFuncAttributeMaxDynamicSharedMemorySize, SMEM_CROSS);

    k_embed<<<BSR/8, 256>>>(x, lin_w, lin_b, pe);

    for (int l = 0; l < DEPTH; l++) {
        const float* prj = proj + (size_t)l*MF*DHD;

        k_ln<<<BSR/8, 256>>>(ph, ln1_g + l*DIMC, ln1_b + l*DIMC, py);

        k_gemm128<0><<<dim3(INNER/128, BSR/128), 256>>>(py, wq + (size_t)l*DIMC*INNER, nullptr, pq, DIMC, INNER);
        k_gemm128<0><<<dim3(INNER/128, BSR/128), 256>>>(py, wk + (size_t)l*DIMC*INNER, nullptr, pk, DIMC, INNER);
        k_gemm128<0><<<dim3(INNER/128, BSR/128), 256>>>(py, wv + (size_t)l*DIMC*INNER, nullptr, pv, DIMC, INNER);

        // K features (dd + diag + blockmax), then stab + exp; Q features fused
        k_feat<0><<<dim3(SS/128, NBH), 256>>>(pk, prj, pkp, pdk, pbm);
        k_stab2<<<1, 32>>>();
        k_fek<<<BHS/8, 256>>>(pkp, pdk);
        k_feat<1><<<dim3(SS/128, NBH), 256>>>(pq, prj, pqp, nullptr, nullptr);

        k_chunk<<<NBH*NC, 512, SMEM_CHUNK>>>(pqp, pkp, pv);
        k_prefix<<<dim3(NBH, 8), 256>>>();
        k_cross<<<NBH*NC, 512, SMEM_CROSS>>>(pqp);

        k_gemm64<2><<<dim3(1, BSR/64), 256>>>(po, wo + (size_t)l*INNER*DIMC, wo_b + l*DIMC, ph, INNER, DIMC);

        k_ln<<<BSR/8, 256>>>(ph, ln2_g + l*DIMC, ln2_b + l*DIMC, py);
        k_gemm128<1><<<dim3(FFD/128, BSR/128), 256>>>(py, ff1_w + (size_t)l*DIMC*FFD, ff1_b + l*FFD, pff, DIMC, FFD);
        k_gemm64<2><<<dim3(1, BSR/64), 256>>>(pff, ff2_w + (size_t)l*FFD*DIMC, ff2_b + l*DIMC, ph, FFD, DIMC);
    }

    k_pool<<<dim3(BB, 16), 128>>>();
    k_final<<<1, 128>>>(fin_w, fin_b, out);
}

// round 4
// speedup vs baseline: 1.1716x; 1.0268x over previous
#include <cuda_runtime.h>
#include <cuda_bf16.h>
#include <math.h>
#include <stdint.h>

// ---------------- problem constants ----------------
#define BB 4
#define SS 2048
#define DIMC 128
#define HH 8
#define DHD 128
#define DEPTH 2
#define NCLS 10
#define MF 128
#define CHUNK 128
#define NC 16
#define INNER 1024
#define FFD 512
#define BSR 8192
#define BHS 65536
#define NBH 32

#define NORMC 0.29730177875068026f
#define RATIOC 0.08838834764831845f

// ---------------- device scratch (fp32) ----------------
__device__ float g_h  [BSR*DIMC];
__device__ float g_q  [BSR*INNER];
__device__ float g_k  [BSR*INNER];
__device__ float g_v  [BSR*INNER];
__device__ float g_qp [(size_t)NBH*SS*MF];
__device__ float g_kp [(size_t)NBH*SS*MF];
__device__ float g_diagq[BHS];
__device__ float g_diagk[BHS];
__device__ float g_bmax[NBH*16];
__device__ float g_stab[NBH];
__device__ float g_o  [BSR*INNER];
__device__ float g_den[BHS];
__device__ float g_kvc[(size_t)NBH*NC*MF*DHD];
__device__ float g_kvp[(size_t)NBH*NC*MF*DHD];
__device__ float g_ksc[NBH*NC*MF];
__device__ float g_ksp[NBH*NC*MF];
__device__ float g_pp [BB*16*DIMC];

// ---------------- device scratch (bf16 hi/lo) ----------------
__device__ __align__(256) __nv_bfloat16 g_yh [BSR*DIMC];
__device__ __align__(256) __nv_bfloat16 g_yl [BSR*DIMC];
__device__ __align__(256) __nv_bfloat16 g_wth[672000];
__device__ __align__(256) __nv_bfloat16 g_wtl[672000];
__device__ __align__(256) __nv_bfloat16 g_qnh[(size_t)BHS*DHD];
__device__ __align__(256) __nv_bfloat16 g_qnl[(size_t)BHS*DHD];
__device__ __align__(256) __nv_bfloat16 g_knh[(size_t)BHS*DHD];
__device__ __align__(256) __nv_bfloat16 g_knl[(size_t)BHS*DHD];
__device__ __align__(256) __nv_bfloat16 g_oh [(size_t)BSR*INNER];
__device__ __align__(256) __nv_bfloat16 g_ol [(size_t)BSR*INNER];
__device__ __align__(256) __nv_bfloat16 g_fh [(size_t)BSR*FFD];
__device__ __align__(256) __nv_bfloat16 g_fl [(size_t)BSR*FFD];

// weight-transpose buffer offsets (elements)
#define WT_Q  0
#define WT_K  131072
#define WT_V  262144
#define WT_O  393216
#define WT_F1 524288
#define WT_F2 589824
#define WT_PJ 655360

// ---------------- warp MMA helpers (baseline PTX, no 'a' features) -----------
__device__ __forceinline__ uint32_t s2u(const void* p){
    uint32_t a;
    asm("{ .reg .u64 t; cvta.to.shared.u64 t, %1; cvt.u32.u64 %0, t; }" : "=r"(a) : "l"(p));
    return a;
}
__device__ __forceinline__ void ldsm4(uint32_t* r, uint32_t addr){
    asm volatile("ldmatrix.sync.aligned.m8n8.x4.shared.b16 {%0,%1,%2,%3}, [%4];"
                 : "=r"(r[0]),"=r"(r[1]),"=r"(r[2]),"=r"(r[3]) : "r"(addr));
}
__device__ __forceinline__ void mma_bf16(float* c, const uint32_t* a, const uint32_t* b){
    asm volatile("mma.sync.aligned.m16n8k16.row.col.f32.bf16.bf16.f32 "
                 "{%0,%1,%2,%3}, {%4,%5,%6,%7}, {%8,%9}, {%0,%1,%2,%3};"
                 : "+f"(c[0]),"+f"(c[1]),"+f"(c[2]),"+f"(c[3])
                 : "r"(a[0]),"r"(a[1]),"r"(a[2]),"r"(a[3]), "r"(b[0]),"r"(b[1]));
}
__device__ __forceinline__ void split_bf16(float v, __nv_bfloat16& h, __nv_bfloat16& l){
    h = __float2bfloat16(v);
    l = __float2bfloat16(v - __bfloat162float(h));
}
__device__ __forceinline__ float gelu(float xx){
    return 0.5f*xx*(1.0f + tanhf(0.7978845608028654f*(xx + 0.044715f*xx*xx*xx)));
}

// ============ HMMA GEMM: C[128-tile,128-tile] = (Ah+Al) @ (Bh+Bl)^T ============
// A: [Mrows, lda] bf16 hi/lo (K-major). B: [Ncols, Ktot] bf16 hi/lo (K-major).
// MODE 0: out fp32 = acc
// MODE 1: outH/outL = split(gelu(acc+bias))
// MODE 2: out fp32 += acc + bias
// MODE 3: out = RATIOC*(exp(acc - diag[row] - rowmax)+1e-4)   [needs gridDim.x==1, Nt=128]
// MODE 4: out = acc; bmax[blockIdx.y] = blockmax
#define SROW 72
template<int MODE>
__global__ __launch_bounds__(256) void k_mma(
    const __nv_bfloat16* __restrict__ Ah, const __nv_bfloat16* __restrict__ Al, int lda,
    const __nv_bfloat16* __restrict__ Bh, const __nv_bfloat16* __restrict__ Bl,
    int Ktot, int Nt,
    const float* __restrict__ bias,
    float* __restrict__ out,
    __nv_bfloat16* __restrict__ outH, __nv_bfloat16* __restrict__ outL,
    const float* __restrict__ diag, float* __restrict__ bmax)
{
    extern __shared__ __align__(16) char dsm[];
    __nv_bfloat16* sAh = (__nv_bfloat16*)dsm;         // [128][72]
    __nv_bfloat16* sAl = sAh + 128*SROW;
    __nv_bfloat16* sBh = sAl + 128*SROW;
    __nv_bfloat16* sBl = sBh + 128*SROW;
    __shared__ float s_rm[2][128];
    __shared__ float s_red[256];

    const int t = threadIdx.x, w = t >> 5, lane = t & 31;
    const int wm = w & 3, wn = w >> 2;
    const int row0 = blockIdx.y*128, col0 = blockIdx.x*128;

    float acc[2][8][4];
    #pragma unroll
    for (int mt = 0; mt < 2; mt++)
        #pragma unroll
        for (int nt = 0; nt < 8; nt++)
            #pragma unroll
            for (int f = 0; f < 4; f++) acc[mt][nt][f] = 0.f;

    const int lrow = (lane & 15), lcol8 = (lane >> 4)*8;

    for (int kc = 0; kc < Ktot; kc += 64) {
        #pragma unroll
        for (int i = 0; i < 4; i++) {
            int f = i*256 + t;                 // 0..1023
            int r = f >> 3, c8 = (f & 7) << 3;
            *(uint4*)(sAh + r*SROW + c8) = *(const uint4*)(Ah + (size_t)(row0+r)*lda + kc + c8);
            *(uint4*)(sAl + r*SROW + c8) = *(const uint4*)(Al + (size_t)(row0+r)*lda + kc + c8);
            *(uint4*)(sBh + r*SROW + c8) = *(const uint4*)(Bh + (size_t)(col0+r)*Ktot + kc + c8);
            *(uint4*)(sBl + r*SROW + c8) = *(const uint4*)(Bl + (size_t)(col0+r)*Ktot + kc + c8);
        }
        __syncthreads();
        #pragma unroll
        for (int ks = 0; ks < 4; ks++) {
            int kcol = ks*16 + lcol8;
            uint32_t ah[2][4], al[2][4];
            #pragma unroll
            for (int mt = 0; mt < 2; mt++) {
                int arow = wm*32 + mt*16 + lrow;
                ldsm4(ah[mt], s2u(sAh + arow*SROW + kcol));
                ldsm4(al[mt], s2u(sAl + arow*SROW + kcol));
            }
            #pragma unroll
            for (int nt2 = 0; nt2 < 4; nt2++) {
                int brow = wn*64 + nt2*16 + lrow;
                uint32_t rh[4], rl[4];
                ldsm4(rh, s2u(sBh + brow*SROW + kcol));
                ldsm4(rl, s2u(sBl + brow*SROW + kcol));
                uint32_t b0h[2] = {rh[0], rh[2]}, b1h[2] = {rh[1], rh[3]};
                uint32_t b0l[2] = {rl[0], rl[2]}, b1l[2] = {rl[1], rl[3]};
                #pragma unroll
                for (int mt = 0; mt < 2; mt++) {
                    mma_bf16(acc[mt][nt2*2],   ah[mt], b0h);
                    mma_bf16(acc[mt][nt2*2],   ah[mt], b0l);
                    mma_bf16(acc[mt][nt2*2],   al[mt], b0h);
                    mma_bf16(acc[mt][nt2*2+1], ah[mt], b1h);
                    mma_bf16(acc[mt][nt2*2+1], ah[mt], b1l);
                    mma_bf16(acc[mt][nt2*2+1], al[mt], b1h);
                }
            }
        }
        __syncthreads();
    }

    // epilogue: acc[mt][nt][f]: row = row0+wm*32+mt*16+(lane>>2)+(f>=2?8:0)
    //                          col = col0+wn*64+nt*8+(lane&3)*2+(f&1)
    const int rl4 = lane >> 2;
    const int cl2 = (lane & 3)*2;

    if (MODE == 0 || MODE == 4) {
        #pragma unroll
        for (int mt = 0; mt < 2; mt++)
            #pragma unroll
            for (int h = 0; h < 2; h++) {
                int gr = row0 + wm*32 + mt*16 + rl4 + h*8;
                #pragma unroll
                for (int nt = 0; nt < 8; nt++) {
                    float2 v = {acc[mt][nt][h*2], acc[mt][nt][h*2+1]};
                    *(float2*)(out + (size_t)gr*Nt + col0 + wn*64 + nt*8 + cl2) = v;
                }
            }
        if (MODE == 4) {
            float bm = -1e30f;
            #pragma unroll
            for (int mt = 0; mt < 2; mt++)
                #pragma unroll
                for (int nt = 0; nt < 8; nt++)
                    #pragma unroll
                    for (int f = 0; f < 4; f++) bm = fmaxf(bm, acc[mt][nt][f]);
            s_red[t] = bm; __syncthreads();
            #pragma unroll
            for (int o = 128; o > 0; o >>= 1) { if (t < o) s_red[t] = fmaxf(s_red[t], s_red[t+o]); __syncthreads(); }
            if (t == 0) bmax[blockIdx.y] = s_red[0];
        }
    } else if (MODE == 1) {
        #pragma unroll
        for (int mt = 0; mt < 2; mt++)
            #pragma unroll
            for (int h = 0; h < 2; h++) {
                int gr = row0 + wm*32 + mt*16 + rl4 + h*8;
                #pragma unroll
                for (int nt = 0; nt < 8; nt++) {
                    int gc = col0 + wn*64 + nt*8 + cl2;
                    float v0 = gelu(acc[mt][nt][h*2]   + bias[gc]);
                    float v1 = gelu(acc[mt][nt][h*2+1] + bias[gc+1]);
                    __nv_bfloat16 h0,l0,h1,l1;
                    split_bf16(v0,h0,l0); split_bf16(v1,h1,l1);
                    __nv_bfloat162 hp, lp;
                    hp.x = h0; hp.y = h1; lp.x = l0; lp.y = l1;
                    *(__nv_bfloat162*)(outH + (size_t)gr*Nt + gc) = hp;
                    *(__nv_bfloat162*)(outL + (size_t)gr*Nt + gc) = lp;
                }
            }
    } else if (MODE == 2) {
        #pragma unroll
        for (int mt = 0; mt < 2; mt++)
            #pragma unroll
            for (int h = 0; h < 2; h++) {
                int gr = row0 + wm*32 + mt*16 + rl4 + h*8;
                #pragma unroll
                for (int nt = 0; nt < 8; nt++) {
                    int gc = col0 + wn*64 + nt*8 + cl2;
                    size_t idx = (size_t)gr*Nt + gc;
                    float2 v = *(float2*)(out + idx);
                    v.x += acc[mt][nt][h*2]   + bias[gc];
                    v.y += acc[mt][nt][h*2+1] + bias[gc+1];
                    *(float2*)(out + idx) = v;
                }
            }
    } else { // MODE 3: Q features
        float rm[2][2];
        #pragma unroll
        for (int mt = 0; mt < 2; mt++)
            #pragma unroll
            for (int h = 0; h < 2; h++) {
                float m = -1e30f;
                #pragma unroll
                for (int nt = 0; nt < 8; nt++)
                    m = fmaxf(m, fmaxf(acc[mt][nt][h*2], acc[mt][nt][h*2+1]));
                m = fmaxf(m, __shfl_xor_sync(0xffffffffu, m, 1));
                m = fmaxf(m, __shfl_xor_sync(0xffffffffu, m, 2));
                rm[mt][h] = m;
            }
        if ((lane & 3) == 0) {
            #pragma unroll
            for (int mt = 0; mt < 2; mt++)
                #pragma unroll
                for (int h = 0; h < 2; h++)
                    s_rm[wn][wm*32 + mt*16 + rl4 + h*8] = rm[mt][h];
        }
        __syncthreads();
        #pragma unroll
        for (int mt = 0; mt < 2; mt++)
            #pragma unroll
            for (int h = 0; h < 2; h++) {
                int lr = wm*32 + mt*16 + rl4 + h*8;
                int gr = row0 + lr;
                float rmax = fmaxf(s_rm[0][lr], s_rm[1][lr]);
                float dg = diag[gr];
                #pragma unroll
                for (int nt = 0; nt < 8; nt++) {
                    float2 v;
                    v.x = RATIOC*(expf(acc[mt][nt][h*2]  -dg-rmax) + 1e-4f);
                    v.y = RATIOC*(expf(acc[mt][nt][h*2+1]-dg-rmax) + 1e-4f);
                    *(float2*)(out + (size_t)gr*Nt + wn*64 + nt*8 + cl2) = v;
                }
            }
    }
}

// ---------------- embed ----------------
__global__ void k_embed(const float* __restrict__ x, const float* __restrict__ lw,
                        const float* __restrict__ lb, const float* __restrict__ pe)
{
    int warp = threadIdx.x >> 5, lane = threadIdx.x & 31;
    int r = blockIdx.x*8 + warp;
    float xv = x[r];
    float4 l4 = ((const float4*)lw)[lane];
    float4 b4 = ((const float4*)lb)[lane];
    float4 p4 = ((const float4*)(pe + (size_t)(r % SS)*DIMC))[lane];
    float4 o4 = { xv*l4.x + b4.x + p4.x, xv*l4.y + b4.y + p4.y,
                  xv*l4.z + b4.z + p4.z, xv*l4.w + b4.w + p4.w };
    ((float4*)(g_h + (size_t)r*DIMC))[lane] = o4;
}

// ---------------- layernorm -> bf16 hi/lo ----------------
__global__ void k_ln(const float* __restrict__ in, const float* __restrict__ g,
                     const float* __restrict__ b,
                     __nv_bfloat16* __restrict__ outH, __nv_bfloat16* __restrict__ outL)
{
    int warp = threadIdx.x >> 5, lane = threadIdx.x & 31;
    int r = blockIdx.x*8 + warp;
    float4 v = ((const float4*)(in + (size_t)r*DIMC))[lane];
    float s = v.x + v.y + v.z + v.w;
    #pragma unroll
    for (int o = 16; o > 0; o >>= 1) s += __shfl_xor_sync(0xffffffffu, s, o);
    float mu = s * (1.0f/DIMC);
    float dx = v.x-mu, dy = v.y-mu, dz = v.z-mu, dw = v.w-mu;
    float q = dx*dx + dy*dy + dz*dz + dw*dw;
    #pragma unroll
    for (int o = 16; o > 0; o >>= 1) q += __shfl_xor_sync(0xffffffffu, q, o);
    float inv = rsqrtf(q*(1.0f/DIMC) + 1e-5f);
    float4 gv = ((const float4*)g)[lane];
    float4 bv = ((const float4*)b)[lane];
    float o4[4] = { dx*inv*gv.x + bv.x, dy*inv*gv.y + bv.y,
                    dz*inv*gv.z + bv.z, dw*inv*gv.w + bv.w };
    __nv_bfloat16 hh[4], ll[4];
    #pragma unroll
    for (int j = 0; j < 4; j++) split_bf16(o4[j], hh[j], ll[j]);
    size_t base = (size_t)r*DIMC + lane*4;
    *(__nv_bfloat162*)(outH+base)   = *(__nv_bfloat162*)&hh[0];
    *(__nv_bfloat162*)(outH+base+2) = *(__nv_bfloat162*)&hh[2];
    *(__nv_bfloat162*)(outL+base)   = *(__nv_bfloat162*)&ll[0];
    *(__nv_bfloat162*)(outL+base+2) = *(__nv_bfloat162*)&ll[2];
}

// ---------------- weight transpose+split: W[K,N] -> out[N,K] hi/lo -------------
__global__ void k_wt(const float* __restrict__ W, __nv_bfloat16* __restrict__ outH,
                     __nv_bfloat16* __restrict__ outL, int K, int N)
{
    int e = blockIdx.x*256 + threadIdx.x;
    if (e >= K*N) return;
    int k = e / N, n = e % N;
    __nv_bfloat16 hh, ll;
    split_bf16(W[(size_t)k*N + n], hh, ll);
    outH[(size_t)n*K + k] = hh;
    outL[(size_t)n*K + k] = ll;
}

// ---------------- plain split (proj) ----------------
__global__ void k_cvt(const float* __restrict__ in, __nv_bfloat16* __restrict__ outH,
                      __nv_bfloat16* __restrict__ outL, int n4)
{
    int i = blockIdx.x*256 + threadIdx.x;
    if (i >= n4) return;
    float4 v = ((const float4*)in)[i];
    __nv_bfloat16 hh[4], ll[4];
    split_bf16(v.x, hh[0], ll[0]); split_bf16(v.y, hh[1], ll[1]);
    split_bf16(v.z, hh[2], ll[2]); split_bf16(v.w, hh[3], ll[3]);
    *(__nv_bfloat162*)(outH + i*4)     = *(__nv_bfloat162*)&hh[0];
    *(__nv_bfloat162*)(outH + i*4 + 2) = *(__nv_bfloat162*)&hh[2];
    *(__nv_bfloat162*)(outL + i*4)     = *(__nv_bfloat162*)&ll[0];
    *(__nv_bfloat162*)(outL + i*4 + 2) = *(__nv_bfloat162*)&ll[2];
}

// ------- q/k convert: [B,S,H,DH] fp32 -> [B,H,S,DH] bf16 hi/lo *NORMC + diag -----
__global__ void k_cvt_qk(const float* __restrict__ in, __nv_bfloat16* __restrict__ outH,
                         __nv_bfloat16* __restrict__ outL, float* __restrict__ diag)
{
    int warp = threadIdx.x >> 5, lane = threadIdx.x & 31;
    int wr = blockIdx.x*8 + warp;
    int b = wr >> 14, h = (wr >> 11) & 7, s = wr & 2047;
    const float* src = in + ((size_t)(b*SS + s)*HH + h)*DHD;
    float4 v = ((const float4*)src)[lane];
    v.x *= NORMC; v.y *= NORMC; v.z *= NORMC; v.w *= NORMC;
    float sq = v.x*v.x + v.y*v.y + v.z*v.z + v.w*v.w;
    #pragma unroll
    for (int o = 16; o > 0; o >>= 1) sq += __shfl_xor_sync(0xffffffffu, sq, o);
    if (lane == 0) diag[wr] = 0.5f*sq;
    __nv_bfloat16 hh[4], ll[4];
    split_bf16(v.x, hh[0], ll[0]); split_bf16(v.y, hh[1], ll[1]);
    split_bf16(v.z, hh[2], ll[2]); split_bf16(v.w, hh[3], ll[3]);
    size_t base = (size_t)wr*DHD + lane*4;
    *(__nv_bfloat162*)(outH+base)   = *(__nv_bfloat162*)&hh[0];
    *(__nv_bfloat162*)(outH+base+2) = *(__nv_bfloat162*)&hh[2];
    *(__nv_bfloat162*)(outL+base)   = *(__nv_bfloat162*)&ll[0];
    *(__nv_bfloat162*)(outL+base+2) = *(__nv_bfloat162*)&ll[2];
}

// ---------------- stab reduce ----------------
__global__ void k_stab2()
{
    int bh = threadIdx.x;
    if (bh < NBH) {
        float m = -1e30f;
        #pragma unroll
        for (int i = 0; i < 16; i++) m = fmaxf(m, g_bmax[bh*16 + i]);
        g_stab[bh] = m;
    }
}

// ---------------- key feature exp ----------------
__global__ void k_fek(float* __restrict__ dd, const float* __restrict__ diag)
{
    int r = blockIdx.x*8 + (threadIdx.x >> 5);
    int lane = threadIdx.x & 31;
    float st = g_stab[r >> 11];
    float dg = diag[r];
    float4* p = (float4*)(dd + (size_t)r*MF);
    float4 v = p[lane];
    v.x = RATIOC*(expf(v.x-dg-st) + 1e-4f);
    v.y = RATIOC*(expf(v.y-dg-st) + 1e-4f);
    v.z = RATIOC*(expf(v.z-dg-st) + 1e-4f);
    v.w = RATIOC*(expf(v.w-dg-st) + 1e-4f);
    p[lane] = v;
}

// ---------------- chunk-local attention (phase A), fp32 ----------------
__global__ __launch_bounds__(512) void k_chunk(const float* __restrict__ qp,
                                               const float* __restrict__ kp,
                                               const float* __restrict__ v)
{
    extern __shared__ float sm[];
    float* s0 = sm;
    float* s1 = sm + 128*132;
    float* s2 = s1 + 128*132;
    int blk = blockIdx.x, bh = blk >> 4, c = blk & 15;
    int b = bh >> 3, hh = bh & 7;
    int t = threadIdx.x;
    int ty = t >> 5, tx = t & 31;
    int i0 = ty*8, j0 = tx*4;
    const float* qb = qp + ((size_t)bh*SS + c*CHUNK)*MF;
    const float* kb = kp + ((size_t)bh*SS + c*CHUNK)*MF;

    #pragma unroll
    for (int rr = 0; rr < 8; rr++) {
        int f = rr*512 + t;
        int i = f >> 5;
        int m4 = (f & 31) << 2;
        float4 qv = *(const float4*)(qb + (size_t)i*MF + m4);
        s0[(m4+0)*132+i]=qv.x; s0[(m4+1)*132+i]=qv.y; s0[(m4+2)*132+i]=qv.z; s0[(m4+3)*132+i]=qv.w;
        float4 kv = *(const float4*)(kb + (size_t)i*MF + m4);
        s1[(m4+0)*132+i]=kv.x; s1[(m4+1)*132+i]=kv.y; s1[(m4+2)*132+i]=kv.z; s1[(m4+3)*132+i]=kv.w;
    }
    __syncthreads();

    float acc[8][4] = {};
    for (int m = 0; m < 128; m++) {
        float4 x0 = *(const float4*)&s0[m*132 + i0];
        float4 x1 = *(const float4*)&s0[m*132 + i0 + 4];
        float4 y  = *(const float4*)&s1[m*132 + j0];
        float av[8] = {x0.x,x0.y,x0.z,x0.w,x1.x,x1.y,x1.z,x1.w};
        float bv[4] = {y.x,y.y,y.z,y.w};
        #pragma unroll
        for (int ii = 0; ii < 8; ii++)
            #pragma unroll
            for (int jj = 0; jj < 4; jj++) acc[ii][jj] += av[ii]*bv[jj];
    }
    float den[8];
    #pragma unroll
    for (int ii = 0; ii < 8; ii++) {
        float s = 0.f;
        #pragma unroll
        for (int jj = 0; jj < 4; jj++) if (j0+jj <= i0+ii) s += acc[ii][jj];
        den[ii] = s;
    }
    #pragma unroll
    for (int o = 16; o > 0; o >>= 1)
        #pragma unroll
        for (int ii = 0; ii < 8; ii++) den[ii] += __shfl_xor_sync(0xffffffffu, den[ii], o);
    if (tx == 0) {
        #pragma unroll
        for (int ii = 0; ii < 8; ii++) g_den[(size_t)bh*SS + c*CHUNK + i0 + ii] = den[ii];
    }
    if (t < 128) {
        float ks = 0.f;
        #pragma unroll
        for (int j = 0; j < 128; j += 4) {
            float4 kv = *(const float4*)&s1[t*132 + j];
            ks += kv.x + kv.y + kv.z + kv.w;
        }
        g_ksc[((size_t)bh*NC + c)*MF + t] = ks;
    }
    __syncthreads();

    #pragma unroll
    for (int ii = 0; ii < 8; ii++)
        #pragma unroll
        for (int jj = 0; jj < 4; jj++)
            s0[(j0+jj)*132 + (i0+ii)] = (j0+jj <= i0+ii) ? acc[ii][jj] : 0.f;
    #pragma unroll
    for (int rr = 0; rr < 8; rr++) {
        int f = rr*512 + t;
        int j = f >> 5;
        int m4 = (f & 31) << 2;
        *(float4*)&s1[j*132 + m4] = *(const float4*)(kb + (size_t)j*MF + m4);
        *(float4*)&s2[j*132 + m4] = *(const float4*)(v + ((size_t)(b*SS + c*CHUNK + j)*HH + hh)*DHD + m4);
    }
    __syncthreads();

    {
        float an[8][4] = {};
        for (int j = 0; j < 128; j++) {
            float4 x0 = *(const float4*)&s0[j*132 + i0];
            float4 x1 = *(const float4*)&s0[j*132 + i0 + 4];
            float4 y  = *(const float4*)&s2[j*132 + j0];
            float av[8] = {x0.x,x0.y,x0.z,x0.w,x1.x,x1.y,x1.z,x1.w};
            float bv[4] = {y.x,y.y,y.z,y.w};
            #pragma unroll
            for (int ii = 0; ii < 8; ii++)
                #pragma unroll
                for (int dd = 0; dd < 4; dd++) an[ii][dd] += av[ii]*bv[dd];
        }
        #pragma unroll
        for (int ii = 0; ii < 8; ii++) {
            float4 o4 = {an[ii][0], an[ii][1], an[ii][2], an[ii][3]};
            *(float4*)(g_o + ((size_t)(b*SS + c*CHUNK + i0 + ii)*HH + hh)*DHD + j0) = o4;
        }
    }
    {
        float ak[8][4] = {};
        for (int j = 0; j < 128; j++) {
            float4 x0 = *(const float4*)&s1[j*132 + i0];
            float4 x1 = *(const float4*)&s1[j*132 + i0 + 4];
            float4 y  = *(const float4*)&s2[j*132 + j0];
            float av[8] = {x0.x,x0.y,x0.z,x0.w,x1.x,x1.y,x1.z,x1.w};
            float bv[4] = {y.x,y.y,y.z,y.w};
            #pragma unroll
            for (int mm = 0; mm < 8; mm++)
                #pragma unroll
                for (int dd = 0; dd < 4; dd++) ak[mm][dd] += av[mm]*bv[dd];
        }
        #pragma unroll
        for (int mm = 0; mm < 8; mm++) {
            float4 o4 = {ak[mm][0], ak[mm][1], ak[mm][2], ak[mm][3]};
            *(float4*)(g_kvc + ((size_t)bh*NC + c)*(MF*DHD) + (size_t)(i0+mm)*DHD + j0) = o4;
        }
    }
}

// ---------------- exclusive prefix over chunks ----------------
__global__ void k_prefix()
{
    int bh = blockIdx.x, seg = blockIdx.y, t = threadIdx.x;
    for (int e = seg*2048 + t; e < (seg+1)*2048; e += 256) {
        float run = 0.f;
        #pragma unroll
        for (int c = 0; c < NC; c++) {
            size_t idx = ((size_t)bh*NC + c)*(MF*DHD) + e;
            g_kvp[idx] = run; run += g_kvc[idx];
        }
    }
    if (seg == 0) {
        for (int e = t; e < MF; e += 256) {
            float run = 0.f;
            #pragma unroll
            for (int c = 0; c < NC; c++) {
                size_t idx = ((size_t)bh*NC + c)*MF + e;
                g_ksp[idx] = run; run += g_ksc[idx];
            }
        }
    }
}

// ---------- cross terms + normalization; emits bf16 hi/lo of o for WO GEMM ------
__global__ __launch_bounds__(512) void k_cross(const float* __restrict__ qp)
{
    extern __shared__ float sm[];
    float* sQ = sm;
    float* sP = sm + 128*132;
    float* sS = sP + 128*132;
    float* sD = sS + 128;
    int blk = blockIdx.x, bh = blk >> 4, c = blk & 15;
    int b = bh >> 3, hh = bh & 7;
    int t = threadIdx.x;
    int ty = t >> 5, tx = t & 31;
    int i0 = ty*8, j0 = tx*4;
    const float* qb = qp + ((size_t)bh*SS + c*CHUNK)*MF;

    #pragma unroll
    for (int rr = 0; rr < 8; rr++) {
        int f = rr*512 + t;
        int i = f >> 5;
        int m4 = (f & 31) << 2;
        float4 qv = *(const float4*)(qb + (size_t)i*MF + m4);
        sQ[(m4+0)*132+i]=qv.x; sQ[(m4+1)*132+i]=qv.y; sQ[(m4+2)*132+i]=qv.z; sQ[(m4+3)*132+i]=qv.w;
        *(float4*)&sP[i*132 + m4] =
            *(const float4*)(g_kvp + ((size_t)bh*NC + c)*(MF*DHD) + (size_t)i*DHD + m4);
    }
    if (t < 128) sS[t] = g_ksp[((size_t)bh*NC + c)*MF + t];
    __syncthreads();
    if (t < 128) {
        float dc = 0.f;
        for (int m = 0; m < 128; m++) dc += sQ[m*132 + t]*sS[m];
        sD[t] = g_den[(size_t)bh*SS + c*CHUNK + t] + dc + 1e-6f;
    }
    __syncthreads();

    float ac[8][4] = {};
    for (int m = 0; m < 128; m++) {
        float4 x0 = *(const float4*)&sQ[m*132 + i0];
        float4 x1 = *(const float4*)&sQ[m*132 + i0 + 4];
        float4 y  = *(const float4*)&sP[m*132 + j0];
        float av[8] = {x0.x,x0.y,x0.z,x0.w,x1.x,x1.y,x1.z,x1.w};
        float bv[4] = {y.x,y.y,y.z,y.w};
        #pragma unroll
        for (int ii = 0; ii < 8; ii++)
            #pragma unroll
            for (int dd = 0; dd < 4; dd++) ac[ii][dd] += av[ii]*bv[dd];
    }
    #pragma unroll
    for (int ii = 0; ii < 8; ii++) {
        float inv = 1.0f / sD[i0 + ii];
        size_t base = ((size_t)(b*SS + c*CHUNK + i0 + ii)*HH + hh)*DHD + j0;
        float4 o4 = *(float4*)(g_o + base);
        float vals[4] = { (o4.x + ac[ii][0])*inv, (o4.y + ac[ii][1])*inv,
                          (o4.z + ac[ii][2])*inv, (o4.w + ac[ii][3])*inv };
        __nv_bfloat16 hh4[4], ll4[4];
        #pragma unroll
        for (int j = 0; j < 4; j++) split_bf16(vals[j], hh4[j], ll4[j]);
        *(__nv_bfloat162*)(g_oh + base)   = *(__nv_bfloat162*)&hh4[0];
        *(__nv_bfloat162*)(g_oh + base+2) = *(__nv_bfloat162*)&hh4[2];
        *(__nv_bfloat162*)(g_ol + base)   = *(__nv_bfloat162*)&ll4[0];
        *(__nv_bfloat162*)(g_ol + base+2) = *(__nv_bfloat162*)&ll4[2];
    }
}

// ---------------- pooling ----------------
__global__ void k_pool()
{
    int b = blockIdx.x, seg = blockIdx.y, t = threadIdx.x;
    float acc = 0.f;
    for (int s = seg*128; s < (seg+1)*128; s++) acc += g_h[((size_t)b*SS + s)*DIMC + t];
    g_pp[(b*16 + seg)*DIMC + t] = acc;
}

__global__ void k_final(const float* __restrict__ fw, const float* __restrict__ fb,
                        float* __restrict__ out)
{
    __shared__ float pooled[BB*DIMC];
    int t = threadIdx.x;
    for (int b = 0; b < BB; b++) {
        float a = 0.f;
        #pragma unroll
        for (int s = 0; s < 16; s++) a += g_pp[(b*16 + s)*DIMC + t];
        pooled[b*DIMC + t] = a * (1.0f/SS);
    }
    __syncthreads();
    if (t < BB*NCLS) {
        int b = t / NCLS, c = t % NCLS;
        float acc = fb[c];
        for (int d = 0; d < DIMC; d++) acc += pooled[b*DIMC + d]*fw[d*NCLS + c];
        out[t] = acc;
    }
}

// ---------------- host driver ----------------
static void* sym(const void* s) { void* p = nullptr; cudaGetSymbolAddress(&p, s); return p; }

extern "C" void kernel_launch(void* const* d_in, const int* in_sizes, int n_in,
                              void* d_out, int out_size)
{
    const float* x     = (const float*)d_in[0];
    const float* lin_w = (const float*)d_in[1];
    const float* lin_b = (const float*)d_in[2];
    const float* pe    = (const float*)d_in[3];
    const float* proj  = (const float*)d_in[4];
    const float* ln1_g = (const float*)d_in[5];
    const float* ln1_b = (const float*)d_in[6];
    const float* wq    = (const float*)d_in[7];
    const float* wk    = (const float*)d_in[8];
    const float* wv    = (const float*)d_in[9];
    const float* wo    = (const float*)d_in[10];
    const float* wo_b  = (const float*)d_in[11];
    const float* ln2_g = (const float*)d_in[12];
    const float* ln2_b = (const float*)d_in[13];
    const float* ff1_w = (const float*)d_in[14];
    const float* ff1_b = (const float*)d_in[15];
    const float* ff2_w = (const float*)d_in[16];
    const float* ff2_b = (const float*)d_in[17];
    const float* fin_w = (const float*)d_in[18];
    const float* fin_b = (const float*)d_in[19];
    float* out = (float*)d_out;

    float* ph  = (float*)sym(g_h);
    float* pq  = (float*)sym(g_q);
    float* pk  = (float*)sym(g_k);
    float* pv  = (float*)sym(g_v);
    float* pqp = (float*)sym(g_qp);
    float* pkp = (float*)sym(g_kp);
    float* pdq = (float*)sym(g_diagq);
    float* pdk = (float*)sym(g_diagk);
    float* pbm = (float*)sym(g_bmax);

    __nv_bfloat16* yh  = (__nv_bfloat16*)sym(g_yh);
    __nv_bfloat16* yl  = (__nv_bfloat16*)sym(g_yl);
    __nv_bfloat16* wth = (__nv_bfloat16*)sym(g_wth);
    __nv_bfloat16* wtl = (__nv_bfloat16*)sym(g_wtl);
    __nv_bfloat16* qnh = (__nv_bfloat16*)sym(g_qnh);
    __nv_bfloat16* qnl = (__nv_bfloat16*)sym(g_qnl);
    __nv_bfloat16* knh = (__nv_bfloat16*)sym(g_knh);
    __nv_bfloat16* knl = (__nv_bfloat16*)sym(g_knl);
    __nv_bfloat16* oh  = (__nv_bfloat16*)sym(g_oh);
    __nv_bfloat16* ol  = (__nv_bfloat16*)sym(g_ol);
    __nv_bfloat16* fh  = (__nv_bfloat16*)sym(g_fh);
    __nv_bfloat16* fl  = (__nv_bfloat16*)sym(g_fl);

    const int SMEM_MMA   = 4*128*SROW*2;            // 73728
    const int SMEM_CHUNK = 3*128*132*4;             // 202752
    const int SMEM_CROSS = (2*128*132 + 256)*4;     // 136192
    cudaFuncSetAttribute(k_mma<0>, cudaFuncAttributeMaxDynamicSharedMemorySize, SMEM_MMA);
    cudaFuncSetAttribute(k_mma<1>, cudaFuncAttributeMaxDynamicSharedMemorySize, SMEM_MMA);
    cudaFuncSetAttribute(k_mma<2>, cudaFuncAttributeMaxDynamicSharedMemorySize, SMEM_MMA);
    cudaFuncSetAttribute(k_mma<3>, cudaFuncAttributeMaxDynamicSharedMemorySize, SMEM_MMA);
    cudaFuncSetAttribute(k_mma<4>, cudaFuncAttributeMaxDynamicSharedMemorySize, SMEM_MMA);
    cudaFuncSetAttribute(k_chunk, cudaFuncAttributeMaxDynamicSharedMemorySize, SMEM_CHUNK);
    cudaFuncSetAttribute(k_cross, cudaFuncAttributeMaxDynamicSharedMemorySize, SMEM_CROSS);

    k_embed<<<BSR/8, 256>>>(x, lin_w, lin_b, pe);

    for (int l = 0; l < DEPTH; l++) {
        const float* prj = proj + (size_t)l*MF*DHD;

        k_wt<<<512, 256>>>(wq + (size_t)l*DIMC*INNER, wth+WT_Q, wtl+WT_Q, DIMC, INNER);
        k_wt<<<512, 256>>>(wk + (size_t)l*DIMC*INNER, wth+WT_K, wtl+WT_K, DIMC, INNER);
        k_wt<<<512, 256>>>(wv + (size_t)l*DIMC*INNER, wth+WT_V, wtl+WT_V, DIMC, INNER);
        k_wt<<<512, 256>>>(wo + (size_t)l*INNER*DIMC, wth+WT_O, wtl+WT_O, INNER, DIMC);
        k_wt<<<256, 256>>>(ff1_w + (size_t)l*DIMC*FFD, wth+WT_F1, wtl+WT_F1, DIMC, FFD);
        k_wt<<<256, 256>>>(ff2_w + (size_t)l*FFD*DIMC, wth+WT_F2, wtl+WT_F2, FFD, DIMC);
        k_cvt<<<16, 256>>>(prj, wth+WT_PJ, wtl+WT_PJ, MF*DHD/4);

        k_ln<<<BSR/8, 256>>>(ph, ln1_g + l*DIMC, ln1_b + l*DIMC, yh, yl);

        // QKV via HMMA
        k_mma<0><<<dim3(8,64), 256, SMEM_MMA>>>(yh, yl, DIMC, wth+WT_Q, wtl+WT_Q, DIMC, INNER,
                                                nullptr, pq, nullptr, nullptr, nullptr, nullptr);
        k_mma<0><<<dim3(8,64), 256, SMEM_MMA>>>(yh, yl, DIMC, wth+WT_K, wtl+WT_K, DIMC, INNER,
                                                nullptr, pk, nullptr, nullptr, nullptr, nullptr);
        k_mma<0><<<dim3(8,64), 256, SMEM_MMA>>>(yh, yl, DIMC, wth+WT_V, wtl+WT_V, DIMC, INNER,
                                                nullptr, pv, nullptr, nullptr, nullptr, nullptr);

        k_cvt_qk<<<BHS/8, 256>>>(pq, qnh, qnl, pdq);
        k_cvt_qk<<<BHS/8, 256>>>(pk, knh, knl, pdk);

        // K features: dd + blockmax, then stab + exp
        k_mma<4><<<dim3(1,512), 256, SMEM_MMA>>>(knh, knl, DHD, wth+WT_PJ, wtl+WT_PJ, DHD, MF,
                                                 nullptr, pkp, nullptr, nullptr, nullptr, pbm);
        k_stab2<<<1, 32>>>();
        k_fek<<<BHS/8, 256>>>(pkp, pdk);
        // Q features: fused exp
        k_mma<3><<<dim3(1,512), 256, SMEM_MMA>>>(qnh, qnl, DHD, wth+WT_PJ, wtl+WT_PJ, DHD, MF,
                                                 nullptr, pqp, nullptr, nullptr, pdq, nullptr);

        // chunked causal linear attention (fp32)
        k_chunk<<<NBH*NC, 512, SMEM_CHUNK>>>(pqp, pkp, pv);
        k_prefix<<<dim3(NBH, 8), 256>>>();
        k_cross<<<NBH*NC, 512, SMEM_CROSS>>>(pqp);

        // output projection + residual
        k_mma<2><<<dim3(1,64), 256, SMEM_MMA>>>(oh, ol, INNER, wth+WT_O, wtl+WT_O, INNER, DIMC,
                                                wo_b + l*DIMC, ph, nullptr, nullptr, nullptr, nullptr);
        // FFN
        k_ln<<<BSR/8, 256>>>(ph, ln2_g + l*DIMC, ln2_b + l*DIMC, yh, yl);
        k_mma<1><<<dim3(4,64), 256, SMEM_MMA>>>(yh, yl, DIMC, wth+WT_F1, wtl+WT_F1, DIMC, FFD,
                                                ff1_b + l*FFD, nullptr, fh, fl, nullptr, nullptr);
        k_mma<2><<<dim3(1,64), 256, SMEM_MMA>>>(fh, fl, FFD, wth+WT_F2, wtl+WT_F2, FFD, DIMC,
                                                ff2_b + l*DIMC, ph, nullptr, nullptr, nullptr, nullptr);
    }

    k_pool<<<dim3(BB, 16), 128>>>();
    k_final<<<1, 128>>>(fin_w, fin_b, out);
}

// round 5
// speedup vs baseline: 1.7029x; 1.4535x over previous
#include <cuda_runtime.h>
#include <cuda_bf16.h>
#include <math.h>
#include <stdint.h>

// ---------------- problem constants ----------------
#define BB 4
#define SS 2048
#define DIMC 128
#define HH 8
#define DHD 128
#define DEPTH 2
#define NCLS 10
#define MF 128
#define CHUNK 128
#define NC 16
#define INNER 1024
#define FFD 512
#define BSR 8192
#define BHS 65536
#define NBH 32

#define NORMC 0.29730177875068026f
#define RATIOC 0.08838834764831845f

// ---------------- device scratch (fp32) ----------------
__device__ float g_h  [BSR*DIMC];
__device__ float g_q  [BSR*INNER];
__device__ float g_k  [BSR*INNER];
__device__ float g_v  [BSR*INNER];
__device__ float g_kp [(size_t)NBH*SS*MF];       // K features dd (pre-exp)
__device__ float g_diagq[BHS];
__device__ float g_diagk[BHS];
__device__ float g_bmax[NBH*16];
__device__ float g_stab[NBH];
__device__ float g_o  [BSR*INNER];               // local num, [B,S,H,DH]
__device__ float g_den[BHS];
__device__ float g_kvc[(size_t)NBH*NC*MF*DHD];
__device__ float g_ksc[NBH*NC*MF];
__device__ float g_ksp[NBH*NC*MF];
__device__ float g_pp [BB*16*DIMC];

// ---------------- device scratch (bf16 hi/lo) ----------------
__device__ __align__(256) __nv_bfloat16 g_yh [BSR*DIMC];
__device__ __align__(256) __nv_bfloat16 g_yl [BSR*DIMC];
__device__ __align__(256) __nv_bfloat16 g_wth[672000];
__device__ __align__(256) __nv_bfloat16 g_wtl[672000];
__device__ __align__(256) __nv_bfloat16 g_qnh[(size_t)BHS*DHD];
__device__ __align__(256) __nv_bfloat16 g_qnl[(size_t)BHS*DHD];
__device__ __align__(256) __nv_bfloat16 g_knh[(size_t)BHS*DHD];
__device__ __align__(256) __nv_bfloat16 g_knl[(size_t)BHS*DHD];
__device__ __align__(256) __nv_bfloat16 g_qph[(size_t)NBH*SS*MF];
__device__ __align__(256) __nv_bfloat16 g_qpl[(size_t)NBH*SS*MF];
__device__ __align__(256) __nv_bfloat16 g_kph[(size_t)NBH*SS*MF];
__device__ __align__(256) __nv_bfloat16 g_kpl[(size_t)NBH*SS*MF];
__device__ __align__(256) __nv_bfloat16 g_kvph[(size_t)NBH*NC*MF*DHD];
__device__ __align__(256) __nv_bfloat16 g_kvpl[(size_t)NBH*NC*MF*DHD];
__device__ __align__(256) __nv_bfloat16 g_oh [(size_t)BSR*INNER];
__device__ __align__(256) __nv_bfloat16 g_ol [(size_t)BSR*INNER];
__device__ __align__(256) __nv_bfloat16 g_fh [(size_t)BSR*FFD];
__device__ __align__(256) __nv_bfloat16 g_fl [(size_t)BSR*FFD];

#define WT_Q  0
#define WT_K  131072
#define WT_V  262144
#define WT_O  393216
#define WT_F1 524288
#define WT_F2 589824
#define WT_PJ 655360

// ---------------- warp MMA helpers ----------------
__device__ __forceinline__ uint32_t s2u(const void* p){
    uint32_t a;
    asm("{ .reg .u64 t; cvta.to.shared.u64 t, %1; cvt.u32.u64 %0, t; }" : "=r"(a) : "l"(p));
    return a;
}
__device__ __forceinline__ void ldsm4(uint32_t* r, uint32_t addr){
    asm volatile("ldmatrix.sync.aligned.m8n8.x4.shared.b16 {%0,%1,%2,%3}, [%4];"
                 : "=r"(r[0]),"=r"(r[1]),"=r"(r[2]),"=r"(r[3]) : "r"(addr));
}
__device__ __forceinline__ void ldsm4t(uint32_t* r, uint32_t addr){
    asm volatile("ldmatrix.sync.aligned.m8n8.x4.trans.shared.b16 {%0,%1,%2,%3}, [%4];"
                 : "=r"(r[0]),"=r"(r[1]),"=r"(r[2]),"=r"(r[3]) : "r"(addr));
}
__device__ __forceinline__ void mma_bf16(float* c, const uint32_t* a, const uint32_t* b){
    asm volatile("mma.sync.aligned.m16n8k16.row.col.f32.bf16.bf16.f32 "
                 "{%0,%1,%2,%3}, {%4,%5,%6,%7}, {%8,%9}, {%0,%1,%2,%3};"
                 : "+f"(c[0]),"+f"(c[1]),"+f"(c[2]),"+f"(c[3])
                 : "r"(a[0]),"r"(a[1]),"r"(a[2]),"r"(a[3]), "r"(b[0]),"r"(b[1]));
}
__device__ __forceinline__ void split_bf16(float v, __nv_bfloat16& h, __nv_bfloat16& l){
    h = __float2bfloat16(v);
    l = __float2bfloat16(v - __bfloat162float(h));
}
__device__ __forceinline__ float gelu(float xx){
    return 0.5f*xx*(1.0f + tanhf(0.7978845608028654f*(xx + 0.044715f*xx*xx*xx)));
}
// trans-ldsm lane address for 16x16 block of S[k][n] (pitch P elements):
// covers (kbase..+16) x (nbase..+16); fragments come out as
// d0=(n0-7,k0-7) d1=(n8-15,k0-7) d2=(n0-7,k8-15) d3=(n8-15,k8-15)
__device__ __forceinline__ uint32_t taddr(const __nv_bfloat16* S, int P, int kbase, int nbase, int lane){
    int kk = (lane & 7) + ((lane >> 4) << 3);
    int nn = ((lane >> 3) & 1) << 3;
    return s2u(S + (size_t)(kbase + kk)*P + nbase + nn);
}

// ============ HMMA GEMM (verified) ============
#define SROW 72
template<int MODE>
__global__ __launch_bounds__(256) void k_mma(
    const __nv_bfloat16* __restrict__ Ah, const __nv_bfloat16* __restrict__ Al, int lda,
    const __nv_bfloat16* __restrict__ Bh, const __nv_bfloat16* __restrict__ Bl,
    int Ktot, int Nt,
    const float* __restrict__ bias,
    float* __restrict__ out,
    __nv_bfloat16* __restrict__ outH, __nv_bfloat16* __restrict__ outL,
    const float* __restrict__ diag, float* __restrict__ bmax)
{
    extern __shared__ __align__(16) char dsm[];
    __nv_bfloat16* sAh = (__nv_bfloat16*)dsm;
    __nv_bfloat16* sAl = sAh + 128*SROW;
    __nv_bfloat16* sBh = sAl + 128*SROW;
    __nv_bfloat16* sBl = sBh + 128*SROW;
    __shared__ float s_rm[2][128];
    __shared__ float s_red[256];

    const int t = threadIdx.x, w = t >> 5, lane = t & 31;
    const int wm = w & 3, wn = w >> 2;
    const int row0 = blockIdx.y*128, col0 = blockIdx.x*128;

    float acc[2][8][4] = {};
    const int lrow = (lane & 15), lcol8 = (lane >> 4)*8;

    for (int kc = 0; kc < Ktot; kc += 64) {
        #pragma unroll
        for (int i = 0; i < 4; i++) {
            int f = i*256 + t;
            int r = f >> 3, c8 = (f & 7) << 3;
            *(uint4*)(sAh + r*SROW + c8) = *(const uint4*)(Ah + (size_t)(row0+r)*lda + kc + c8);
            *(uint4*)(sAl + r*SROW + c8) = *(const uint4*)(Al + (size_t)(row0+r)*lda + kc + c8);
            *(uint4*)(sBh + r*SROW + c8) = *(const uint4*)(Bh + (size_t)(col0+r)*Ktot + kc + c8);
            *(uint4*)(sBl + r*SROW + c8) = *(const uint4*)(Bl + (size_t)(col0+r)*Ktot + kc + c8);
        }
        __syncthreads();
        #pragma unroll
        for (int ks = 0; ks < 4; ks++) {
            int kcol = ks*16 + lcol8;
            uint32_t ah[2][4], al[2][4];
            #pragma unroll
            for (int mt = 0; mt < 2; mt++) {
                int arow = wm*32 + mt*16 + lrow;
                ldsm4(ah[mt], s2u(sAh + arow*SROW + kcol));
                ldsm4(al[mt], s2u(sAl + arow*SROW + kcol));
            }
            #pragma unroll
            for (int nt2 = 0; nt2 < 4; nt2++) {
                int brow = wn*64 + nt2*16 + lrow;
                uint32_t rh[4], rl[4];
                ldsm4(rh, s2u(sBh + brow*SROW + kcol));
                ldsm4(rl, s2u(sBl + brow*SROW + kcol));
                uint32_t b0h[2] = {rh[0], rh[2]}, b1h[2] = {rh[1], rh[3]};
                uint32_t b0l[2] = {rl[0], rl[2]}, b1l[2] = {rl[1], rl[3]};
                #pragma unroll
                for (int mt = 0; mt < 2; mt++) {
                    mma_bf16(acc[mt][nt2*2],   ah[mt], b0h);
                    mma_bf16(acc[mt][nt2*2],   ah[mt], b0l);
                    mma_bf16(acc[mt][nt2*2],   al[mt], b0h);
                    mma_bf16(acc[mt][nt2*2+1], ah[mt], b1h);
                    mma_bf16(acc[mt][nt2*2+1], ah[mt], b1l);
                    mma_bf16(acc[mt][nt2*2+1], al[mt], b1h);
                }
            }
        }
        __syncthreads();
    }

    const int rl4 = lane >> 2;
    const int cl2 = (lane & 3)*2;

    if (MODE == 0 || MODE == 4) {
        #pragma unroll
        for (int mt = 0; mt < 2; mt++)
            #pragma unroll
            for (int h = 0; h < 2; h++) {
                int gr = row0 + wm*32 + mt*16 + rl4 + h*8;
                #pragma unroll
                for (int nt = 0; nt < 8; nt++) {
                    float2 v = {acc[mt][nt][h*2], acc[mt][nt][h*2+1]};
                    *(float2*)(out + (size_t)gr*Nt + col0 + wn*64 + nt*8 + cl2) = v;
                }
            }
        if (MODE == 4) {
            float bm = -1e30f;
            #pragma unroll
            for (int mt = 0; mt < 2; mt++)
                #pragma unroll
                for (int nt = 0; nt < 8; nt++)
                    #pragma unroll
                    for (int f = 0; f < 4; f++) bm = fmaxf(bm, acc[mt][nt][f]);
            s_red[t] = bm; __syncthreads();
            #pragma unroll
            for (int o = 128; o > 0; o >>= 1) { if (t < o) s_red[t] = fmaxf(s_red[t], s_red[t+o]); __syncthreads(); }
            if (t == 0) bmax[blockIdx.y] = s_red[0];
        }
    } else if (MODE == 1) {
        #pragma unroll
        for (int mt = 0; mt < 2; mt++)
            #pragma unroll
            for (int h = 0; h < 2; h++) {
                int gr = row0 + wm*32 + mt*16 + rl4 + h*8;
                #pragma unroll
                for (int nt = 0; nt < 8; nt++) {
                    int gc = col0 + wn*64 + nt*8 + cl2;
                    float v0 = gelu(acc[mt][nt][h*2]   + bias[gc]);
                    float v1 = gelu(acc[mt][nt][h*2+1] + bias[gc+1]);
                    __nv_bfloat16 h0,l0,h1,l1;
                    split_bf16(v0,h0,l0); split_bf16(v1,h1,l1);
                    __nv_bfloat162 hp, lp;
                    hp.x = h0; hp.y = h1; lp.x = l0; lp.y = l1;
                    *(__nv_bfloat162*)(outH + (size_t)gr*Nt + gc) = hp;
                    *(__nv_bfloat162*)(outL + (size_t)gr*Nt + gc) = lp;
                }
            }
    } else if (MODE == 2) {
        #pragma unroll
        for (int mt = 0; mt < 2; mt++)
            #pragma unroll
            for (int h = 0; h < 2; h++) {
                int gr = row0 + wm*32 + mt*16 + rl4 + h*8;
                #pragma unroll
                for (int nt = 0; nt < 8; nt++) {
                    int gc = col0 + wn*64 + nt*8 + cl2;
                    size_t idx = (size_t)gr*Nt + gc;
                    float2 v = *(float2*)(out + idx);
                    v.x += acc[mt][nt][h*2]   + bias[gc];
                    v.y += acc[mt][nt][h*2+1] + bias[gc+1];
                    *(float2*)(out + idx) = v;
                }
            }
    } else { // MODE 3: Q features -> bf16 hi/lo
        float rm[2][2];
        #pragma unroll
        for (int mt = 0; mt < 2; mt++)
            #pragma unroll
            for (int h = 0; h < 2; h++) {
                float m = -1e30f;
                #pragma unroll
                for (int nt = 0; nt < 8; nt++)
                    m = fmaxf(m, fmaxf(acc[mt][nt][h*2], acc[mt][nt][h*2+1]));
                m = fmaxf(m, __shfl_xor_sync(0xffffffffu, m, 1));
                m = fmaxf(m, __shfl_xor_sync(0xffffffffu, m, 2));
                rm[mt][h] = m;
            }
        if ((lane & 3) == 0) {
            #pragma unroll
            for (int mt = 0; mt < 2; mt++)
                #pragma unroll
                for (int h = 0; h < 2; h++)
                    s_rm[wn][wm*32 + mt*16 + rl4 + h*8] = rm[mt][h];
        }
        __syncthreads();
        #pragma unroll
        for (int mt = 0; mt < 2; mt++)
            #pragma unroll
            for (int h = 0; h < 2; h++) {
                int lr = wm*32 + mt*16 + rl4 + h*8;
                int gr = row0 + lr;
                float rmax = fmaxf(s_rm[0][lr], s_rm[1][lr]);
                float dg = diag[gr];
                #pragma unroll
                for (int nt = 0; nt < 8; nt++) {
                    int gc = wn*64 + nt*8 + cl2;
                    float v0 = RATIOC*(expf(acc[mt][nt][h*2]  -dg-rmax) + 1e-4f);
                    float v1 = RATIOC*(expf(acc[mt][nt][h*2+1]-dg-rmax) + 1e-4f);
                    __nv_bfloat16 h0,l0,h1,l1;
                    split_bf16(v0,h0,l0); split_bf16(v1,h1,l1);
                    __nv_bfloat162 hp, lp;
                    hp.x = h0; hp.y = h1; lp.x = l0; lp.y = l1;
                    *(__nv_bfloat162*)(outH + (size_t)gr*Nt + gc) = hp;
                    *(__nv_bfloat162*)(outL + (size_t)gr*Nt + gc) = lp;
                }
            }
    }
}

// ---------------- embed ----------------
__global__ void k_embed(const float* __restrict__ x, const float* __restrict__ lw,
                        const float* __restrict__ lb, const float* __restrict__ pe)
{
    int warp = threadIdx.x >> 5, lane = threadIdx.x & 31;
    int r = blockIdx.x*8 + warp;
    float xv = x[r];
    float4 l4 = ((const float4*)lw)[lane];
    float4 b4 = ((const float4*)lb)[lane];
    float4 p4 = ((const float4*)(pe + (size_t)(r % SS)*DIMC))[lane];
    float4 o4 = { xv*l4.x + b4.x + p4.x, xv*l4.y + b4.y + p4.y,
                  xv*l4.z + b4.z + p4.z, xv*l4.w + b4.w + p4.w };
    ((float4*)(g_h + (size_t)r*DIMC))[lane] = o4;
}

// ---------------- layernorm -> bf16 hi/lo ----------------
__global__ void k_ln(const float* __restrict__ in, const float* __restrict__ g,
                     const float* __restrict__ b,
                     __nv_bfloat16* __restrict__ outH, __nv_bfloat16* __restrict__ outL)
{
    int warp = threadIdx.x >> 5, lane = threadIdx.x & 31;
    int r = blockIdx.x*8 + warp;
    float4 v = ((const float4*)(in + (size_t)r*DIMC))[lane];
    float s = v.x + v.y + v.z + v.w;
    #pragma unroll
    for (int o = 16; o > 0; o >>= 1) s += __shfl_xor_sync(0xffffffffu, s, o);
    float mu = s * (1.0f/DIMC);
    float dx = v.x-mu, dy = v.y-mu, dz = v.z-mu, dw = v.w-mu;
    float q = dx*dx + dy*dy + dz*dz + dw*dw;
    #pragma unroll
    for (int o = 16; o > 0; o >>= 1) q += __shfl_xor_sync(0xffffffffu, q, o);
    float inv = rsqrtf(q*(1.0f/DIMC) + 1e-5f);
    float4 gv = ((const float4*)g)[lane];
    float4 bv = ((const float4*)b)[lane];
    float o4[4] = { dx*inv*gv.x + bv.x, dy*inv*gv.y + bv.y,
                    dz*inv*gv.z + bv.z, dw*inv*gv.w + bv.w };
    __nv_bfloat16 hh[4], ll[4];
    #pragma unroll
    for (int j = 0; j < 4; j++) split_bf16(o4[j], hh[j], ll[j]);
    size_t base = (size_t)r*DIMC + lane*4;
    *(uint2*)(outH+base) = *(uint2*)hh;
    *(uint2*)(outL+base) = *(uint2*)ll;
}

// -------- weight transpose+split (smem-tiled, coalesced both sides) --------
__global__ __launch_bounds__(256) void k_wt(const float* __restrict__ W,
                                            __nv_bfloat16* __restrict__ outH,
                                            __nv_bfloat16* __restrict__ outL, int K, int N)
{
    __shared__ float tile[32][33];
    int n0 = blockIdx.x*32, k0 = blockIdx.y*32;
    int tx = threadIdx.x & 31, ty = threadIdx.x >> 5;
    #pragma unroll
    for (int i = ty; i < 32; i += 8)
        tile[i][tx] = W[(size_t)(k0+i)*N + n0 + tx];
    __syncthreads();
    #pragma unroll
    for (int i = ty; i < 32; i += 8) {
        float v = tile[tx][i];
        __nv_bfloat16 hh, ll;
        split_bf16(v, hh, ll);
        outH[(size_t)(n0+i)*K + k0 + tx] = hh;
        outL[(size_t)(n0+i)*K + k0 + tx] = ll;
    }
}

// ---------------- plain split (proj, already K-major) ----------------
__global__ void k_cvt(const float* __restrict__ in, __nv_bfloat16* __restrict__ outH,
                      __nv_bfloat16* __restrict__ outL, int n4)
{
    int i = blockIdx.x*256 + threadIdx.x;
    if (i >= n4) return;
    float4 v = ((const float4*)in)[i];
    __nv_bfloat16 hh[4], ll[4];
    split_bf16(v.x, hh[0], ll[0]); split_bf16(v.y, hh[1], ll[1]);
    split_bf16(v.z, hh[2], ll[2]); split_bf16(v.w, hh[3], ll[3]);
    *(uint2*)(outH + i*4) = *(uint2*)hh;
    *(uint2*)(outL + i*4) = *(uint2*)ll;
}

// ------- q/k convert: [B,S,H,DH] fp32 -> [B,H,S,DH] bf16 hi/lo *NORMC + diag -----
__global__ void k_cvt_qk(const float* __restrict__ in, __nv_bfloat16* __restrict__ outH,
                         __nv_bfloat16* __restrict__ outL, float* __restrict__ diag)
{
    int warp = threadIdx.x >> 5, lane = threadIdx.x & 31;
    int wr = blockIdx.x*8 + warp;
    int b = wr >> 14, h = (wr >> 11) & 7, s = wr & 2047;
    const float* src = in + ((size_t)(b*SS + s)*HH + h)*DHD;
    float4 v = ((const float4*)src)[lane];
    v.x *= NORMC; v.y *= NORMC; v.z *= NORMC; v.w *= NORMC;
    float sq = v.x*v.x + v.y*v.y + v.z*v.z + v.w*v.w;
    #pragma unroll
    for (int o = 16; o > 0; o >>= 1) sq += __shfl_xor_sync(0xffffffffu, sq, o);
    if (lane == 0) diag[wr] = 0.5f*sq;
    __nv_bfloat16 hh[4], ll[4];
    split_bf16(v.x, hh[0], ll[0]); split_bf16(v.y, hh[1], ll[1]);
    split_bf16(v.z, hh[2], ll[2]); split_bf16(v.w, hh[3], ll[3]);
    size_t base = (size_t)wr*DHD + lane*4;
    *(uint2*)(outH+base) = *(uint2*)hh;
    *(uint2*)(outL+base) = *(uint2*)ll;
}

// ---------------- stab reduce ----------------
__global__ void k_stab2()
{
    int bh = threadIdx.x;
    if (bh < NBH) {
        float m = -1e30f;
        #pragma unroll
        for (int i = 0; i < 16; i++) m = fmaxf(m, g_bmax[bh*16 + i]);
        g_stab[bh] = m;
    }
}

// ---------------- key feature exp -> bf16 hi/lo ----------------
__global__ void k_fek(const float* __restrict__ dd, const float* __restrict__ diag,
                      __nv_bfloat16* __restrict__ outH, __nv_bfloat16* __restrict__ outL)
{
    int r = blockIdx.x*8 + (threadIdx.x >> 5);
    int lane = threadIdx.x & 31;
    float st = g_stab[r >> 11];
    float dg = diag[r];
    float4 v = ((const float4*)(dd + (size_t)r*MF))[lane];
    float o[4] = { RATIOC*(expf(v.x-dg-st) + 1e-4f), RATIOC*(expf(v.y-dg-st) + 1e-4f),
                   RATIOC*(expf(v.z-dg-st) + 1e-4f), RATIOC*(expf(v.w-dg-st) + 1e-4f) };
    __nv_bfloat16 hh[4], ll[4];
    #pragma unroll
    for (int j = 0; j < 4; j++) split_bf16(o[j], hh[j], ll[j]);
    size_t base = (size_t)r*MF + lane*4;
    *(uint2*)(outH+base) = *(uint2*)hh;
    *(uint2*)(outL+base) = *(uint2*)ll;
}

// ================= chunk-local attention via HMMA =================
// per block = (b,h,c). attn = tril(Q@K^T); num=attn@V -> g_o; den; kv=K^T@V; ksc.
#define CP 136
__global__ __launch_bounds__(256) void k_chunk(
    const __nv_bfloat16* __restrict__ qph, const __nv_bfloat16* __restrict__ qpl,
    const __nv_bfloat16* __restrict__ kph, const __nv_bfloat16* __restrict__ kpl,
    const float* __restrict__ v)
{
    extern __shared__ __align__(16) __nv_bfloat16 cs[];
    __nv_bfloat16* sQh = cs;                    // Q^... [i][m]; later attn [i][j]
    __nv_bfloat16* sQl = sQh + 128*CP;
    __nv_bfloat16* sKh = sQl + 128*CP;          // [j][m]
    __nv_bfloat16* sKl = sKh + 128*CP;
    __nv_bfloat16* sVh = sKl + 128*CP;          // [j][d]
    __nv_bfloat16* sVl = sVh + 128*CP;
    __shared__ float s_den[2][128];

    int blk = blockIdx.x, bh = blk >> 4, c = blk & 15;
    int b = bh >> 3, hh = bh & 7;
    int t = threadIdx.x, w = t >> 5, lane = t & 31;
    int wm = w & 3, wn = w >> 2;
    const int lrow = lane & 15, lcol8 = (lane >> 4)*8;
    const int rl4 = lane >> 2, cl2 = (lane & 3)*2;

    const size_t qbase = ((size_t)bh*SS + c*CHUNK)*MF;
    for (int i = t; i < 2048; i += 256) {
        int r = i >> 4, c8 = (i & 15) << 3;
        *(uint4*)(sQh + r*CP + c8) = *(const uint4*)(qph + qbase + r*MF + c8);
        *(uint4*)(sQl + r*CP + c8) = *(const uint4*)(qpl + qbase + r*MF + c8);
        *(uint4*)(sKh + r*CP + c8) = *(const uint4*)(kph + qbase + r*MF + c8);
        *(uint4*)(sKl + r*CP + c8) = *(const uint4*)(kpl + qbase + r*MF + c8);
    }
    for (int i = t; i < 4096; i += 256) {
        int r = i >> 5, c4 = (i & 31) << 2;
        float4 vv = *(const float4*)(v + ((size_t)(b*SS + c*CHUNK + r)*HH + hh)*DHD + c4);
        __nv_bfloat16 hh4[4], ll4[4];
        split_bf16(vv.x, hh4[0], ll4[0]); split_bf16(vv.y, hh4[1], ll4[1]);
        split_bf16(vv.z, hh4[2], ll4[2]); split_bf16(vv.w, hh4[3], ll4[3]);
        *(uint2*)(sVh + r*CP + c4) = *(uint2*)hh4;
        *(uint2*)(sVl + r*CP + c4) = *(uint2*)ll4;
    }
    __syncthreads();

    // ---- phase 1: attn = Q@K^T (K-dim = m = 128) ----
    float acc[2][8][4] = {};
    #pragma unroll
    for (int ks = 0; ks < 8; ks++) {
        int kcol = ks*16 + lcol8;
        uint32_t ah[2][4], al[2][4];
        #pragma unroll
        for (int mt = 0; mt < 2; mt++) {
            int arow = wm*32 + mt*16 + lrow;
            ldsm4(ah[mt], s2u(sQh + arow*CP + kcol));
            ldsm4(al[mt], s2u(sQl + arow*CP + kcol));
        }
        #pragma unroll
        for (int nt2 = 0; nt2 < 4; nt2++) {
            int brow = wn*64 + nt2*16 + lrow;
            uint32_t rh[4], rl[4];
            ldsm4(rh, s2u(sKh + brow*CP + kcol));
            ldsm4(rl, s2u(sKl + brow*CP + kcol));
            uint32_t b0h[2] = {rh[0], rh[2]}, b1h[2] = {rh[1], rh[3]};
            uint32_t b0l[2] = {rl[0], rl[2]}, b1l[2] = {rl[1], rl[3]};
            #pragma unroll
            for (int mt = 0; mt < 2; mt++) {
                mma_bf16(acc[mt][nt2*2],   ah[mt], b0h);
                mma_bf16(acc[mt][nt2*2],   ah[mt], b0l);
                mma_bf16(acc[mt][nt2*2],   al[mt], b0h);
                mma_bf16(acc[mt][nt2*2+1], ah[mt], b1h);
                mma_bf16(acc[mt][nt2*2+1], ah[mt], b1l);
                mma_bf16(acc[mt][nt2*2+1], al[mt], b1h);
            }
        }
    }
    // mask + den partials
    float dp[2][2] = {};
    #pragma unroll
    for (int mt = 0; mt < 2; mt++)
        #pragma unroll
        for (int nt = 0; nt < 8; nt++)
            #pragma unroll
            for (int f = 0; f < 4; f++) {
                int i = wm*32 + mt*16 + rl4 + ((f>>1)<<3);
                int j = wn*64 + nt*8 + cl2 + (f&1);
                if (j > i) acc[mt][nt][f] = 0.f;
                dp[mt][f>>1] += acc[mt][nt][f];
            }
    #pragma unroll
    for (int o = 1; o < 4; o <<= 1)
        #pragma unroll
        for (int mt = 0; mt < 2; mt++)
            #pragma unroll
            for (int h2 = 0; h2 < 2; h2++)
                dp[mt][h2] += __shfl_xor_sync(0xffffffffu, dp[mt][h2], o);
    if ((lane & 3) == 0) {
        #pragma unroll
        for (int mt = 0; mt < 2; mt++)
            #pragma unroll
            for (int h2 = 0; h2 < 2; h2++)
                s_den[wn][wm*32 + mt*16 + rl4 + h2*8] = dp[mt][h2];
    }
    __syncthreads();

    // overwrite sQ with masked attn (hi/lo)
    #pragma unroll
    for (int mt = 0; mt < 2; mt++)
        #pragma unroll
        for (int nt = 0; nt < 8; nt++)
            #pragma unroll
            for (int f = 0; f < 4; f++) {
                int i = wm*32 + mt*16 + rl4 + ((f>>1)<<3);
                int j = wn*64 + nt*8 + cl2 + (f&1);
                __nv_bfloat16 hh2, ll2;
                split_bf16(acc[mt][nt][f], hh2, ll2);
                sQh[i*CP + j] = hh2;
                sQl[i*CP + j] = ll2;
            }
    // den + ksc
    if (t < 128) {
        g_den[(size_t)bh*SS + c*CHUNK + t] = s_den[0][t] + s_den[1][t];
        float kssum = 0.f;
        for (int j = 0; j < 128; j++)
            kssum += __bfloat162float(sKh[j*CP + t]) + __bfloat162float(sKl[j*CP + t]);
        g_ksc[((size_t)bh*NC + c)*MF + t] = kssum;
    }
    __syncthreads();

    // ---- phase 2: num = attn @ V  (A = sQ non-trans, B = V trans) ----
    #pragma unroll
    for (int mt = 0; mt < 2; mt++)
        #pragma unroll
        for (int nt = 0; nt < 8; nt++)
            #pragma unroll
            for (int f = 0; f < 4; f++) acc[mt][nt][f] = 0.f;
    #pragma unroll
    for (int ks = 0; ks < 8; ks++) {
        int kcol = ks*16 + lcol8;
        uint32_t ah[2][4], al[2][4];
        #pragma unroll
        for (int mt = 0; mt < 2; mt++) {
            int arow = wm*32 + mt*16 + lrow;
            ldsm4(ah[mt], s2u(sQh + arow*CP + kcol));
            ldsm4(al[mt], s2u(sQl + arow*CP + kcol));
        }
        #pragma unroll
        for (int nt2 = 0; nt2 < 4; nt2++) {
            int nbase = wn*64 + nt2*16;
            uint32_t dh[4], dl[4];
            ldsm4t(dh, taddr(sVh, CP, ks*16, nbase, lane));
            ldsm4t(dl, taddr(sVl, CP, ks*16, nbase, lane));
            uint32_t b0h[2] = {dh[0], dh[2]}, b1h[2] = {dh[1], dh[3]};
            uint32_t b0l[2] = {dl[0], dl[2]}, b1l[2] = {dl[1], dl[3]};
            #pragma unroll
            for (int mt = 0; mt < 2; mt++) {
                mma_bf16(acc[mt][nt2*2],   ah[mt], b0h);
                mma_bf16(acc[mt][nt2*2],   ah[mt], b0l);
                mma_bf16(acc[mt][nt2*2],   al[mt], b0h);
                mma_bf16(acc[mt][nt2*2+1], ah[mt], b1h);
                mma_bf16(acc[mt][nt2*2+1], ah[mt], b1l);
                mma_bf16(acc[mt][nt2*2+1], al[mt], b1h);
            }
        }
    }
    #pragma unroll
    for (int mt = 0; mt < 2; mt++)
        #pragma unroll
        for (int h2 = 0; h2 < 2; h2++) {
            int i = wm*32 + mt*16 + rl4 + h2*8;
            size_t base = ((size_t)(b*SS + c*CHUNK + i)*HH + hh)*DHD;
            #pragma unroll
            for (int nt = 0; nt < 8; nt++) {
                float2 vv = {acc[mt][nt][h2*2], acc[mt][nt][h2*2+1]};
                *(float2*)(g_o + base + wn*64 + nt*8 + cl2) = vv;
            }
        }

    // ---- phase 3: kv = K^T @ V  (A = sK trans, B = V trans) ----
    #pragma unroll
    for (int mt = 0; mt < 2; mt++)
        #pragma unroll
        for (int nt = 0; nt < 8; nt++)
            #pragma unroll
            for (int f = 0; f < 4; f++) acc[mt][nt][f] = 0.f;
    #pragma unroll
    for (int ks = 0; ks < 8; ks++) {
        uint32_t ah[2][4], al[2][4];
        #pragma unroll
        for (int mt = 0; mt < 2; mt++) {
            int mbase = wm*32 + mt*16;
            ldsm4t(ah[mt], taddr(sKh, CP, ks*16, mbase, lane));
            ldsm4t(al[mt], taddr(sKl, CP, ks*16, mbase, lane));
        }
        #pragma unroll
        for (int nt2 = 0; nt2 < 4; nt2++) {
            int nbase = wn*64 + nt2*16;
            uint32_t dh[4], dl[4];
            ldsm4t(dh, taddr(sVh, CP, ks*16, nbase, lane));
            ldsm4t(dl, taddr(sVl, CP, ks*16, nbase, lane));
            uint32_t b0h[2] = {dh[0], dh[2]}, b1h[2] = {dh[1], dh[3]};
            uint32_t b0l[2] = {dl[0], dl[2]}, b1l[2] = {dl[1], dl[3]};
            #pragma unroll
            for (int mt = 0; mt < 2; mt++) {
                mma_bf16(acc[mt][nt2*2],   ah[mt], b0h);
                mma_bf16(acc[mt][nt2*2],   ah[mt], b0l);
                mma_bf16(acc[mt][nt2*2],   al[mt], b0h);
                mma_bf16(acc[mt][nt2*2+1], ah[mt], b1h);
                mma_bf16(acc[mt][nt2*2+1], ah[mt], b1l);
                mma_bf16(acc[mt][nt2*2+1], al[mt], b1h);
            }
        }
    }
    {
        size_t kvbase = ((size_t)bh*NC + c)*(MF*DHD);
        #pragma unroll
        for (int mt = 0; mt < 2; mt++)
            #pragma unroll
            for (int h2 = 0; h2 < 2; h2++) {
                int m = wm*32 + mt*16 + rl4 + h2*8;
                #pragma unroll
                for (int nt = 0; nt < 8; nt++) {
                    float2 vv = {acc[mt][nt][h2*2], acc[mt][nt][h2*2+1]};
                    *(float2*)(g_kvc + kvbase + (size_t)m*DHD + wn*64 + nt*8 + cl2) = vv;
                }
            }
    }
}

// ---------------- exclusive prefix over chunks (emits bf16 hi/lo) ----------------
__global__ void k_prefix()
{
    int bh = blockIdx.x, seg = blockIdx.y, t = threadIdx.x;
    for (int e = seg*2048 + t; e < (seg+1)*2048; e += 256) {
        float run = 0.f;
        #pragma unroll
        for (int c = 0; c < NC; c++) {
            size_t idx = ((size_t)bh*NC + c)*(MF*DHD) + e;
            __nv_bfloat16 hh, ll;
            split_bf16(run, hh, ll);
            g_kvph[idx] = hh; g_kvpl[idx] = ll;
            run += g_kvc[idx];
        }
    }
    if (seg == 0) {
        for (int e = t; e < MF; e += 256) {
            float run = 0.f;
            #pragma unroll
            for (int c = 0; c < NC; c++) {
                size_t idx = ((size_t)bh*NC + c)*MF + e;
                g_ksp[idx] = run; run += g_ksc[idx];
            }
        }
    }
}

// ========== cross = qp @ kvp, + num, normalize, split -> oh/ol (HMMA) ==========
__global__ __launch_bounds__(256) void k_cross(
    const __nv_bfloat16* __restrict__ qph, const __nv_bfloat16* __restrict__ qpl)
{
    extern __shared__ __align__(16) __nv_bfloat16 cs[];
    __nv_bfloat16* sQh = cs;                    // [i][m]
    __nv_bfloat16* sQl = sQh + 128*CP;
    __nv_bfloat16* sPh = sQl + 128*CP;          // kvp [m][d]
    __nv_bfloat16* sPl = sPh + 128*CP;
    __shared__ float s_ks[128];
    __shared__ float s_dc[128];

    int blk = blockIdx.x, bh = blk >> 4, c = blk & 15;
    int b = bh >> 3, hh = bh & 7;
    int t = threadIdx.x, w = t >> 5, lane = t & 31;
    int wm = w & 3, wn = w >> 2;
    const int lrow = lane & 15, lcol8 = (lane >> 4)*8;
    const int rl4 = lane >> 2, cl2 = (lane & 3)*2;

    const size_t qbase = ((size_t)bh*SS + c*CHUNK)*MF;
    const size_t pbase = ((size_t)bh*NC + c)*(MF*DHD);
    for (int i = t; i < 2048; i += 256) {
        int r = i >> 4, c8 = (i & 15) << 3;
        *(uint4*)(sQh + r*CP + c8) = *(const uint4*)(qph + qbase + r*MF + c8);
        *(uint4*)(sQl + r*CP + c8) = *(const uint4*)(qpl + qbase + r*MF + c8);
        *(uint4*)(sPh + r*CP + c8) = *(const uint4*)(g_kvph + pbase + r*DHD + c8);
        *(uint4*)(sPl + r*CP + c8) = *(const uint4*)(g_kvpl + pbase + r*DHD + c8);
    }
    if (t < 128) s_ks[t] = g_ksp[((size_t)bh*NC + c)*MF + t];
    __syncthreads();
    if (t < 128) {
        float dc = 0.f;
        for (int m = 0; m < 128; m++)
            dc += (__bfloat162float(sQh[t*CP + m]) + __bfloat162float(sQl[t*CP + m]))*s_ks[m];
        s_dc[t] = g_den[(size_t)bh*SS + c*CHUNK + t] + dc + 1e-6f;
    }
    __syncthreads();

    float acc[2][8][4] = {};
    #pragma unroll
    for (int ks = 0; ks < 8; ks++) {
        int kcol = ks*16 + lcol8;
        uint32_t ah[2][4], al[2][4];
        #pragma unroll
        for (int mt = 0; mt < 2; mt++) {
            int arow = wm*32 + mt*16 + lrow;
            ldsm4(ah[mt], s2u(sQh + arow*CP + kcol));
            ldsm4(al[mt], s2u(sQl + arow*CP + kcol));
        }
        #pragma unroll
        for (int nt2 = 0; nt2 < 4; nt2++) {
            int nbase = wn*64 + nt2*16;
            uint32_t dh[4], dl[4];
            ldsm4t(dh, taddr(sPh, CP, ks*16, nbase, lane));
            ldsm4t(dl, taddr(sPl, CP, ks*16, nbase, lane));
            uint32_t b0h[2] = {dh[0], dh[2]}, b1h[2] = {dh[1], dh[3]};
            uint32_t b0l[2] = {dl[0], dl[2]}, b1l[2] = {dl[1], dl[3]};
            #pragma unroll
            for (int mt = 0; mt < 2; mt++) {
                mma_bf16(acc[mt][nt2*2],   ah[mt], b0h);
                mma_bf16(acc[mt][nt2*2],   ah[mt], b0l);
                mma_bf16(acc[mt][nt2*2],   al[mt], b0h);
                mma_bf16(acc[mt][nt2*2+1], ah[mt], b1h);
                mma_bf16(acc[mt][nt2*2+1], ah[mt], b1l);
                mma_bf16(acc[mt][nt2*2+1], al[mt], b1h);
            }
        }
    }
    #pragma unroll
    for (int mt = 0; mt < 2; mt++)
        #pragma unroll
        for (int h2 = 0; h2 < 2; h2++) {
            int i = wm*32 + mt*16 + rl4 + h2*8;
            float inv = 1.0f / s_dc[i];
            size_t base = ((size_t)(b*SS + c*CHUNK + i)*HH + hh)*DHD;
            #pragma unroll
            for (int nt = 0; nt < 8; nt++) {
                size_t idx = base + wn*64 + nt*8 + cl2;
                float2 nn = *(float2*)(g_o + idx);
                float v0 = (nn.x + acc[mt][nt][h2*2])   * inv;
                float v1 = (nn.y + acc[mt][nt][h2*2+1]) * inv;
                __nv_bfloat16 h0,l0,h1,l1;
                split_bf16(v0,h0,l0); split_bf16(v1,h1,l1);
                __nv_bfloat162 hp, lp;
                hp.x = h0; hp.y = h1; lp.x = l0; lp.y = l1;
                *(__nv_bfloat162*)(g_oh + idx) = hp;
                *(__nv_bfloat162*)(g_ol + idx) = lp;
            }
        }
}

// ---------------- pooling ----------------
__global__ void k_pool()
{
    int b = blockIdx.x, seg = blockIdx.y, t = threadIdx.x;
    float acc = 0.f;
    for (int s = seg*128; s < (seg+1)*128; s++) acc += g_h[((size_t)b*SS + s)*DIMC + t];
    g_pp[(b*16 + seg)*DIMC + t] = acc;
}

__global__ void k_final(const float* __restrict__ fw, const float* __restrict__ fb,
                        float* __restrict__ out)
{
    __shared__ float pooled[BB*DIMC];
    int t = threadIdx.x;
    for (int b = 0; b < BB; b++) {
        float a = 0.f;
        #pragma unroll
        for (int s = 0; s < 16; s++) a += g_pp[(b*16 + s)*DIMC + t];
        pooled[b*DIMC + t] = a * (1.0f/SS);
    }
    __syncthreads();
    if (t < BB*NCLS) {
        int b = t / NCLS, c = t % NCLS;
        float acc = fb[c];
        for (int d = 0; d < DIMC; d++) acc += pooled[b*DIMC + d]*fw[d*NCLS + c];
        out[t] = acc;
    }
}

// ---------------- host driver ----------------
static void* sym(const void* s) { void* p = nullptr; cudaGetSymbolAddress(&p, s); return p; }

extern "C" void kernel_launch(void* const* d_in, const int* in_sizes, int n_in,
                              void* d_out, int out_size)
{
    const float* x     = (const float*)d_in[0];
    const float* lin_w = (const float*)d_in[1];
    const float* lin_b = (const float*)d_in[2];
    const float* pe    = (const float*)d_in[3];
    const float* proj  = (const float*)d_in[4];
    const float* ln1_g = (const float*)d_in[5];
    const float* ln1_b = (const float*)d_in[6];
    const float* wq    = (const float*)d_in[7];
    const float* wk    = (const float*)d_in[8];
    const float* wv    = (const float*)d_in[9];
    const float* wo    = (const float*)d_in[10];
    const float* wo_b  = (const float*)d_in[11];
    const float* ln2_g = (const float*)d_in[12];
    const float* ln2_b = (const float*)d_in[13];
    const float* ff1_w = (const float*)d_in[14];
    const float* ff1_b = (const float*)d_in[15];
    const float* ff2_w = (const float*)d_in[16];
    const float* ff2_b = (const float*)d_in[17];
    const float* fin_w = (const float*)d_in[18];
    const float* fin_b = (const float*)d_in[19];
    float* out = (float*)d_out;

    float* ph  = (float*)sym(g_h);
    float* pq  = (float*)sym(g_q);
    float* pk  = (float*)sym(g_k);
    float* pv  = (float*)sym(g_v);
    float* pkp = (float*)sym(g_kp);
    float* pdq = (float*)sym(g_diagq);
    float* pdk = (float*)sym(g_diagk);
    float* pbm = (float*)sym(g_bmax);

    __nv_bfloat16* yh  = (__nv_bfloat16*)sym(g_yh);
    __nv_bfloat16* yl  = (__nv_bfloat16*)sym(g_yl);
    __nv_bfloat16* wth = (__nv_bfloat16*)sym(g_wth);
    __nv_bfloat16* wtl = (__nv_bfloat16*)sym(g_wtl);
    __nv_bfloat16* qnh = (__nv_bfloat16*)sym(g_qnh);
    __nv_bfloat16* qnl = (__nv_bfloat16*)sym(g_qnl);
    __nv_bfloat16* knh = (__nv_bfloat16*)sym(g_knh);
    __nv_bfloat16* knl = (__nv_bfloat16*)sym(g_knl);
    __nv_bfloat16* qp_h = (__nv_bfloat16*)sym(g_qph);
    __nv_bfloat16* qp_l = (__nv_bfloat16*)sym(g_qpl);
    __nv_bfloat16* kp_h = (__nv_bfloat16*)sym(g_kph);
    __nv_bfloat16* kp_l = (__nv_bfloat16*)sym(g_kpl);
    __nv_bfloat16* oh  = (__nv_bfloat16*)sym(g_oh);
    __nv_bfloat16* ol  = (__nv_bfloat16*)sym(g_ol);
    __nv_bfloat16* fh  = (__nv_bfloat16*)sym(g_fh);
    __nv_bfloat16* fl  = (__nv_bfloat16*)sym(g_fl);

    const int SMEM_MMA   = 4*128*SROW*2;        // 73728
    const int SMEM_CHUNK = 6*128*CP*2;          // 208896
    const int SMEM_CROSS = 4*128*CP*2;          // 139264
    cudaFuncSetAttribute(k_mma<0>, cudaFuncAttributeMaxDynamicSharedMemorySize, SMEM_MMA);
    cudaFuncSetAttribute(k_mma<1>, cudaFuncAttributeMaxDynamicSharedMemorySize, SMEM_MMA);
    cudaFuncSetAttribute(k_mma<2>, cudaFuncAttributeMaxDynamicSharedMemorySize, SMEM_MMA);
    cudaFuncSetAttribute(k_mma<3>, cudaFuncAttributeMaxDynamicSharedMemorySize, SMEM_MMA);
    cudaFuncSetAttribute(k_mma<4>, cudaFuncAttributeMaxDynamicSharedMemorySize, SMEM_MMA);
    cudaFuncSetAttribute(k_chunk, cudaFuncAttributeMaxDynamicSharedMemorySize, SMEM_CHUNK);
    cudaFuncSetAttribute(k_cross, cudaFuncAttributeMaxDynamicSharedMemorySize, SMEM_CROSS);

    k_embed<<<BSR/8, 256>>>(x, lin_w, lin_b, pe);

    for (int l = 0; l < DEPTH; l++) {
        const float* prj = proj + (size_t)l*MF*DHD;

        k_wt<<<dim3(INNER/32, DIMC/32), 256>>>(wq + (size_t)l*DIMC*INNER, wth+WT_Q, wtl+WT_Q, DIMC, INNER);
        k_wt<<<dim3(INNER/32, DIMC/32), 256>>>(wk + (size_t)l*DIMC*INNER, wth+WT_K, wtl+WT_K, DIMC, INNER);
        k_wt<<<dim3(INNER/32, DIMC/32), 256>>>(wv + (size_t)l*DIMC*INNER, wth+WT_V, wtl+WT_V, DIMC, INNER);
        k_wt<<<dim3(DIMC/32, INNER/32), 256>>>(wo + (size_t)l*INNER*DIMC, wth+WT_O, wtl+WT_O, INNER, DIMC);
        k_wt<<<dim3(FFD/32, DIMC/32), 256>>>(ff1_w + (size_t)l*DIMC*FFD, wth+WT_F1, wtl+WT_F1, DIMC, FFD);
        k_wt<<<dim3(DIMC/32, FFD/32), 256>>>(ff2_w + (size_t)l*FFD*DIMC, wth+WT_F2, wtl+WT_F2, FFD, DIMC);
        k_cvt<<<16, 256>>>(prj, wth+WT_PJ, wtl+WT_PJ, MF*DHD/4);

        k_ln<<<BSR/8, 256>>>(ph, ln1_g + l*DIMC, ln1_b + l*DIMC, yh, yl);

        k_mma<0><<<dim3(8,64), 256, SMEM_MMA>>>(yh, yl, DIMC, wth+WT_Q, wtl+WT_Q, DIMC, INNER,
                                                nullptr, pq, nullptr, nullptr, nullptr, nullptr);
        k_mma<0><<<dim3(8,64), 256, SMEM_MMA>>>(yh, yl, DIMC, wth+WT_K, wtl+WT_K, DIMC, INNER,
                                                nullptr, pk, nullptr, nullptr, nullptr, nullptr);
        k_mma<0><<<dim3(8,64), 256, SMEM_MMA>>>(yh, yl, DIMC, wth+WT_V, wtl+WT_V, DIMC, INNER,
                                                nullptr, pv, nullptr, nullptr, nullptr, nullptr);

        k_cvt_qk<<<BHS/8, 256>>>(pq, qnh, qnl, pdq);
        k_cvt_qk<<<BHS/8, 256>>>(pk, knh, knl, pdk);

        k_mma<4><<<dim3(1,512), 256, SMEM_MMA>>>(knh, knl, DHD, wth+WT_PJ, wtl+WT_PJ, DHD, MF,
                                                 nullptr, pkp, nullptr, nullptr, nullptr, pbm);
        k_stab2<<<1, 32>>>();
        k_fek<<<BHS/8, 256>>>(pkp, pdk, kp_h, kp_l);
        k_mma<3><<<dim3(1,512), 256, SMEM_MMA>>>(qnh, qnl, DHD, wth+WT_PJ, wtl+WT_PJ, DHD, MF,
                                                 nullptr, nullptr, qp_h, qp_l, pdq, nullptr);

        k_chunk<<<NBH*NC, 256, SMEM_CHUNK>>>(qp_h, qp_l, kp_h, kp_l, pv);
        k_prefix<<<dim3(NBH, 8), 256>>>();
        k_cross<<<NBH*NC, 256, SMEM_CROSS>>>(qp_h, qp_l);

        k_mma<2><<<dim3(1,64), 256, SMEM_MMA>>>(oh, ol, INNER, wth+WT_O, wtl+WT_O, INNER, DIMC,
                                                wo_b + l*DIMC, ph, nullptr, nullptr, nullptr, nullptr);

        k_ln<<<BSR/8, 256>>>(ph, ln2_g + l*DIMC, ln2_b + l*DIMC, yh, yl);
        k_mma<1><<<dim3(4,64), 256, SMEM_MMA>>>(yh, yl, DIMC, wth+WT_F1, wtl+WT_F1, DIMC, FFD,
                                                ff1_b + l*FFD, nullptr, fh, fl, nullptr, nullptr);
        k_mma<2><<<dim3(1,64), 256, SMEM_MMA>>>(fh, fl, FFD, wth+WT_F2, wtl+WT_F2, FFD, DIMC,
                                                ff2_b + l*DIMC, ph, nullptr, nullptr, nullptr, nullptr);
    }

    k_pool<<<dim3(BB, 16), 128>>>();
    k_final<<<1, 128>>>(fin_w, fin_b, out);
}

// round 6
// speedup vs baseline: 2.0149x; 1.1832x over previous
#include <cuda_runtime.h>
#include <cuda_bf16.h>
#include <math.h>
#include <stdint.h>

// ---------------- problem constants ----------------
#define BB 4
#define SS 2048
#define DIMC 128
#define HH 8
#define DHD 128
#define DEPTH 2
#define NCLS 10
#define MF 128
#define CHUNK 128
#define NC 16
#define INNER 1024
#define FFD 512
#define BSR 8192
#define BHS 65536
#define NBH 32

#define NORMC 0.29730177875068026f
#define RATIOC 0.08838834764831845f

// ---------------- device scratch (fp32) ----------------
__device__ float g_h  [BSR*DIMC];
__device__ float g_qkv[(size_t)BSR*3*INNER];     // fused QKV out, row stride 3072
__device__ float g_kp [(size_t)NBH*SS*MF];
__device__ float g_diagq[BHS];
__device__ float g_diagk[BHS];
__device__ float g_bmax[NBH*16];
__device__ float g_stab[NBH];
__device__ float g_o  [BSR*INNER];               // local num, [B,S,H,DH]
__device__ float g_den[BHS];
__device__ float g_kvc[(size_t)NBH*NC*MF*DHD];
__device__ float g_ksc[NBH*NC*MF];
__device__ float g_ksp[NBH*NC*MF];
__device__ float g_pp [BB*16*DIMC];

// ---------------- device scratch (bf16 hi/lo) ----------------
__device__ __align__(256) __nv_bfloat16 g_yh [BSR*DIMC];
__device__ __align__(256) __nv_bfloat16 g_yl [BSR*DIMC];
__device__ __align__(256) __nv_bfloat16 g_wth[2*672000];
__device__ __align__(256) __nv_bfloat16 g_wtl[2*672000];
__device__ __align__(256) __nv_bfloat16 g_qnh[(size_t)BHS*DHD];
__device__ __align__(256) __nv_bfloat16 g_qnl[(size_t)BHS*DHD];
__device__ __align__(256) __nv_bfloat16 g_knh[(size_t)BHS*DHD];
__device__ __align__(256) __nv_bfloat16 g_knl[(size_t)BHS*DHD];
__device__ __align__(256) __nv_bfloat16 g_qph[(size_t)NBH*SS*MF];
__device__ __align__(256) __nv_bfloat16 g_qpl[(size_t)NBH*SS*MF];
__device__ __align__(256) __nv_bfloat16 g_kph[(size_t)NBH*SS*MF];
__device__ __align__(256) __nv_bfloat16 g_kpl[(size_t)NBH*SS*MF];
__device__ __align__(256) __nv_bfloat16 g_kvph[(size_t)NBH*NC*MF*DHD];
__device__ __align__(256) __nv_bfloat16 g_kvpl[(size_t)NBH*NC*MF*DHD];
__device__ __align__(256) __nv_bfloat16 g_oh [(size_t)BSR*INNER];
__device__ __align__(256) __nv_bfloat16 g_ol [(size_t)BSR*INNER];
__device__ __align__(256) __nv_bfloat16 g_fh [(size_t)BSR*FFD];
__device__ __align__(256) __nv_bfloat16 g_fl [(size_t)BSR*FFD];

#define WT_Q  0
#define WT_K  131072
#define WT_V  262144
#define WT_O  393216
#define WT_F1 524288
#define WT_F2 589824
#define WT_PJ 655360
#define WT_LAYER 672000

// ---------------- warp MMA helpers ----------------
__device__ __forceinline__ uint32_t s2u(const void* p){
    uint32_t a;
    asm("{ .reg .u64 t; cvta.to.shared.u64 t, %1; cvt.u32.u64 %0, t; }" : "=r"(a) : "l"(p));
    return a;
}
__device__ __forceinline__ void ldsm4(uint32_t* r, uint32_t addr){
    asm volatile("ldmatrix.sync.aligned.m8n8.x4.shared.b16 {%0,%1,%2,%3}, [%4];"
                 : "=r"(r[0]),"=r"(r[1]),"=r"(r[2]),"=r"(r[3]) : "r"(addr));
}
__device__ __forceinline__ void ldsm4t(uint32_t* r, uint32_t addr){
    asm volatile("ldmatrix.sync.aligned.m8n8.x4.trans.shared.b16 {%0,%1,%2,%3}, [%4];"
                 : "=r"(r[0]),"=r"(r[1]),"=r"(r[2]),"=r"(r[3]) : "r"(addr));
}
__device__ __forceinline__ void mma_bf16(float* c, const uint32_t* a, const uint32_t* b){
    asm volatile("mma.sync.aligned.m16n8k16.row.col.f32.bf16.bf16.f32 "
                 "{%0,%1,%2,%3}, {%4,%5,%6,%7}, {%8,%9}, {%0,%1,%2,%3};"
                 : "+f"(c[0]),"+f"(c[1]),"+f"(c[2]),"+f"(c[3])
                 : "r"(a[0]),"r"(a[1]),"r"(a[2]),"r"(a[3]), "r"(b[0]),"r"(b[1]));
}
__device__ __forceinline__ void split_bf16(float v, __nv_bfloat16& h, __nv_bfloat16& l){
    h = __float2bfloat16(v);
    l = __float2bfloat16(v - __bfloat162float(h));
}
__device__ __forceinline__ float gelu(float xx){
    return 0.5f*xx*(1.0f + tanhf(0.7978845608028654f*(xx + 0.044715f*xx*xx*xx)));
}
__device__ __forceinline__ uint32_t taddr(const __nv_bfloat16* S, int P, int kbase, int nbase, int lane){
    int kk = (lane & 7) + ((lane >> 4) << 3);
    int nn = ((lane >> 3) & 1) << 3;
    return s2u(S + (size_t)(kbase + kk)*P + nbase + nn);
}

// ============ HMMA GEMM 128x128 tile (wide-N GEMMs) ============
#define SROW 72
template<int MODE>
__global__ __launch_bounds__(256) void k_mma(
    const __nv_bfloat16* __restrict__ Ah, const __nv_bfloat16* __restrict__ Al, int lda,
    const __nv_bfloat16* __restrict__ Bh, const __nv_bfloat16* __restrict__ Bl,
    int Ktot, int Nt,
    const float* __restrict__ bias,
    float* __restrict__ out,
    __nv_bfloat16* __restrict__ outH, __nv_bfloat16* __restrict__ outL,
    const float* __restrict__ diag, float* __restrict__ bmax)
{
    extern __shared__ __align__(16) char dsm[];
    __nv_bfloat16* sAh = (__nv_bfloat16*)dsm;
    __nv_bfloat16* sAl = sAh + 128*SROW;
    __nv_bfloat16* sBh = sAl + 128*SROW;
    __nv_bfloat16* sBl = sBh + 128*SROW;
    __shared__ float s_rm[2][128];
    __shared__ float s_red[256];

    const int t = threadIdx.x, w = t >> 5, lane = t & 31;
    const int wm = w & 3, wn = w >> 2;
    const int row0 = blockIdx.y*128, col0 = blockIdx.x*128;

    float acc[2][8][4] = {};
    const int lrow = (lane & 15), lcol8 = (lane >> 4)*8;

    for (int kc = 0; kc < Ktot; kc += 64) {
        #pragma unroll
        for (int i = 0; i < 4; i++) {
            int f = i*256 + t;
            int r = f >> 3, c8 = (f & 7) << 3;
            *(uint4*)(sAh + r*SROW + c8) = *(const uint4*)(Ah + (size_t)(row0+r)*lda + kc + c8);
            *(uint4*)(sAl + r*SROW + c8) = *(const uint4*)(Al + (size_t)(row0+r)*lda + kc + c8);
            *(uint4*)(sBh + r*SROW + c8) = *(const uint4*)(Bh + (size_t)(col0+r)*Ktot + kc + c8);
            *(uint4*)(sBl + r*SROW + c8) = *(const uint4*)(Bl + (size_t)(col0+r)*Ktot + kc + c8);
        }
        __syncthreads();
        #pragma unroll
        for (int ks = 0; ks < 4; ks++) {
            int kcol = ks*16 + lcol8;
            uint32_t ah[2][4], al[2][4];
            #pragma unroll
            for (int mt = 0; mt < 2; mt++) {
                int arow = wm*32 + mt*16 + lrow;
                ldsm4(ah[mt], s2u(sAh + arow*SROW + kcol));
                ldsm4(al[mt], s2u(sAl + arow*SROW + kcol));
            }
            #pragma unroll
            for (int nt2 = 0; nt2 < 4; nt2++) {
                int brow = wn*64 + nt2*16 + lrow;
                uint32_t rh[4], rl[4];
                ldsm4(rh, s2u(sBh + brow*SROW + kcol));
                ldsm4(rl, s2u(sBl + brow*SROW + kcol));
                uint32_t b0h[2] = {rh[0], rh[2]}, b1h[2] = {rh[1], rh[3]};
                uint32_t b0l[2] = {rl[0], rl[2]}, b1l[2] = {rl[1], rl[3]};
                #pragma unroll
                for (int mt = 0; mt < 2; mt++) {
                    mma_bf16(acc[mt][nt2*2],   ah[mt], b0h);
                    mma_bf16(acc[mt][nt2*2],   ah[mt], b0l);
                    mma_bf16(acc[mt][nt2*2],   al[mt], b0h);
                    mma_bf16(acc[mt][nt2*2+1], ah[mt], b1h);
                    mma_bf16(acc[mt][nt2*2+1], ah[mt], b1l);
                    mma_bf16(acc[mt][nt2*2+1], al[mt], b1h);
                }
            }
        }
        __syncthreads();
    }

    const int rl4 = lane >> 2;
    const int cl2 = (lane & 3)*2;

    if (MODE == 0 || MODE == 4) {
        #pragma unroll
        for (int mt = 0; mt < 2; mt++)
            #pragma unroll
            for (int h = 0; h < 2; h++) {
                int gr = row0 + wm*32 + mt*16 + rl4 + h*8;
                #pragma unroll
                for (int nt = 0; nt < 8; nt++) {
                    float2 v = {acc[mt][nt][h*2], acc[mt][nt][h*2+1]};
                    *(float2*)(out + (size_t)gr*Nt + col0 + wn*64 + nt*8 + cl2) = v;
                }
            }
        if (MODE == 4) {
            float bm = -1e30f;
            #pragma unroll
            for (int mt = 0; mt < 2; mt++)
                #pragma unroll
                for (int nt = 0; nt < 8; nt++)
                    #pragma unroll
                    for (int f = 0; f < 4; f++) bm = fmaxf(bm, acc[mt][nt][f]);
            s_red[t] = bm; __syncthreads();
            #pragma unroll
            for (int o = 128; o > 0; o >>= 1) { if (t < o) s_red[t] = fmaxf(s_red[t], s_red[t+o]); __syncthreads(); }
            if (t == 0) bmax[blockIdx.y] = s_red[0];
        }
    } else if (MODE == 1) {
        #pragma unroll
        for (int mt = 0; mt < 2; mt++)
            #pragma unroll
            for (int h = 0; h < 2; h++) {
                int gr = row0 + wm*32 + mt*16 + rl4 + h*8;
                #pragma unroll
                for (int nt = 0; nt < 8; nt++) {
                    int gc = col0 + wn*64 + nt*8 + cl2;
                    float v0 = gelu(acc[mt][nt][h*2]   + bias[gc]);
                    float v1 = gelu(acc[mt][nt][h*2+1] + bias[gc+1]);
                    __nv_bfloat16 h0,l0,h1,l1;
                    split_bf16(v0,h0,l0); split_bf16(v1,h1,l1);
                    __nv_bfloat162 hp, lp;
                    hp.x = h0; hp.y = h1; lp.x = l0; lp.y = l1;
                    *(__nv_bfloat162*)(outH + (size_t)gr*Nt + gc) = hp;
                    *(__nv_bfloat162*)(outL + (size_t)gr*Nt + gc) = lp;
                }
            }
    } else { // MODE 3: Q features -> bf16 hi/lo
        float rm[2][2];
        #pragma unroll
        for (int mt = 0; mt < 2; mt++)
            #pragma unroll
            for (int h = 0; h < 2; h++) {
                float m = -1e30f;
                #pragma unroll
                for (int nt = 0; nt < 8; nt++)
                    m = fmaxf(m, fmaxf(acc[mt][nt][h*2], acc[mt][nt][h*2+1]));
                m = fmaxf(m, __shfl_xor_sync(0xffffffffu, m, 1));
                m = fmaxf(m, __shfl_xor_sync(0xffffffffu, m, 2));
                rm[mt][h] = m;
            }
        if ((lane & 3) == 0) {
            #pragma unroll
            for (int mt = 0; mt < 2; mt++)
                #pragma unroll
                for (int h = 0; h < 2; h++)
                    s_rm[wn][wm*32 + mt*16 + rl4 + h*8] = rm[mt][h];
        }
        __syncthreads();
        #pragma unroll
        for (int mt = 0; mt < 2; mt++)
            #pragma unroll
            for (int h = 0; h < 2; h++) {
                int lr = wm*32 + mt*16 + rl4 + h*8;
                int gr = row0 + lr;
                float rmax = fmaxf(s_rm[0][lr], s_rm[1][lr]);
                float dg = diag[gr];
                #pragma unroll
                for (int nt = 0; nt < 8; nt++) {
                    int gc = wn*64 + nt*8 + cl2;
                    float v0 = RATIOC*(expf(acc[mt][nt][h*2]  -dg-rmax) + 1e-4f);
                    float v1 = RATIOC*(expf(acc[mt][nt][h*2+1]-dg-rmax) + 1e-4f);
                    __nv_bfloat16 h0,l0,h1,l1;
                    split_bf16(v0,h0,l0); split_bf16(v1,h1,l1);
                    __nv_bfloat162 hp, lp;
                    hp.x = h0; hp.y = h1; lp.x = l0; lp.y = l1;
                    *(__nv_bfloat162*)(outH + (size_t)gr*Nt + gc) = hp;
                    *(__nv_bfloat162*)(outL + (size_t)gr*Nt + gc) = lp;
                }
            }
    }
}

// ============ HMMA GEMM 64x128 tile (narrow-N residual GEMMs: WO/FF2) ============
// out[row, 0..127] += acc + bias. grid (1, Mrows/64).
__global__ __launch_bounds__(256) void k_mma64(
    const __nv_bfloat16* __restrict__ Ah, const __nv_bfloat16* __restrict__ Al, int lda,
    const __nv_bfloat16* __restrict__ Bh, const __nv_bfloat16* __restrict__ Bl,
    int Ktot,
    const float* __restrict__ bias,
    float* __restrict__ out)
{
    extern __shared__ __align__(16) char dsm[];
    __nv_bfloat16* sAh = (__nv_bfloat16*)dsm;            // 64 x SROW
    __nv_bfloat16* sAl = sAh + 64*SROW;
    __nv_bfloat16* sBh = sAl + 64*SROW;                  // 128 x SROW
    __nv_bfloat16* sBl = sBh + 128*SROW;

    const int t = threadIdx.x, w = t >> 5, lane = t & 31;
    const int wm = w & 1, wn = w >> 1;                   // wm 0..1, wn 0..3
    const int row0 = blockIdx.y*64;

    float acc[2][4][4] = {};
    const int lrow = (lane & 15), lcol8 = (lane >> 4)*8;

    for (int kc = 0; kc < Ktot; kc += 64) {
        #pragma unroll
        for (int i = 0; i < 2; i++) {
            int f = i*256 + t;
            int r = f >> 3, c8 = (f & 7) << 3;
            *(uint4*)(sAh + r*SROW + c8) = *(const uint4*)(Ah + (size_t)(row0+r)*lda + kc + c8);
            *(uint4*)(sAl + r*SROW + c8) = *(const uint4*)(Al + (size_t)(row0+r)*lda + kc + c8);
        }
        #pragma unroll
        for (int i = 0; i < 4; i++) {
            int f = i*256 + t;
            int r = f >> 3, c8 = (f & 7) << 3;
            *(uint4*)(sBh + r*SROW + c8) = *(const uint4*)(Bh + (size_t)r*Ktot + kc + c8);
            *(uint4*)(sBl + r*SROW + c8) = *(const uint4*)(Bl + (size_t)r*Ktot + kc + c8);
        }
        __syncthreads();
        #pragma unroll
        for (int ks = 0; ks < 4; ks++) {
            int kcol = ks*16 + lcol8;
            uint32_t ah[2][4], al[2][4];
            #pragma unroll
            for (int mt = 0; mt < 2; mt++) {
                int arow = wm*32 + mt*16 + lrow;
                ldsm4(ah[mt], s2u(sAh + arow*SROW + kcol));
                ldsm4(al[mt], s2u(sAl + arow*SROW + kcol));
            }
            #pragma unroll
            for (int nt2 = 0; nt2 < 2; nt2++) {
                int brow = wn*32 + nt2*16 + lrow;
                uint32_t rh[4], rl[4];
                ldsm4(rh, s2u(sBh + brow*SROW + kcol));
                ldsm4(rl, s2u(sBl + brow*SROW + kcol));
                uint32_t b0h[2] = {rh[0], rh[2]}, b1h[2] = {rh[1], rh[3]};
                uint32_t b0l[2] = {rl[0], rl[2]}, b1l[2] = {rl[1], rl[3]};
                #pragma unroll
                for (int mt = 0; mt < 2; mt++) {
                    mma_bf16(acc[mt][nt2*2],   ah[mt], b0h);
                    mma_bf16(acc[mt][nt2*2],   ah[mt], b0l);
                    mma_bf16(acc[mt][nt2*2],   al[mt], b0h);
                    mma_bf16(acc[mt][nt2*2+1], ah[mt], b1h);
                    mma_bf16(acc[mt][nt2*2+1], ah[mt], b1l);
                    mma_bf16(acc[mt][nt2*2+1], al[mt], b1h);
                }
            }
        }
        __syncthreads();
    }

    const int rl4 = lane >> 2, cl2 = (lane & 3)*2;
    #pragma unroll
    for (int mt = 0; mt < 2; mt++)
        #pragma unroll
        for (int h2 = 0; h2 < 2; h2++) {
            int gr = row0 + wm*32 + mt*16 + rl4 + h2*8;
            #pragma unroll
            for (int nt = 0; nt < 4; nt++) {
                int gc = wn*32 + nt*8 + cl2;
                size_t idx = (size_t)gr*DIMC + gc;
                float2 v = *(float2*)(out + idx);
                v.x += acc[mt][nt][h2*2]   + bias[gc];
                v.y += acc[mt][nt][h2*2+1] + bias[gc+1];
                *(float2*)(out + idx) = v;
            }
        }
}

// ---------------- embed ----------------
__global__ void k_embed(const float* __restrict__ x, const float* __restrict__ lw,
                        const float* __restrict__ lb, const float* __restrict__ pe)
{
    int warp = threadIdx.x >> 5, lane = threadIdx.x & 31;
    int r = blockIdx.x*8 + warp;
    float xv = x[r];
    float4 l4 = ((const float4*)lw)[lane];
    float4 b4 = ((const float4*)lb)[lane];
    float4 p4 = ((const float4*)(pe + (size_t)(r % SS)*DIMC))[lane];
    float4 o4 = { xv*l4.x + b4.x + p4.x, xv*l4.y + b4.y + p4.y,
                  xv*l4.z + b4.z + p4.z, xv*l4.w + b4.w + p4.w };
    ((float4*)(g_h + (size_t)r*DIMC))[lane] = o4;
}

// ---------------- layernorm -> bf16 hi/lo ----------------
__global__ void k_ln(const float* __restrict__ in, const float* __restrict__ g,
                     const float* __restrict__ b,
                     __nv_bfloat16* __restrict__ outH, __nv_bfloat16* __restrict__ outL)
{
    int warp = threadIdx.x >> 5, lane = threadIdx.x & 31;
    int r = blockIdx.x*8 + warp;
    float4 v = ((const float4*)(in + (size_t)r*DIMC))[lane];
    float s = v.x + v.y + v.z + v.w;
    #pragma unroll
    for (int o = 16; o > 0; o >>= 1) s += __shfl_xor_sync(0xffffffffu, s, o);
    float mu = s * (1.0f/DIMC);
    float dx = v.x-mu, dy = v.y-mu, dz = v.z-mu, dw = v.w-mu;
    float q = dx*dx + dy*dy + dz*dz + dw*dw;
    #pragma unroll
    for (int o = 16; o > 0; o >>= 1) q += __shfl_xor_sync(0xffffffffu, q, o);
    float inv = rsqrtf(q*(1.0f/DIMC) + 1e-5f);
    float4 gv = ((const float4*)g)[lane];
    float4 bv = ((const float4*)b)[lane];
    float o4[4] = { dx*inv*gv.x + bv.x, dy*inv*gv.y + bv.y,
                    dz*inv*gv.z + bv.z, dw*inv*gv.w + bv.w };
    __nv_bfloat16 hh[4], ll[4];
    #pragma unroll
    for (int j = 0; j < 4; j++) split_bf16(o4[j], hh[j], ll[j]);
    size_t base = (size_t)r*DIMC + lane*4;
    *(uint2*)(outH+base) = *(uint2*)hh;
    *(uint2*)(outL+base) = *(uint2*)ll;
}

// -------- weight transpose+split --------
__global__ __launch_bounds__(256) void k_wt(const float* __restrict__ W,
                                            __nv_bfloat16* __restrict__ outH,
                                            __nv_bfloat16* __restrict__ outL, int K, int N)
{
    __shared__ float tile[32][33];
    int n0 = blockIdx.x*32, k0 = blockIdx.y*32;
    int tx = threadIdx.x & 31, ty = threadIdx.x >> 5;
    #pragma unroll
    for (int i = ty; i < 32; i += 8)
        tile[i][tx] = W[(size_t)(k0+i)*N + n0 + tx];
    __syncthreads();
    #pragma unroll
    for (int i = ty; i < 32; i += 8) {
        float v = tile[tx][i];
        __nv_bfloat16 hh, ll;
        split_bf16(v, hh, ll);
        outH[(size_t)(n0+i)*K + k0 + tx] = hh;
        outL[(size_t)(n0+i)*K + k0 + tx] = ll;
    }
}

// ---------------- plain split (proj) ----------------
__global__ void k_cvt(const float* __restrict__ in, __nv_bfloat16* __restrict__ outH,
                      __nv_bfloat16* __restrict__ outL, int n4)
{
    int i = blockIdx.x*256 + threadIdx.x;
    if (i >= n4) return;
    float4 v = ((const float4*)in)[i];
    __nv_bfloat16 hh[4], ll[4];
    split_bf16(v.x, hh[0], ll[0]); split_bf16(v.y, hh[1], ll[1]);
    split_bf16(v.z, hh[2], ll[2]); split_bf16(v.w, hh[3], ll[3]);
    *(uint2*)(outH + i*4) = *(uint2*)hh;
    *(uint2*)(outL + i*4) = *(uint2*)ll;
}

// ------- q/k convert from fused qkv buffer (row stride 3072) -------
__global__ void k_cvt_qk(const float* __restrict__ in, __nv_bfloat16* __restrict__ outH,
                         __nv_bfloat16* __restrict__ outL, float* __restrict__ diag)
{
    int warp = threadIdx.x >> 5, lane = threadIdx.x & 31;
    int wr = blockIdx.x*8 + warp;
    int b = wr >> 14, h = (wr >> 11) & 7, s = wr & 2047;
    const float* src = in + (size_t)(b*SS + s)*(3*INNER) + h*DHD;
    float4 v = ((const float4*)src)[lane];
    v.x *= NORMC; v.y *= NORMC; v.z *= NORMC; v.w *= NORMC;
    float sq = v.x*v.x + v.y*v.y + v.z*v.z + v.w*v.w;
    #pragma unroll
    for (int o = 16; o > 0; o >>= 1) sq += __shfl_xor_sync(0xffffffffu, sq, o);
    if (lane == 0) diag[wr] = 0.5f*sq;
    __nv_bfloat16 hh[4], ll[4];
    split_bf16(v.x, hh[0], ll[0]); split_bf16(v.y, hh[1], ll[1]);
    split_bf16(v.z, hh[2], ll[2]); split_bf16(v.w, hh[3], ll[3]);
    size_t base = (size_t)wr*DHD + lane*4;
    *(uint2*)(outH+base) = *(uint2*)hh;
    *(uint2*)(outL+base) = *(uint2*)ll;
}

// ---------------- stab reduce ----------------
__global__ void k_stab2()
{
    int bh = threadIdx.x;
    if (bh < NBH) {
        float m = -1e30f;
        #pragma unroll
        for (int i = 0; i < 16; i++) m = fmaxf(m, g_bmax[bh*16 + i]);
        g_stab[bh] = m;
    }
}

// ---------------- key feature exp -> bf16 hi/lo ----------------
__global__ void k_fek(const float* __restrict__ dd, const float* __restrict__ diag,
                      __nv_bfloat16* __restrict__ outH, __nv_bfloat16* __restrict__ outL)
{
    int r = blockIdx.x*8 + (threadIdx.x >> 5);
    int lane = threadIdx.x & 31;
    float st = g_stab[r >> 11];
    float dg = diag[r];
    float4 v = ((const float4*)(dd + (size_t)r*MF))[lane];
    float o[4] = { RATIOC*(expf(v.x-dg-st) + 1e-4f), RATIOC*(expf(v.y-dg-st) + 1e-4f),
                   RATIOC*(expf(v.z-dg-st) + 1e-4f), RATIOC*(expf(v.w-dg-st) + 1e-4f) };
    __nv_bfloat16 hh[4], ll[4];
    #pragma unroll
    for (int j = 0; j < 4; j++) split_bf16(o[j], hh[j], ll[j]);
    size_t base = (size_t)r*MF + lane*4;
    *(uint2*)(outH+base) = *(uint2*)hh;
    *(uint2*)(outL+base) = *(uint2*)ll;
}

// ================= chunk-local attention via HMMA, 512 threads =================
#define CP 136
__global__ __launch_bounds__(512) void k_chunk(
    const __nv_bfloat16* __restrict__ qph, const __nv_bfloat16* __restrict__ qpl,
    const __nv_bfloat16* __restrict__ kph, const __nv_bfloat16* __restrict__ kpl,
    const float* __restrict__ v)
{
    extern __shared__ __align__(16) __nv_bfloat16 cs[];
    __nv_bfloat16* sQh = cs;                    // [i][m]; later attn [i][j]
    __nv_bfloat16* sQl = sQh + 128*CP;
    __nv_bfloat16* sKh = sQl + 128*CP;          // [j][m]
    __nv_bfloat16* sKl = sKh + 128*CP;
    __nv_bfloat16* sVh = sKl + 128*CP;          // [j][d]
    __nv_bfloat16* sVl = sVh + 128*CP;
    __shared__ float s_den[4][128];

    int blk = blockIdx.x, bh = blk >> 4, c = blk & 15;
    int b = bh >> 3, hh = bh & 7;
    int t = threadIdx.x, w = t >> 5, lane = t & 31;
    int wm = w & 3, wn = w >> 2;                // both 0..3, warp tile 32x32
    const int lrow = lane & 15, lcol8 = (lane >> 4)*8;
    const int rl4 = lane >> 2, cl2 = (lane & 3)*2;

    const size_t qbase = ((size_t)bh*SS + c*CHUNK)*MF;
    for (int i = t; i < 2048; i += 512) {
        int r = i >> 4, c8 = (i & 15) << 3;
        *(uint4*)(sQh + r*CP + c8) = *(const uint4*)(qph + qbase + r*MF + c8);
        *(uint4*)(sQl + r*CP + c8) = *(const uint4*)(qpl + qbase + r*MF + c8);
        *(uint4*)(sKh + r*CP + c8) = *(const uint4*)(kph + qbase + r*MF + c8);
        *(uint4*)(sKl + r*CP + c8) = *(const uint4*)(kpl + qbase + r*MF + c8);
    }
    for (int i = t; i < 4096; i += 512) {
        int r = i >> 5, c4 = (i & 31) << 2;
        float4 vv = *(const float4*)(v + (size_t)(b*SS + c*CHUNK + r)*(3*INNER) + hh*DHD + c4);
        __nv_bfloat16 hh4[4], ll4[4];
        split_bf16(vv.x, hh4[0], ll4[0]); split_bf16(vv.y, hh4[1], ll4[1]);
        split_bf16(vv.z, hh4[2], ll4[2]); split_bf16(vv.w, hh4[3], ll4[3]);
        *(uint2*)(sVh + r*CP + c4) = *(uint2*)hh4;
        *(uint2*)(sVl + r*CP + c4) = *(uint2*)ll4;
    }
    __syncthreads();

    // ---- phase 1: attn = Q@K^T ; warps fully above the diagonal skip MMA ----
    float acc[2][4][4] = {};
    if (wn <= wm) {
        #pragma unroll
        for (int ks = 0; ks < 8; ks++) {
            int kcol = ks*16 + lcol8;
            uint32_t ah[2][4], al[2][4];
            #pragma unroll
            for (int mt = 0; mt < 2; mt++) {
                int arow = wm*32 + mt*16 + lrow;
                ldsm4(ah[mt], s2u(sQh + arow*CP + kcol));
                ldsm4(al[mt], s2u(sQl + arow*CP + kcol));
            }
            #pragma unroll
            for (int nt2 = 0; nt2 < 2; nt2++) {
                int brow = wn*32 + nt2*16 + lrow;
                uint32_t rh[4], rl[4];
                ldsm4(rh, s2u(sKh + brow*CP + kcol));
                ldsm4(rl, s2u(sKl + brow*CP + kcol));
                uint32_t b0h[2] = {rh[0], rh[2]}, b1h[2] = {rh[1], rh[3]};
                uint32_t b0l[2] = {rl[0], rl[2]}, b1l[2] = {rl[1], rl[3]};
                #pragma unroll
                for (int mt = 0; mt < 2; mt++) {
                    mma_bf16(acc[mt][nt2*2],   ah[mt], b0h);
                    mma_bf16(acc[mt][nt2*2],   ah[mt], b0l);
                    mma_bf16(acc[mt][nt2*2],   al[mt], b0h);
                    mma_bf16(acc[mt][nt2*2+1], ah[mt], b1h);
                    mma_bf16(acc[mt][nt2*2+1], ah[mt], b1l);
                    mma_bf16(acc[mt][nt2*2+1], al[mt], b1h);
                }
            }
        }
    }
    // mask + den partials
    float dp[2][2] = {};
    #pragma unroll
    for (int mt = 0; mt < 2; mt++)
        #pragma unroll
        for (int nt = 0; nt < 4; nt++)
            #pragma unroll
            for (int f = 0; f < 4; f++) {
                int i = wm*32 + mt*16 + rl4 + ((f>>1)<<3);
                int j = wn*32 + nt*8 + cl2 + (f&1);
                if (j > i) acc[mt][nt][f] = 0.f;
                dp[mt][f>>1] += acc[mt][nt][f];
            }
    #pragma unroll
    for (int o = 1; o < 4; o <<= 1)
        #pragma unroll
        for (int mt = 0; mt < 2; mt++)
            #pragma unroll
            for (int h2 = 0; h2 < 2; h2++)
                dp[mt][h2] += __shfl_xor_sync(0xffffffffu, dp[mt][h2], o);
    if ((lane & 3) == 0) {
        #pragma unroll
        for (int mt = 0; mt < 2; mt++)
            #pragma unroll
            for (int h2 = 0; h2 < 2; h2++)
                s_den[wn][wm*32 + mt*16 + rl4 + h2*8] = dp[mt][h2];
    }
    __syncthreads();

    // overwrite sQ with masked attn (hi/lo)
    #pragma unroll
    for (int mt = 0; mt < 2; mt++)
        #pragma unroll
        for (int nt = 0; nt < 4; nt++)
            #pragma unroll
            for (int f = 0; f < 4; f++) {
                int i = wm*32 + mt*16 + rl4 + ((f>>1)<<3);
                int j = wn*32 + nt*8 + cl2 + (f&1);
                __nv_bfloat16 hh2, ll2;
                split_bf16(acc[mt][nt][f], hh2, ll2);
                sQh[i*CP + j] = hh2;
                sQl[i*CP + j] = ll2;
            }
    if (t < 128) {
        g_den[(size_t)bh*SS + c*CHUNK + t] = s_den[0][t] + s_den[1][t] + s_den[2][t] + s_den[3][t];
        float kssum = 0.f;
        for (int j = 0; j < 128; j++)
            kssum += __bfloat162float(sKh[j*CP + t]) + __bfloat162float(sKl[j*CP + t]);
        g_ksc[((size_t)bh*NC + c)*MF + t] = kssum;
    }
    __syncthreads();

    // ---- phase 2: num = attn @ V ----
    #pragma unroll
    for (int mt = 0; mt < 2; mt++)
        #pragma unroll
        for (int nt = 0; nt < 4; nt++)
            #pragma unroll
            for (int f = 0; f < 4; f++) acc[mt][nt][f] = 0.f;
    #pragma unroll
    for (int ks = 0; ks < 8; ks++) {
        int kcol = ks*16 + lcol8;
        uint32_t ah[2][4], al[2][4];
        #pragma unroll
        for (int mt = 0; mt < 2; mt++) {
            int arow = wm*32 + mt*16 + lrow;
            ldsm4(ah[mt], s2u(sQh + arow*CP + kcol));
            ldsm4(al[mt], s2u(sQl + arow*CP + kcol));
        }
        #pragma unroll
        for (int nt2 = 0; nt2 < 2; nt2++) {
            int nbase = wn*32 + nt2*16;
            uint32_t dh[4], dl[4];
            ldsm4t(dh, taddr(sVh, CP, ks*16, nbase, lane));
            ldsm4t(dl, taddr(sVl, CP, ks*16, nbase, lane));
            uint32_t b0h[2] = {dh[0], dh[2]}, b1h[2] = {dh[1], dh[3]};
            uint32_t b0l[2] = {dl[0], dl[2]}, b1l[2] = {dl[1], dl[3]};
            #pragma unroll
            for (int mt = 0; mt < 2; mt++) {
                mma_bf16(acc[mt][nt2*2],   ah[mt], b0h);
                mma_bf16(acc[mt][nt2*2],   ah[mt], b0l);
                mma_bf16(acc[mt][nt2*2],   al[mt], b0h);
                mma_bf16(acc[mt][nt2*2+1], ah[mt], b1h);
                mma_bf16(acc[mt][nt2*2+1], ah[mt], b1l);
                mma_bf16(acc[mt][nt2*2+1], al[mt], b1h);
            }
        }
    }
    #pragma unroll
    for (int mt = 0; mt < 2; mt++)
        #pragma unroll
        for (int h2 = 0; h2 < 2; h2++) {
            int i = wm*32 + mt*16 + rl4 + h2*8;
            size_t base = ((size_t)(b*SS + c*CHUNK + i)*HH + hh)*DHD;
            #pragma unroll
            for (int nt = 0; nt < 4; nt++) {
                float2 vv = {acc[mt][nt][h2*2], acc[mt][nt][h2*2+1]};
                *(float2*)(g_o + base + wn*32 + nt*8 + cl2) = vv;
            }
        }

    // ---- phase 3: kv = K^T @ V ----
    #pragma unroll
    for (int mt = 0; mt < 2; mt++)
        #pragma unroll
        for (int nt = 0; nt < 4; nt++)
            #pragma unroll
            for (int f = 0; f < 4; f++) acc[mt][nt][f] = 0.f;
    #pragma unroll
    for (int ks = 0; ks < 8; ks++) {
        uint32_t ah[2][4], al[2][4];
        #pragma unroll
        for (int mt = 0; mt < 2; mt++) {
            int mbase = wm*32 + mt*16;
            ldsm4t(ah[mt], taddr(sKh, CP, ks*16, mbase, lane));
            ldsm4t(al[mt], taddr(sKl, CP, ks*16, mbase, lane));
        }
        #pragma unroll
        for (int nt2 = 0; nt2 < 2; nt2++) {
            int nbase = wn*32 + nt2*16;
            uint32_t dh[4], dl[4];
            ldsm4t(dh, taddr(sVh, CP, ks*16, nbase, lane));
            ldsm4t(dl, taddr(sVl, CP, ks*16, nbase, lane));
            uint32_t b0h[2] = {dh[0], dh[2]}, b1h[2] = {dh[1], dh[3]};
            uint32_t b0l[2] = {dl[0], dl[2]}, b1l[2] = {dl[1], dl[3]};
            #pragma unroll
            for (int mt = 0; mt < 2; mt++) {
                mma_bf16(acc[mt][nt2*2],   ah[mt], b0h);
                mma_bf16(acc[mt][nt2*2],   ah[mt], b0l);
                mma_bf16(acc[mt][nt2*2],   al[mt], b0h);
                mma_bf16(acc[mt][nt2*2+1], ah[mt], b1h);
                mma_bf16(acc[mt][nt2*2+1], ah[mt], b1l);
                mma_bf16(acc[mt][nt2*2+1], al[mt], b1h);
            }
        }
    }
    {
        size_t kvbase = ((size_t)bh*NC + c)*(MF*DHD);
        #pragma unroll
        for (int mt = 0; mt < 2; mt++)
            #pragma unroll
            for (int h2 = 0; h2 < 2; h2++) {
                int m = wm*32 + mt*16 + rl4 + h2*8;
                #pragma unroll
                for (int nt = 0; nt < 4; nt++) {
                    float2 vv = {acc[mt][nt][h2*2], acc[mt][nt][h2*2+1]};
                    *(float2*)(g_kvc + kvbase + (size_t)m*DHD + wn*32 + nt*8 + cl2) = vv;
                }
            }
    }
}

// ---------------- exclusive prefix over chunks (emits bf16 hi/lo) ----------------
__global__ void k_prefix()
{
    int bh = blockIdx.x, seg = blockIdx.y, t = threadIdx.x;
    for (int e = seg*2048 + t; e < (seg+1)*2048; e += 256) {
        float run = 0.f;
        #pragma unroll
        for (int c = 0; c < NC; c++) {
            size_t idx = ((size_t)bh*NC + c)*(MF*DHD) + e;
            __nv_bfloat16 hh, ll;
            split_bf16(run, hh, ll);
            g_kvph[idx] = hh; g_kvpl[idx] = ll;
            run += g_kvc[idx];
        }
    }
    if (seg == 0) {
        for (int e = t; e < MF; e += 256) {
            float run = 0.f;
            #pragma unroll
            for (int c = 0; c < NC; c++) {
                size_t idx = ((size_t)bh*NC + c)*MF + e;
                g_ksp[idx] = run; run += g_ksc[idx];
            }
        }
    }
}

// ========== cross = qp @ kvp, + num, normalize -> oh/ol (HMMA, 512 thr) ==========
__global__ __launch_bounds__(512) void k_cross(
    const __nv_bfloat16* __restrict__ qph, const __nv_bfloat16* __restrict__ qpl)
{
    extern __shared__ __align__(16) __nv_bfloat16 cs[];
    __nv_bfloat16* sQh = cs;                    // [i][m]
    __nv_bfloat16* sQl = sQh + 128*CP;
    __nv_bfloat16* sPh = sQl + 128*CP;          // kvp [m][d]
    __nv_bfloat16* sPl = sPh + 128*CP;
    __shared__ float s_ks[128];
    __shared__ float s_dc[128];

    int blk = blockIdx.x, bh = blk >> 4, c = blk & 15;
    int b = bh >> 3, hh = bh & 7;
    int t = threadIdx.x, w = t >> 5, lane = t & 31;
    int wm = w & 3, wn = w >> 2;
    const int lrow = lane & 15, lcol8 = (lane >> 4)*8;
    const int rl4 = lane >> 2, cl2 = (lane & 3)*2;

    const size_t qbase = ((size_t)bh*SS + c*CHUNK)*MF;
    const size_t pbase = ((size_t)bh*NC + c)*(MF*DHD);
    for (int i = t; i < 2048; i += 512) {
        int r = i >> 4, c8 = (i & 15) << 3;
        *(uint4*)(sQh + r*CP + c8) = *(const uint4*)(qph + qbase + r*MF + c8);
        *(uint4*)(sQl + r*CP + c8) = *(const uint4*)(qpl + qbase + r*MF + c8);
        *(uint4*)(sPh + r*CP + c8) = *(const uint4*)(g_kvph + pbase + r*DHD + c8);
        *(uint4*)(sPl + r*CP + c8) = *(const uint4*)(g_kvpl + pbase + r*DHD + c8);
    }
    if (t < 128) s_ks[t] = g_ksp[((size_t)bh*NC + c)*MF + t];
    __syncthreads();
    if (t < 128) {
        float dc = 0.f;
        for (int m = 0; m < 128; m++)
            dc += (__bfloat162float(sQh[t*CP + m]) + __bfloat162float(sQl[t*CP + m]))*s_ks[m];
        s_dc[t] = g_den[(size_t)bh*SS + c*CHUNK + t] + dc + 1e-6f;
    }
    __syncthreads();

    float acc[2][4][4] = {};
    #pragma unroll
    for (int ks = 0; ks < 8; ks++) {
        int kcol = ks*16 + lcol8;
        uint32_t ah[2][4], al[2][4];
        #pragma unroll
        for (int mt = 0; mt < 2; mt++) {
            int arow = wm*32 + mt*16 + lrow;
            ldsm4(ah[mt], s2u(sQh + arow*CP + kcol));
            ldsm4(al[mt], s2u(sQl + arow*CP + kcol));
        }
        #pragma unroll
        for (int nt2 = 0; nt2 < 2; nt2++) {
            int nbase = wn*32 + nt2*16;
            uint32_t dh[4], dl[4];
            ldsm4t(dh, taddr(sPh, CP, ks*16, nbase, lane));
            ldsm4t(dl, taddr(sPl, CP, ks*16, nbase, lane));
            uint32_t b0h[2] = {dh[0], dh[2]}, b1h[2] = {dh[1], dh[3]};
            uint32_t b0l[2] = {dl[0], dl[2]}, b1l[2] = {dl[1], dl[3]};
            #pragma unroll
            for (int mt = 0; mt < 2; mt++) {
                mma_bf16(acc[mt][nt2*2],   ah[mt], b0h);
                mma_bf16(acc[mt][nt2*2],   ah[mt], b0l);
                mma_bf16(acc[mt][nt2*2],   al[mt], b0h);
                mma_bf16(acc[mt][nt2*2+1], ah[mt], b1h);
                mma_bf16(acc[mt][nt2*2+1], ah[mt], b1l);
                mma_bf16(acc[mt][nt2*2+1], al[mt], b1h);
            }
        }
    }
    #pragma unroll
    for (int mt = 0; mt < 2; mt++)
        #pragma unroll
        for (int h2 = 0; h2 < 2; h2++) {
            int i = wm*32 + mt*16 + rl4 + h2*8;
            float inv = 1.0f / s_dc[i];
            size_t base = ((size_t)(b*SS + c*CHUNK + i)*HH + hh)*DHD;
            #pragma unroll
            for (int nt = 0; nt < 4; nt++) {
                size_t idx = base + wn*32 + nt*8 + cl2;
                float2 nn = *(float2*)(g_o + idx);
                float v0 = (nn.x + acc[mt][nt][h2*2])   * inv;
                float v1 = (nn.y + acc[mt][nt][h2*2+1]) * inv;
                __nv_bfloat16 h0,l0,h1,l1;
                split_bf16(v0,h0,l0); split_bf16(v1,h1,l1);
                __nv_bfloat162 hp, lp;
                hp.x = h0; hp.y = h1; lp.x = l0; lp.y = l1;
                *(__nv_bfloat162*)(g_oh + idx) = hp;
                *(__nv_bfloat162*)(g_ol + idx) = lp;
            }
        }
}

// ---------------- pooling ----------------
__global__ void k_pool()
{
    int b = blockIdx.x, seg = blockIdx.y, t = threadIdx.x;
    float acc = 0.f;
    for (int s = seg*128; s < (seg+1)*128; s++) acc += g_h[((size_t)b*SS + s)*DIMC + t];
    g_pp[(b*16 + seg)*DIMC + t] = acc;
}

__global__ void k_final(const float* __restrict__ fw, const float* __restrict__ fb,
                        float* __restrict__ out)
{
    __shared__ float pooled[BB*DIMC];
    int t = threadIdx.x;
    for (int b = 0; b < BB; b++) {
        float a = 0.f;
        #pragma unroll
        for (int s = 0; s < 16; s++) a += g_pp[(b*16 + s)*DIMC + t];
        pooled[b*DIMC + t] = a * (1.0f/SS);
    }
    __syncthreads();
    if (t < BB*NCLS) {
        int b = t / NCLS, c = t % NCLS;
        float acc = fb[c];
        for (int d = 0; d < DIMC; d++) acc += pooled[b*DIMC + d]*fw[d*NCLS + c];
        out[t] = acc;
    }
}

// ---------------- host driver ----------------
static void* sym(const void* s) { void* p = nullptr; cudaGetSymbolAddress(&p, s); return p; }

extern "C" void kernel_launch(void* const* d_in, const int* in_sizes, int n_in,
                              void* d_out, int out_size)
{
    const float* x     = (const float*)d_in[0];
    const float* lin_w = (const float*)d_in[1];
    const float* lin_b = (const float*)d_in[2];
    const float* pe    = (const float*)d_in[3];
    const float* proj  = (const float*)d_in[4];
    const float* ln1_g = (const float*)d_in[5];
    const float* ln1_b = (const float*)d_in[6];
    const float* wq    = (const float*)d_in[7];
    const float* wk    = (const float*)d_in[8];
    const float* wv    = (const float*)d_in[9];
    const float* wo    = (const float*)d_in[10];
    const float* wo_b  = (const float*)d_in[11];
    const float* ln2_g = (const float*)d_in[12];
    const float* ln2_b = (const float*)d_in[13];
    const float* ff1_w = (const float*)d_in[14];
    const float* ff1_b = (const float*)d_in[15];
    const float* ff2_w = (const float*)d_in[16];
    const float* ff2_b = (const float*)d_in[17];
    const float* fin_w = (const float*)d_in[18];
    const float* fin_b = (const float*)d_in[19];
    float* out = (float*)d_out;

    float* ph   = (float*)sym(g_h);
    float* pqkv = (float*)sym(g_qkv);
    float* pkp  = (float*)sym(g_kp);
    float* pdq  = (float*)sym(g_diagq);
    float* pdk  = (float*)sym(g_diagk);
    float* pbm  = (float*)sym(g_bmax);

    __nv_bfloat16* yh  = (__nv_bfloat16*)sym(g_yh);
    __nv_bfloat16* yl  = (__nv_bfloat16*)sym(g_yl);
    __nv_bfloat16* wth = (__nv_bfloat16*)sym(g_wth);
    __nv_bfloat16* wtl = (__nv_bfloat16*)sym(g_wtl);
    __nv_bfloat16* qnh = (__nv_bfloat16*)sym(g_qnh);
    __nv_bfloat16* qnl = (__nv_bfloat16*)sym(g_qnl);
    __nv_bfloat16* knh = (__nv_bfloat16*)sym(g_knh);
    __nv_bfloat16* knl = (__nv_bfloat16*)sym(g_knl);
    __nv_bfloat16* qp_h = (__nv_bfloat16*)sym(g_qph);
    __nv_bfloat16* qp_l = (__nv_bfloat16*)sym(g_qpl);
    __nv_bfloat16* kp_h = (__nv_bfloat16*)sym(g_kph);
    __nv_bfloat16* kp_l = (__nv_bfloat16*)sym(g_kpl);
    __nv_bfloat16* oh  = (__nv_bfloat16*)sym(g_oh);
    __nv_bfloat16* ol  = (__nv_bfloat16*)sym(g_ol);
    __nv_bfloat16* fh  = (__nv_bfloat16*)sym(g_fh);
    __nv_bfloat16* fl  = (__nv_bfloat16*)sym(g_fl);

    const int SMEM_MMA   = 4*128*SROW*2;        // 73728
    const int SMEM_MMA64 = (2*64 + 2*128)*SROW*2; // 55296
    const int SMEM_CHUNK = 6*128*CP*2;          // 208896
    const int SMEM_CROSS = 4*128*CP*2;          // 139264
    cudaFuncSetAttribute(k_mma<0>, cudaFuncAttributeMaxDynamicSharedMemorySize, SMEM_MMA);
    cudaFuncSetAttribute(k_mma<1>, cudaFuncAttributeMaxDynamicSharedMemorySize, SMEM_MMA);
    cudaFuncSetAttribute(k_mma<3>, cudaFuncAttributeMaxDynamicSharedMemorySize, SMEM_MMA);
    cudaFuncSetAttribute(k_mma<4>, cudaFuncAttributeMaxDynamicSharedMemorySize, SMEM_MMA);
    cudaFuncSetAttribute(k_mma64, cudaFuncAttributeMaxDynamicSharedMemorySize, SMEM_MMA64);
    cudaFuncSetAttribute(k_chunk, cudaFuncAttributeMaxDynamicSharedMemorySize, SMEM_CHUNK);
    cudaFuncSetAttribute(k_cross, cudaFuncAttributeMaxDynamicSharedMemorySize, SMEM_CROSS);

    k_embed<<<BSR/8, 256>>>(x, lin_w, lin_b, pe);

    // hoisted weight prep for both layers
    for (int l = 0; l < DEPTH; l++) {
        size_t wb = (size_t)l*WT_LAYER;
        k_wt<<<dim3(INNER/32, DIMC/32), 256>>>(wq + (size_t)l*DIMC*INNER, wth+wb+WT_Q, wtl+wb+WT_Q, DIMC, INNER);
        k_wt<<<dim3(INNER/32, DIMC/32), 256>>>(wk + (size_t)l*DIMC*INNER, wth+wb+WT_K, wtl+wb+WT_K, DIMC, INNER);
        k_wt<<<dim3(INNER/32, DIMC/32), 256>>>(wv + (size_t)l*DIMC*INNER, wth+wb+WT_V, wtl+wb+WT_V, DIMC, INNER);
        k_wt<<<dim3(DIMC/32, INNER/32), 256>>>(wo + (size_t)l*INNER*DIMC, wth+wb+WT_O, wtl+wb+WT_O, INNER, DIMC);
        k_wt<<<dim3(FFD/32, DIMC/32), 256>>>(ff1_w + (size_t)l*DIMC*FFD, wth+wb+WT_F1, wtl+wb+WT_F1, DIMC, FFD);
        k_wt<<<dim3(DIMC/32, FFD/32), 256>>>(ff2_w + (size_t)l*FFD*DIMC, wth+wb+WT_F2, wtl+wb+WT_F2, FFD, DIMC);
        k_cvt<<<16, 256>>>(proj + (size_t)l*MF*DHD, wth+wb+WT_PJ, wtl+wb+WT_PJ, MF*DHD/4);
    }

    for (int l = 0; l < DEPTH; l++) {
        size_t wb = (size_t)l*WT_LAYER;

        k_ln<<<BSR/8, 256>>>(ph, ln1_g + l*DIMC, ln1_b + l*DIMC, yh, yl);

        // fused QKV: B = [3072,128] contiguous (Q,K,V) -> g_qkv rows of 3072
        k_mma<0><<<dim3(24,64), 256, SMEM_MMA>>>(yh, yl, DIMC, wth+wb+WT_Q, wtl+wb+WT_Q, DIMC, 3*INNER,
                                                 nullptr, pqkv, nullptr, nullptr, nullptr, nullptr);

        k_cvt_qk<<<BHS/8, 256>>>(pqkv,        qnh, qnl, pdq);
        k_cvt_qk<<<BHS/8, 256>>>(pqkv + INNER, knh, knl, pdk);

        k_mma<4><<<dim3(1,512), 256, SMEM_MMA>>>(knh, knl, DHD, wth+wb+WT_PJ, wtl+wb+WT_PJ, DHD, MF,
                                                 nullptr, pkp, nullptr, nullptr, nullptr, pbm);
        k_stab2<<<1, 32>>>();
        k_fek<<<BHS/8, 256>>>(pkp, pdk, kp_h, kp_l);
        k_mma<3><<<dim3(1,512), 256, SMEM_MMA>>>(qnh, qnl, DHD, wth+wb+WT_PJ, wtl+wb+WT_PJ, DHD, MF,
                                                 nullptr, nullptr, qp_h, qp_l, pdq, nullptr);

        k_chunk<<<NBH*NC, 512, SMEM_CHUNK>>>(qp_h, qp_l, kp_h, kp_l, pqkv + 2*INNER);
        k_prefix<<<dim3(NBH, 8), 256>>>();
        k_cross<<<NBH*NC, 512, SMEM_CROSS>>>(qp_h, qp_l);

        // output projection + residual (64-row tiles, 128 blocks)
        k_mma64<<<dim3(1,BSR/64), 256, SMEM_MMA64>>>(oh, ol, INNER, wth+wb+WT_O, wtl+wb+WT_O, INNER,
                                                     wo_b + l*DIMC, ph);

        k_ln<<<BSR/8, 256>>>(ph, ln2_g + l*DIMC, ln2_b + l*DIMC, yh, yl);
        k_mma<1><<<dim3(4,64), 256, SMEM_MMA>>>(yh, yl, DIMC, wth+wb+WT_F1, wtl+wb+WT_F1, DIMC, FFD,
                                                ff1_b + l*FFD, nullptr, fh, fl, nullptr, nullptr);
        k_mma64<<<dim3(1,BSR/64), 256, SMEM_MMA64>>>(fh, fl, FFD, wth+wb+WT_F2, wtl+wb+WT_F2, FFD,
                                                     ff2_b + l*DIMC, ph);
    }

    k_pool<<<dim3(BB, 16), 128>>>();
    k_final<<<1, 128>>>(fin_w, fin_b, out);
}

// round 7
// speedup vs baseline: 2.1435x; 1.0639x over previous
#include <cuda_runtime.h>
#include <cuda_bf16.h>
#include <math.h>
#include <stdint.h>

// ---------------- problem constants ----------------
#define BB 4
#define SS 2048
#define DIMC 128
#define HH 8
#define DHD 128
#define DEPTH 2
#define NCLS 10
#define MF 128
#define CHUNK 128
#define NC 16
#define INNER 1024
#define FFD 512
#define BSR 8192
#define BHS 65536
#define NBH 32

#define NORMC 0.29730177875068026f
#define RATIOC 0.08838834764831845f

// ---------------- device scratch (fp32) ----------------
__device__ float g_h  [BSR*DIMC];
__device__ float g_kp [(size_t)NBH*SS*MF];       // K features dd (pre-exp)
__device__ float g_diagq[BHS];
__device__ float g_diagk[BHS];
__device__ float g_bmax[NBH*16];
__device__ float g_stab[NBH];
__device__ float g_o  [BSR*INNER];               // local num, [B,S,H,DH]
__device__ float g_den[BHS];
__device__ float g_kvc[(size_t)NBH*NC*MF*DHD];
__device__ float g_ksc[NBH*NC*MF];
__device__ float g_ksp[NBH*NC*MF];
__device__ float g_pp [BB*16*DIMC];

// ---------------- device scratch (bf16 hi/lo) ----------------
__device__ __align__(256) __nv_bfloat16 g_yh [BSR*DIMC];
__device__ __align__(256) __nv_bfloat16 g_yl [BSR*DIMC];
__device__ __align__(256) __nv_bfloat16 g_wth[2*672000];
__device__ __align__(256) __nv_bfloat16 g_wtl[2*672000];
__device__ __align__(256) __nv_bfloat16 g_qnh[(size_t)BHS*DHD];
__device__ __align__(256) __nv_bfloat16 g_qnl[(size_t)BHS*DHD];
__device__ __align__(256) __nv_bfloat16 g_knh[(size_t)BHS*DHD];
__device__ __align__(256) __nv_bfloat16 g_knl[(size_t)BHS*DHD];
__device__ __align__(256) __nv_bfloat16 g_vh [(size_t)BSR*INNER];
__device__ __align__(256) __nv_bfloat16 g_vl [(size_t)BSR*INNER];
__device__ __align__(256) __nv_bfloat16 g_qph[(size_t)NBH*SS*MF];
__device__ __align__(256) __nv_bfloat16 g_qpl[(size_t)NBH*SS*MF];
__device__ __align__(256) __nv_bfloat16 g_kph[(size_t)NBH*SS*MF];
__device__ __align__(256) __nv_bfloat16 g_kpl[(size_t)NBH*SS*MF];
__device__ __align__(256) __nv_bfloat16 g_kvph[(size_t)NBH*NC*MF*DHD];
__device__ __align__(256) __nv_bfloat16 g_kvpl[(size_t)NBH*NC*MF*DHD];
__device__ __align__(256) __nv_bfloat16 g_oh [(size_t)BSR*INNER];
__device__ __align__(256) __nv_bfloat16 g_ol [(size_t)BSR*INNER];
__device__ __align__(256) __nv_bfloat16 g_fh [(size_t)BSR*FFD];
__device__ __align__(256) __nv_bfloat16 g_fl [(size_t)BSR*FFD];

#define WT_Q  0
#define WT_K  131072
#define WT_V  262144
#define WT_O  393216
#define WT_F1 524288
#define WT_F2 589824
#define WT_PJ 655360
#define WT_LAYER 672000

// ---------------- warp MMA helpers ----------------
__device__ __forceinline__ uint32_t s2u(const void* p){
    uint32_t a;
    asm("{ .reg .u64 t; cvta.to.shared.u64 t, %1; cvt.u32.u64 %0, t; }" : "=r"(a) : "l"(p));
    return a;
}
__device__ __forceinline__ void ldsm4(uint32_t* r, uint32_t addr){
    asm volatile("ldmatrix.sync.aligned.m8n8.x4.shared.b16 {%0,%1,%2,%3}, [%4];"
                 : "=r"(r[0]),"=r"(r[1]),"=r"(r[2]),"=r"(r[3]) : "r"(addr));
}
__device__ __forceinline__ void ldsm4t(uint32_t* r, uint32_t addr){
    asm volatile("ldmatrix.sync.aligned.m8n8.x4.trans.shared.b16 {%0,%1,%2,%3}, [%4];"
                 : "=r"(r[0]),"=r"(r[1]),"=r"(r[2]),"=r"(r[3]) : "r"(addr));
}
__device__ __forceinline__ void mma_bf16(float* c, const uint32_t* a, const uint32_t* b){
    asm volatile("mma.sync.aligned.m16n8k16.row.col.f32.bf16.bf16.f32 "
                 "{%0,%1,%2,%3}, {%4,%5,%6,%7}, {%8,%9}, {%0,%1,%2,%3};"
                 : "+f"(c[0]),"+f"(c[1]),"+f"(c[2]),"+f"(c[3])
                 : "r"(a[0]),"r"(a[1]),"r"(a[2]),"r"(a[3]), "r"(b[0]),"r"(b[1]));
}
__device__ __forceinline__ void split_bf16(float v, __nv_bfloat16& h, __nv_bfloat16& l){
    h = __float2bfloat16(v);
    l = __float2bfloat16(v - __bfloat162float(h));
}
__device__ __forceinline__ float gelu(float xx){
    return 0.5f*xx*(1.0f + tanhf(0.7978845608028654f*(xx + 0.044715f*xx*xx*xx)));
}
__device__ __forceinline__ uint32_t taddr(const __nv_bfloat16* S, int P, int kbase, int nbase, int lane){
    int kk = (lane & 7) + ((lane >> 4) << 3);
    int nn = ((lane >> 3) & 1) << 3;
    return s2u(S + (size_t)(kbase + kk)*P + nbase + nn);
}

// helper macro for 3-MMA hi/lo product pair (two n-subtiles)
#define MMA3x2(accA, accB, ah_, al_, b0h_, b0l_, b1h_, b1l_) \
    do { mma_bf16(accA, ah_, b0h_); mma_bf16(accA, ah_, b0l_); mma_bf16(accA, al_, b0h_); \
         mma_bf16(accB, ah_, b1h_); mma_bf16(accB, ah_, b1l_); mma_bf16(accB, al_, b1h_); } while(0)

// ============ HMMA GEMM, 128x128 tile, fixed K=128 (single smem stage) ============
#define KP 136
// MODE 1: outH/outL = split(gelu(acc+bias))  (FF1, Nt=512)
// MODE 3: Q features -> qp hi/lo (Nt=128)
// MODE 4: K features -> out fp32 + blockmax  (Nt=128)
template<int MODE>
__global__ __launch_bounds__(256) void k_mma(
    const __nv_bfloat16* __restrict__ Ah, const __nv_bfloat16* __restrict__ Al,
    const __nv_bfloat16* __restrict__ Bh, const __nv_bfloat16* __restrict__ Bl,
    int Nt,
    const float* __restrict__ bias,
    float* __restrict__ out,
    __nv_bfloat16* __restrict__ outH, __nv_bfloat16* __restrict__ outL,
    const float* __restrict__ diag, float* __restrict__ bmax)
{
    extern __shared__ __align__(16) char dsm[];
    __nv_bfloat16* sAh = (__nv_bfloat16*)dsm;
    __nv_bfloat16* sAl = sAh + 128*KP;
    __nv_bfloat16* sBh = sAl + 128*KP;
    __nv_bfloat16* sBl = sBh + 128*KP;
    __shared__ float s_rm[2][128];
    __shared__ float s_red[256];

    const int t = threadIdx.x, w = t >> 5, lane = t & 31;
    const int wm = w & 3, wn = w >> 2;
    const int row0 = blockIdx.y*128, col0 = blockIdx.x*128;

    float acc[2][8][4] = {};
    const int lrow = (lane & 15), lcol8 = (lane >> 4)*8;

    #pragma unroll
    for (int i = 0; i < 8; i++) {
        int f = i*256 + t;
        int r = f >> 4, c8 = (f & 15) << 3;
        *(uint4*)(sAh + r*KP + c8) = *(const uint4*)(Ah + (size_t)(row0+r)*128 + c8);
        *(uint4*)(sAl + r*KP + c8) = *(const uint4*)(Al + (size_t)(row0+r)*128 + c8);
        *(uint4*)(sBh + r*KP + c8) = *(const uint4*)(Bh + (size_t)(col0+r)*128 + c8);
        *(uint4*)(sBl + r*KP + c8) = *(const uint4*)(Bl + (size_t)(col0+r)*128 + c8);
    }
    __syncthreads();
    #pragma unroll
    for (int ks = 0; ks < 8; ks++) {
        int kcol = ks*16 + lcol8;
        uint32_t ah[2][4], al[2][4];
        #pragma unroll
        for (int mt = 0; mt < 2; mt++) {
            int arow = wm*32 + mt*16 + lrow;
            ldsm4(ah[mt], s2u(sAh + arow*KP + kcol));
            ldsm4(al[mt], s2u(sAl + arow*KP + kcol));
        }
        #pragma unroll
        for (int nt2 = 0; nt2 < 4; nt2++) {
            int brow = wn*64 + nt2*16 + lrow;
            uint32_t rh[4], rl[4];
            ldsm4(rh, s2u(sBh + brow*KP + kcol));
            ldsm4(rl, s2u(sBl + brow*KP + kcol));
            uint32_t b0h[2] = {rh[0], rh[2]}, b1h[2] = {rh[1], rh[3]};
            uint32_t b0l[2] = {rl[0], rl[2]}, b1l[2] = {rl[1], rl[3]};
            #pragma unroll
            for (int mt = 0; mt < 2; mt++)
                MMA3x2(acc[mt][nt2*2], acc[mt][nt2*2+1], ah[mt], al[mt], b0h, b0l, b1h, b1l);
        }
    }

    const int rl4 = lane >> 2;
    const int cl2 = (lane & 3)*2;

    if (MODE == 4) {
        float bm = -1e30f;
        #pragma unroll
        for (int mt = 0; mt < 2; mt++)
            #pragma unroll
            for (int h = 0; h < 2; h++) {
                int gr = row0 + wm*32 + mt*16 + rl4 + h*8;
                #pragma unroll
                for (int nt = 0; nt < 8; nt++) {
                    float2 v = {acc[mt][nt][h*2], acc[mt][nt][h*2+1]};
                    *(float2*)(out + (size_t)gr*Nt + col0 + wn*64 + nt*8 + cl2) = v;
                    bm = fmaxf(bm, fmaxf(v.x, v.y));
                }
            }
        s_red[t] = bm; __syncthreads();
        #pragma unroll
        for (int o = 128; o > 0; o >>= 1) { if (t < o) s_red[t] = fmaxf(s_red[t], s_red[t+o]); __syncthreads(); }
        if (t == 0) bmax[blockIdx.y] = s_red[0];
    } else if (MODE == 1) {
        #pragma unroll
        for (int mt = 0; mt < 2; mt++)
            #pragma unroll
            for (int h = 0; h < 2; h++) {
                int gr = row0 + wm*32 + mt*16 + rl4 + h*8;
                #pragma unroll
                for (int nt = 0; nt < 8; nt++) {
                    int gc = col0 + wn*64 + nt*8 + cl2;
                    float v0 = gelu(acc[mt][nt][h*2]   + bias[gc]);
                    float v1 = gelu(acc[mt][nt][h*2+1] + bias[gc+1]);
                    __nv_bfloat16 h0,l0,h1,l1;
                    split_bf16(v0,h0,l0); split_bf16(v1,h1,l1);
                    __nv_bfloat162 hp, lp;
                    hp.x = h0; hp.y = h1; lp.x = l0; lp.y = l1;
                    *(__nv_bfloat162*)(outH + (size_t)gr*Nt + gc) = hp;
                    *(__nv_bfloat162*)(outL + (size_t)gr*Nt + gc) = lp;
                }
            }
    } else { // MODE 3: Q features -> bf16 hi/lo
        float rm[2][2];
        #pragma unroll
        for (int mt = 0; mt < 2; mt++)
            #pragma unroll
            for (int h = 0; h < 2; h++) {
                float m = -1e30f;
                #pragma unroll
                for (int nt = 0; nt < 8; nt++)
                    m = fmaxf(m, fmaxf(acc[mt][nt][h*2], acc[mt][nt][h*2+1]));
                m = fmaxf(m, __shfl_xor_sync(0xffffffffu, m, 1));
                m = fmaxf(m, __shfl_xor_sync(0xffffffffu, m, 2));
                rm[mt][h] = m;
            }
        if ((lane & 3) == 0) {
            #pragma unroll
            for (int mt = 0; mt < 2; mt++)
                #pragma unroll
                for (int h = 0; h < 2; h++)
                    s_rm[wn][wm*32 + mt*16 + rl4 + h*8] = rm[mt][h];
        }
        __syncthreads();
        #pragma unroll
        for (int mt = 0; mt < 2; mt++)
            #pragma unroll
            for (int h = 0; h < 2; h++) {
                int lr = wm*32 + mt*16 + rl4 + h*8;
                int gr = row0 + lr;
                float rmax = fmaxf(s_rm[0][lr], s_rm[1][lr]);
                float dg = diag[gr];
                #pragma unroll
                for (int nt = 0; nt < 8; nt++) {
                    int gc = wn*64 + nt*8 + cl2;
                    float v0 = RATIOC*(expf(acc[mt][nt][h*2]  -dg-rmax) + 1e-4f);
                    float v1 = RATIOC*(expf(acc[mt][nt][h*2+1]-dg-rmax) + 1e-4f);
                    __nv_bfloat16 h0,l0,h1,l1;
                    split_bf16(v0,h0,l0); split_bf16(v1,h1,l1);
                    __nv_bfloat162 hp, lp;
                    hp.x = h0; hp.y = h1; lp.x = l0; lp.y = l1;
                    *(__nv_bfloat162*)(outH + (size_t)gr*Nt + gc) = hp;
                    *(__nv_bfloat162*)(outL + (size_t)gr*Nt + gc) = lp;
                }
            }
    }
}

// ============ fused QKV GEMM: epilogue writes qn/kn (scaled, head-transposed,
// hi/lo, + diag) and v (hi/lo), straight from accumulators ============
__global__ __launch_bounds__(256) void k_mmaqkv(
    const __nv_bfloat16* __restrict__ Ah, const __nv_bfloat16* __restrict__ Al,
    const __nv_bfloat16* __restrict__ Bh, const __nv_bfloat16* __restrict__ Bl)
{
    extern __shared__ __align__(16) char dsm[];
    __nv_bfloat16* sAh = (__nv_bfloat16*)dsm;
    __nv_bfloat16* sAl = sAh + 128*KP;
    __nv_bfloat16* sBh = sAl + 128*KP;
    __nv_bfloat16* sBl = sBh + 128*KP;
    __shared__ float s_rm[2][128];

    const int t = threadIdx.x, w = t >> 5, lane = t & 31;
    const int wm = w & 3, wn = w >> 2;
    const int row0 = blockIdx.y*128, col0 = blockIdx.x*128;

    float acc[2][8][4] = {};
    const int lrow = (lane & 15), lcol8 = (lane >> 4)*8;

    #pragma unroll
    for (int i = 0; i < 8; i++) {
        int f = i*256 + t;
        int r = f >> 4, c8 = (f & 15) << 3;
        *(uint4*)(sAh + r*KP + c8) = *(const uint4*)(Ah + (size_t)(row0+r)*128 + c8);
        *(uint4*)(sAl + r*KP + c8) = *(const uint4*)(Al + (size_t)(row0+r)*128 + c8);
        *(uint4*)(sBh + r*KP + c8) = *(const uint4*)(Bh + (size_t)(col0+r)*128 + c8);
        *(uint4*)(sBl + r*KP + c8) = *(const uint4*)(Bl + (size_t)(col0+r)*128 + c8);
    }
    __syncthreads();
    #pragma unroll
    for (int ks = 0; ks < 8; ks++) {
        int kcol = ks*16 + lcol8;
        uint32_t ah[2][4], al[2][4];
        #pragma unroll
        for (int mt = 0; mt < 2; mt++) {
            int arow = wm*32 + mt*16 + lrow;
            ldsm4(ah[mt], s2u(sAh + arow*KP + kcol));
            ldsm4(al[mt], s2u(sAl + arow*KP + kcol));
        }
        #pragma unroll
        for (int nt2 = 0; nt2 < 4; nt2++) {
            int brow = wn*64 + nt2*16 + lrow;
            uint32_t rh[4], rl[4];
            ldsm4(rh, s2u(sBh + brow*KP + kcol));
            ldsm4(rl, s2u(sBl + brow*KP + kcol));
            uint32_t b0h[2] = {rh[0], rh[2]}, b1h[2] = {rh[1], rh[3]};
            uint32_t b0l[2] = {rl[0], rl[2]}, b1l[2] = {rl[1], rl[3]};
            #pragma unroll
            for (int mt = 0; mt < 2; mt++)
                MMA3x2(acc[mt][nt2*2], acc[mt][nt2*2+1], ah[mt], al[mt], b0h, b0l, b1h, b1l);
        }
    }

    const int rl4 = lane >> 2, cl2 = (lane & 3)*2;
    const int part = blockIdx.x >> 3;        // 0=q, 1=k, 2=v
    const int h = blockIdx.x & 7;

    if (part < 2) {
        __nv_bfloat16* dH = part ? g_knh : g_qnh;
        __nv_bfloat16* dL = part ? g_knl : g_qnl;
        #pragma unroll
        for (int mt = 0; mt < 2; mt++)
            #pragma unroll
            for (int h2 = 0; h2 < 2; h2++) {
                int lr = wm*32 + mt*16 + rl4 + h2*8;
                int r = row0 + lr;
                int b = r >> 11, s = r & 2047;
                size_t base = ((size_t)(b*HH + h)*SS + s)*DHD;
                float sq = 0.f;
                #pragma unroll
                for (int nt = 0; nt < 8; nt++) {
                    float v0 = acc[mt][nt][h2*2]   * NORMC;
                    float v1 = acc[mt][nt][h2*2+1] * NORMC;
                    sq += v0*v0 + v1*v1;
                    __nv_bfloat16 h0,l0,h1,l1;
                    split_bf16(v0,h0,l0); split_bf16(v1,h1,l1);
                    __nv_bfloat162 hp, lp;
                    hp.x = h0; hp.y = h1; lp.x = l0; lp.y = l1;
                    *(__nv_bfloat162*)(dH + base + wn*64 + nt*8 + cl2) = hp;
                    *(__nv_bfloat162*)(dL + base + wn*64 + nt*8 + cl2) = lp;
                }
                sq += __shfl_xor_sync(0xffffffffu, sq, 1);
                sq += __shfl_xor_sync(0xffffffffu, sq, 2);
                if ((lane & 3) == 0) s_rm[wn][lr] = sq;
            }
        __syncthreads();
        if (wn == 0 && (lane & 3) == 0) {
            float* dg = part ? g_diagk : g_diagq;
            #pragma unroll
            for (int mt = 0; mt < 2; mt++)
                #pragma unroll
                for (int h2 = 0; h2 < 2; h2++) {
                    int lr = wm*32 + mt*16 + rl4 + h2*8;
                    int r = row0 + lr;
                    int b = r >> 11, s = r & 2047;
                    dg[(size_t)(b*HH + h)*SS + s] = 0.5f*(s_rm[0][lr] + s_rm[1][lr]);
                }
        }
    } else {
        #pragma unroll
        for (int mt = 0; mt < 2; mt++)
            #pragma unroll
            for (int h2 = 0; h2 < 2; h2++) {
                int gr = row0 + wm*32 + mt*16 + rl4 + h2*8;
                size_t base = (size_t)gr*INNER + h*DHD;
                #pragma unroll
                for (int nt = 0; nt < 8; nt++) {
                    float v0 = acc[mt][nt][h2*2];
                    float v1 = acc[mt][nt][h2*2+1];
                    __nv_bfloat16 h0,l0,h1,l1;
                    split_bf16(v0,h0,l0); split_bf16(v1,h1,l1);
                    __nv_bfloat162 hp, lp;
                    hp.x = h0; hp.y = h1; lp.x = l0; lp.y = l1;
                    *(__nv_bfloat162*)(g_vh + base + wn*64 + nt*8 + cl2) = hp;
                    *(__nv_bfloat162*)(g_vl + base + wn*64 + nt*8 + cl2) = lp;
                }
            }
    }
}

// ============ HMMA GEMM 64x128 tile, double-buffered (WO/FF2 residual) ============
#define SROW 72
#define BUFSZ (384*SROW)
__global__ __launch_bounds__(256) void k_mma64(
    const __nv_bfloat16* __restrict__ Ah, const __nv_bfloat16* __restrict__ Al, int lda,
    const __nv_bfloat16* __restrict__ Bh, const __nv_bfloat16* __restrict__ Bl,
    int Ktot,
    const float* __restrict__ bias,
    float* __restrict__ out)
{
    extern __shared__ __align__(16) __nv_bfloat16 sb[];
    // per buffer: Ah @0 (64 rows), Al @64*SROW, Bh @128*SROW (128 rows), Bl @256*SROW

    const int t = threadIdx.x, w = t >> 5, lane = t & 31;
    const int wm = w & 1, wn = w >> 1;
    const int row0 = blockIdx.y*64;

    float acc[2][4][4] = {};
    const int lrow = (lane & 15), lcol8 = (lane >> 4)*8;

    const int ar = t >> 2, ac8 = (t & 3) << 3;       // a: 64 rows x 64 cols: f=i*256+t; r=f>>3
    // load chunk 0 directly
    {
        #pragma unroll
        for (int i = 0; i < 2; i++) {
            int f = i*256 + t;
            int r = f >> 3, c8 = (f & 7) << 3;
            *(uint4*)(sb + r*SROW + c8)            = *(const uint4*)(Ah + (size_t)(row0+r)*lda + c8);
            *(uint4*)(sb + 64*SROW + r*SROW + c8)  = *(const uint4*)(Al + (size_t)(row0+r)*lda + c8);
        }
        #pragma unroll
        for (int i = 0; i < 4; i++) {
            int f = i*256 + t;
            int r = f >> 3, c8 = (f & 7) << 3;
            *(uint4*)(sb + 128*SROW + r*SROW + c8) = *(const uint4*)(Bh + (size_t)r*Ktot + c8);
            *(uint4*)(sb + 256*SROW + r*SROW + c8) = *(const uint4*)(Bl + (size_t)r*Ktot + c8);
        }
    }
    __syncthreads();
    int buf = 0;

    for (int kc = 64; kc <= Ktot; kc += 64) {
        uint4 ra[2][2], rb[2][4];
        if (kc < Ktot) {
            #pragma unroll
            for (int i = 0; i < 2; i++) {
                int f = i*256 + t;
                int r = f >> 3, c8 = (f & 7) << 3;
                ra[0][i] = *(const uint4*)(Ah + (size_t)(row0+r)*lda + kc + c8);
                ra[1][i] = *(const uint4*)(Al + (size_t)(row0+r)*lda + kc + c8);
            }
            #pragma unroll
            for (int i = 0; i < 4; i++) {
                int f = i*256 + t;
                int r = f >> 3, c8 = (f & 7) << 3;
                rb[0][i] = *(const uint4*)(Bh + (size_t)r*Ktot + kc + c8);
                rb[1][i] = *(const uint4*)(Bl + (size_t)r*Ktot + kc + c8);
            }
        }
        const __nv_bfloat16* cb = sb + buf*BUFSZ;
        #pragma unroll
        for (int ks = 0; ks < 4; ks++) {
            int kcol = ks*16 + lcol8;
            uint32_t ah[2][4], al[2][4];
            #pragma unroll
            for (int mt = 0; mt < 2; mt++) {
                int arow = wm*32 + mt*16 + lrow;
                ldsm4(ah[mt], s2u(cb + arow*SROW + kcol));
                ldsm4(al[mt], s2u(cb + 64*SROW + arow*SROW + kcol));
            }
            #pragma unroll
            for (int nt2 = 0; nt2 < 2; nt2++) {
                int brow = wn*32 + nt2*16 + lrow;
                uint32_t rh[4], rl[4];
                ldsm4(rh, s2u(cb + 128*SROW + brow*SROW + kcol));
                ldsm4(rl, s2u(cb + 256*SROW + brow*SROW + kcol));
                uint32_t b0h[2] = {rh[0], rh[2]}, b1h[2] = {rh[1], rh[3]};
                uint32_t b0l[2] = {rl[0], rl[2]}, b1l[2] = {rl[1], rl[3]};
                #pragma unroll
                for (int mt = 0; mt < 2; mt++)
                    MMA3x2(acc[mt][nt2*2], acc[mt][nt2*2+1], ah[mt], al[mt], b0h, b0l, b1h, b1l);
            }
        }
        if (kc < Ktot) {
            __nv_bfloat16* nb = sb + (buf^1)*BUFSZ;
            #pragma unroll
            for (int i = 0; i < 2; i++) {
                int f = i*256 + t;
                int r = f >> 3, c8 = (f & 7) << 3;
                *(uint4*)(nb + r*SROW + c8)           = ra[0][i];
                *(uint4*)(nb + 64*SROW + r*SROW + c8) = ra[1][i];
            }
            #pragma unroll
            for (int i = 0; i < 4; i++) {
                int f = i*256 + t;
                int r = f >> 3, c8 = (f & 7) << 3;
                *(uint4*)(nb + 128*SROW + r*SROW + c8) = rb[0][i];
                *(uint4*)(nb + 256*SROW + r*SROW + c8) = rb[1][i];
            }
            __syncthreads();
            buf ^= 1;
        }
    }

    const int rl4 = lane >> 2, cl2 = (lane & 3)*2;
    #pragma unroll
    for (int mt = 0; mt < 2; mt++)
        #pragma unroll
        for (int h2 = 0; h2 < 2; h2++) {
            int gr = row0 + wm*32 + mt*16 + rl4 + h2*8;
            #pragma unroll
            for (int nt = 0; nt < 4; nt++) {
                int gc = wn*32 + nt*8 + cl2;
                size_t idx = (size_t)gr*DIMC + gc;
                float2 v = *(float2*)(out + idx);
                v.x += acc[mt][nt][h2*2]   + bias[gc];
                v.y += acc[mt][nt][h2*2+1] + bias[gc+1];
                *(float2*)(out + idx) = v;
            }
        }
}

// ---------------- embed ----------------
__global__ void k_embed(const float* __restrict__ x, const float* __restrict__ lw,
                        const float* __restrict__ lb, const float* __restrict__ pe)
{
    int warp = threadIdx.x >> 5, lane = threadIdx.x & 31;
    int r = blockIdx.x*8 + warp;
    float xv = x[r];
    float4 l4 = ((const float4*)lw)[lane];
    float4 b4 = ((const float4*)lb)[lane];
    float4 p4 = ((const float4*)(pe + (size_t)(r % SS)*DIMC))[lane];
    float4 o4 = { xv*l4.x + b4.x + p4.x, xv*l4.y + b4.y + p4.y,
                  xv*l4.z + b4.z + p4.z, xv*l4.w + b4.w + p4.w };
    ((float4*)(g_h + (size_t)r*DIMC))[lane] = o4;
}

// ---------------- layernorm -> bf16 hi/lo ----------------
__global__ void k_ln(const float* __restrict__ in, const float* __restrict__ g,
                     const float* __restrict__ b,
                     __nv_bfloat16* __restrict__ outH, __nv_bfloat16* __restrict__ outL)
{
    int warp = threadIdx.x >> 5, lane = threadIdx.x & 31;
    int r = blockIdx.x*8 + warp;
    float4 v = ((const float4*)(in + (size_t)r*DIMC))[lane];
    float s = v.x + v.y + v.z + v.w;
    #pragma unroll
    for (int o = 16; o > 0; o >>= 1) s += __shfl_xor_sync(0xffffffffu, s, o);
    float mu = s * (1.0f/DIMC);
    float dx = v.x-mu, dy = v.y-mu, dz = v.z-mu, dw = v.w-mu;
    float q = dx*dx + dy*dy + dz*dz + dw*dw;
    #pragma unroll
    for (int o = 16; o > 0; o >>= 1) q += __shfl_xor_sync(0xffffffffu, q, o);
    float inv = rsqrtf(q*(1.0f/DIMC) + 1e-5f);
    float4 gv = ((const float4*)g)[lane];
    float4 bv = ((const float4*)b)[lane];
    float o4[4] = { dx*inv*gv.x + bv.x, dy*inv*gv.y + bv.y,
                    dz*inv*gv.z + bv.z, dw*inv*gv.w + bv.w };
    __nv_bfloat16 hh[4], ll[4];
    #pragma unroll
    for (int j = 0; j < 4; j++) split_bf16(o4[j], hh[j], ll[j]);
    size_t base = (size_t)r*DIMC + lane*4;
    *(uint2*)(outH+base) = *(uint2*)hh;
    *(uint2*)(outL+base) = *(uint2*)ll;
}

// -------- weight transpose+split --------
__global__ __launch_bounds__(256) void k_wt(const float* __restrict__ W,
                                            __nv_bfloat16* __restrict__ outH,
                                            __nv_bfloat16* __restrict__ outL, int K, int N)
{
    __shared__ float tile[32][33];
    int n0 = blockIdx.x*32, k0 = blockIdx.y*32;
    int tx = threadIdx.x & 31, ty = threadIdx.x >> 5;
    #pragma unroll
    for (int i = ty; i < 32; i += 8)
        tile[i][tx] = W[(size_t)(k0+i)*N + n0 + tx];
    __syncthreads();
    #pragma unroll
    for (int i = ty; i < 32; i += 8) {
        float v = tile[tx][i];
        __nv_bfloat16 hh, ll;
        split_bf16(v, hh, ll);
        outH[(size_t)(n0+i)*K + k0 + tx] = hh;
        outL[(size_t)(n0+i)*K + k0 + tx] = ll;
    }
}

// ---------------- plain split (proj) ----------------
__global__ void k_cvt(const float* __restrict__ in, __nv_bfloat16* __restrict__ outH,
                      __nv_bfloat16* __restrict__ outL, int n4)
{
    int i = blockIdx.x*256 + threadIdx.x;
    if (i >= n4) return;
    float4 v = ((const float4*)in)[i];
    __nv_bfloat16 hh[4], ll[4];
    split_bf16(v.x, hh[0], ll[0]); split_bf16(v.y, hh[1], ll[1]);
    split_bf16(v.z, hh[2], ll[2]); split_bf16(v.w, hh[3], ll[3]);
    *(uint2*)(outH + i*4) = *(uint2*)hh;
    *(uint2*)(outL + i*4) = *(uint2*)ll;
}

// ---------------- stab reduce ----------------
__global__ void k_stab2()
{
    int bh = threadIdx.x;
    if (bh < NBH) {
        float m = -1e30f;
        #pragma unroll
        for (int i = 0; i < 16; i++) m = fmaxf(m, g_bmax[bh*16 + i]);
        g_stab[bh] = m;
    }
}

// ---------------- key feature exp -> bf16 hi/lo ----------------
__global__ void k_fek(const float* __restrict__ dd, const float* __restrict__ diag,
                      __nv_bfloat16* __restrict__ outH, __nv_bfloat16* __restrict__ outL)
{
    int r = blockIdx.x*8 + (threadIdx.x >> 5);
    int lane = threadIdx.x & 31;
    float st = g_stab[r >> 11];
    float dg = diag[r];
    float4 v = ((const float4*)(dd + (size_t)r*MF))[lane];
    float o[4] = { RATIOC*(expf(v.x-dg-st) + 1e-4f), RATIOC*(expf(v.y-dg-st) + 1e-4f),
                   RATIOC*(expf(v.z-dg-st) + 1e-4f), RATIOC*(expf(v.w-dg-st) + 1e-4f) };
    __nv_bfloat16 hh[4], ll[4];
    #pragma unroll
    for (int j = 0; j < 4; j++) split_bf16(o[j], hh[j], ll[j]);
    size_t base = (size_t)r*MF + lane*4;
    *(uint2*)(outH+base) = *(uint2*)hh;
    *(uint2*)(outL+base) = *(uint2*)ll;
}

// ================= chunk-local attention via HMMA, 512 threads =================
#define CP 136
__global__ __launch_bounds__(512) void k_chunk(
    const __nv_bfloat16* __restrict__ qph, const __nv_bfloat16* __restrict__ qpl,
    const __nv_bfloat16* __restrict__ kph, const __nv_bfloat16* __restrict__ kpl)
{
    extern __shared__ __align__(16) __nv_bfloat16 cs[];
    __nv_bfloat16* sQh = cs;                    // [i][m]; later attn [i][j]
    __nv_bfloat16* sQl = sQh + 128*CP;
    __nv_bfloat16* sKh = sQl + 128*CP;          // [j][m]
    __nv_bfloat16* sKl = sKh + 128*CP;
    __nv_bfloat16* sVh = sKl + 128*CP;          // [j][d]
    __nv_bfloat16* sVl = sVh + 128*CP;
    __shared__ float s_den[4][128];

    int blk = blockIdx.x, bh = blk >> 4, c = blk & 15;
    int b = bh >> 3, hh = bh & 7;
    int t = threadIdx.x, w = t >> 5, lane = t & 31;
    int wm = w & 3, wn = w >> 2;
    const int lrow = lane & 15, lcol8 = (lane >> 4)*8;
    const int rl4 = lane >> 2, cl2 = (lane & 3)*2;

    const size_t qbase = ((size_t)bh*SS + c*CHUNK)*MF;
    for (int i = t; i < 2048; i += 512) {
        int r = i >> 4, c8 = (i & 15) << 3;
        *(uint4*)(sQh + r*CP + c8) = *(const uint4*)(qph + qbase + r*MF + c8);
        *(uint4*)(sQl + r*CP + c8) = *(const uint4*)(qpl + qbase + r*MF + c8);
        *(uint4*)(sKh + r*CP + c8) = *(const uint4*)(kph + qbase + r*MF + c8);
        *(uint4*)(sKl + r*CP + c8) = *(const uint4*)(kpl + qbase + r*MF + c8);
        size_t vsrc = (size_t)(b*SS + c*CHUNK + r)*INNER + hh*DHD + c8;
        *(uint4*)(sVh + r*CP + c8) = *(const uint4*)(g_vh + vsrc);
        *(uint4*)(sVl + r*CP + c8) = *(const uint4*)(g_vl + vsrc);
    }
    __syncthreads();

    // ---- phase 1: attn = Q@K^T ; warps fully above the diagonal skip MMA ----
    float acc[2][4][4] = {};
    if (wn <= wm) {
        #pragma unroll
        for (int ks = 0; ks < 8; ks++) {
            int kcol = ks*16 + lcol8;
            uint32_t ah[2][4], al[2][4];
            #pragma unroll
            for (int mt = 0; mt < 2; mt++) {
                int arow = wm*32 + mt*16 + lrow;
                ldsm4(ah[mt], s2u(sQh + arow*CP + kcol));
                ldsm4(al[mt], s2u(sQl + arow*CP + kcol));
            }
            #pragma unroll
            for (int nt2 = 0; nt2 < 2; nt2++) {
                int brow = wn*32 + nt2*16 + lrow;
                uint32_t rh[4], rl[4];
                ldsm4(rh, s2u(sKh + brow*CP + kcol));
                ldsm4(rl, s2u(sKl + brow*CP + kcol));
                uint32_t b0h[2] = {rh[0], rh[2]}, b1h[2] = {rh[1], rh[3]};
                uint32_t b0l[2] = {rl[0], rl[2]}, b1l[2] = {rl[1], rl[3]};
                #pragma unroll
                for (int mt = 0; mt < 2; mt++)
                    MMA3x2(acc[mt][nt2*2], acc[mt][nt2*2+1], ah[mt], al[mt], b0h, b0l, b1h, b1l);
            }
        }
    }
    // mask + den partials
    float dp[2][2] = {};
    #pragma unroll
    for (int mt = 0; mt < 2; mt++)
        #pragma unroll
        for (int nt = 0; nt < 4; nt++)
            #pragma unroll
            for (int f = 0; f < 4; f++) {
                int i = wm*32 + mt*16 + rl4 + ((f>>1)<<3);
                int j = wn*32 + nt*8 + cl2 + (f&1);
                if (j > i) acc[mt][nt][f] = 0.f;
                dp[mt][f>>1] += acc[mt][nt][f];
            }
    #pragma unroll
    for (int o = 1; o < 4; o <<= 1)
        #pragma unroll
        for (int mt = 0; mt < 2; mt++)
            #pragma unroll
            for (int h2 = 0; h2 < 2; h2++)
                dp[mt][h2] += __shfl_xor_sync(0xffffffffu, dp[mt][h2], o);
    if ((lane & 3) == 0) {
        #pragma unroll
        for (int mt = 0; mt < 2; mt++)
            #pragma unroll
            for (int h2 = 0; h2 < 2; h2++)
                s_den[wn][wm*32 + mt*16 + rl4 + h2*8] = dp[mt][h2];
    }
    __syncthreads();

    // overwrite sQ with masked attn (hi/lo)
    #pragma unroll
    for (int mt = 0; mt < 2; mt++)
        #pragma unroll
        for (int nt = 0; nt < 4; nt++)
            #pragma unroll
            for (int f = 0; f < 4; f++) {
                int i = wm*32 + mt*16 + rl4 + ((f>>1)<<3);
                int j = wn*32 + nt*8 + cl2 + (f&1);
                __nv_bfloat16 hh2, ll2;
                split_bf16(acc[mt][nt][f], hh2, ll2);
                sQh[i*CP + j] = hh2;
                sQl[i*CP + j] = ll2;
            }
    if (t < 128) {
        g_den[(size_t)bh*SS + c*CHUNK + t] = s_den[0][t] + s_den[1][t] + s_den[2][t] + s_den[3][t];
        float kssum = 0.f;
        for (int j = 0; j < 128; j++)
            kssum += __bfloat162float(sKh[j*CP + t]) + __bfloat162float(sKl[j*CP + t]);
        g_ksc[((size_t)bh*NC + c)*MF + t] = kssum;
    }
    __syncthreads();

    // ---- phase 2: num = attn @ V ----
    #pragma unroll
    for (int mt = 0; mt < 2; mt++)
        #pragma unroll
        for (int nt = 0; nt < 4; nt++)
            #pragma unroll
            for (int f = 0; f < 4; f++) acc[mt][nt][f] = 0.f;
    #pragma unroll
    for (int ks = 0; ks < 8; ks++) {
        int kcol = ks*16 + lcol8;
        uint32_t ah[2][4], al[2][4];
        #pragma unroll
        for (int mt = 0; mt < 2; mt++) {
            int arow = wm*32 + mt*16 + lrow;
            ldsm4(ah[mt], s2u(sQh + arow*CP + kcol));
            ldsm4(al[mt], s2u(sQl + arow*CP + kcol));
        }
        #pragma unroll
        for (int nt2 = 0; nt2 < 2; nt2++) {
            int nbase = wn*32 + nt2*16;
            uint32_t dh[4], dl[4];
            ldsm4t(dh, taddr(sVh, CP, ks*16, nbase, lane));
            ldsm4t(dl, taddr(sVl, CP, ks*16, nbase, lane));
            uint32_t b0h[2] = {dh[0], dh[2]}, b1h[2] = {dh[1], dh[3]};
            uint32_t b0l[2] = {dl[0], dl[2]}, b1l[2] = {dl[1], dl[3]};
            #pragma unroll
            for (int mt = 0; mt < 2; mt++)
                MMA3x2(acc[mt][nt2*2], acc[mt][nt2*2+1], ah[mt], al[mt], b0h, b0l, b1h, b1l);
        }
    }
    #pragma unroll
    for (int mt = 0; mt < 2; mt++)
        #pragma unroll
        for (int h2 = 0; h2 < 2; h2++) {
            int i = wm*32 + mt*16 + rl4 + h2*8;
            size_t base = ((size_t)(b*SS + c*CHUNK + i)*HH + hh)*DHD;
            #pragma unroll
            for (int nt = 0; nt < 4; nt++) {
                float2 vv = {acc[mt][nt][h2*2], acc[mt][nt][h2*2+1]};
                *(float2*)(g_o + base + wn*32 + nt*8 + cl2) = vv;
            }
        }

    // ---- phase 3: kv = K^T @ V ----
    #pragma unroll
    for (int mt = 0; mt < 2; mt++)
        #pragma unroll
        for (int nt = 0; nt < 4; nt++)
            #pragma unroll
            for (int f = 0; f < 4; f++) acc[mt][nt][f] = 0.f;
    #pragma unroll
    for (int ks = 0; ks < 8; ks++) {
        uint32_t ah[2][4], al[2][4];
        #pragma unroll
        for (int mt = 0; mt < 2; mt++) {
            int mbase = wm*32 + mt*16;
            ldsm4t(ah[mt], taddr(sKh, CP, ks*16, mbase, lane));
            ldsm4t(al[mt], taddr(sKl, CP, ks*16, mbase, lane));
        }
        #pragma unroll
        for (int nt2 = 0; nt2 < 2; nt2++) {
            int nbase = wn*32 + nt2*16;
            uint32_t dh[4], dl[4];
            ldsm4t(dh, taddr(sVh, CP, ks*16, nbase, lane));
            ldsm4t(dl, taddr(sVl, CP, ks*16, nbase, lane));
            uint32_t b0h[2] = {dh[0], dh[2]}, b1h[2] = {dh[1], dh[3]};
            uint32_t b0l[2] = {dl[0], dl[2]}, b1l[2] = {dl[1], dl[3]};
            #pragma unroll
            for (int mt = 0; mt < 2; mt++)
                MMA3x2(acc[mt][nt2*2], acc[mt][nt2*2+1], ah[mt], al[mt], b0h, b0l, b1h, b1l);
        }
    }
    {
        size_t kvbase = ((size_t)bh*NC + c)*(MF*DHD);
        #pragma unroll
        for (int mt = 0; mt < 2; mt++)
            #pragma unroll
            for (int h2 = 0; h2 < 2; h2++) {
                int m = wm*32 + mt*16 + rl4 + h2*8;
                #pragma unroll
                for (int nt = 0; nt < 4; nt++) {
                    float2 vv = {acc[mt][nt][h2*2], acc[mt][nt][h2*2+1]};
                    *(float2*)(g_kvc + kvbase + (size_t)m*DHD + wn*32 + nt*8 + cl2) = vv;
                }
            }
    }
}

// ---------------- exclusive prefix over chunks (emits bf16 hi/lo) ----------------
__global__ void k_prefix()
{
    int bh = blockIdx.x, seg = blockIdx.y, t = threadIdx.x;
    for (int e = seg*2048 + t; e < (seg+1)*2048; e += 256) {
        float run = 0.f;
        #pragma unroll
        for (int c = 0; c < NC; c++) {
            size_t idx = ((size_t)bh*NC + c)*(MF*DHD) + e;
            __nv_bfloat16 hh, ll;
            split_bf16(run, hh, ll);
            g_kvph[idx] = hh; g_kvpl[idx] = ll;
            run += g_kvc[idx];
        }
    }
    if (seg == 0) {
        for (int e = t; e < MF; e += 256) {
            float run = 0.f;
            #pragma unroll
            for (int c = 0; c < NC; c++) {
                size_t idx = ((size_t)bh*NC + c)*MF + e;
                g_ksp[idx] = run; run += g_ksc[idx];
            }
        }
    }
}

// ========== cross = qp @ kvp, + num, normalize -> oh/ol (HMMA, 512 thr) ==========
__global__ __launch_bounds__(512) void k_cross(
    const __nv_bfloat16* __restrict__ qph, const __nv_bfloat16* __restrict__ qpl)
{
    extern __shared__ __align__(16) __nv_bfloat16 cs[];
    __nv_bfloat16* sQh = cs;
    __nv_bfloat16* sQl = sQh + 128*CP;
    __nv_bfloat16* sPh = sQl + 128*CP;
    __nv_bfloat16* sPl = sPh + 128*CP;
    __shared__ float s_ks[128];
    __shared__ float s_dc[128];

    int blk = blockIdx.x, bh = blk >> 4, c = blk & 15;
    int b = bh >> 3, hh = bh & 7;
    int t = threadIdx.x, w = t >> 5, lane = t & 31;
    int wm = w & 3, wn = w >> 2;
    const int lrow = lane & 15, lcol8 = (lane >> 4)*8;
    const int rl4 = lane >> 2, cl2 = (lane & 3)*2;

    const size_t qbase = ((size_t)bh*SS + c*CHUNK)*MF;
    const size_t pbase = ((size_t)bh*NC + c)*(MF*DHD);
    for (int i = t; i < 2048; i += 512) {
        int r = i >> 4, c8 = (i & 15) << 3;
        *(uint4*)(sQh + r*CP + c8) = *(const uint4*)(qph + qbase + r*MF + c8);
        *(uint4*)(sQl + r*CP + c8) = *(const uint4*)(qpl + qbase + r*MF + c8);
        *(uint4*)(sPh + r*CP + c8) = *(const uint4*)(g_kvph + pbase + r*DHD + c8);
        *(uint4*)(sPl + r*CP + c8) = *(const uint4*)(g_kvpl + pbase + r*DHD + c8);
    }
    if (t < 128) s_ks[t] = g_ksp[((size_t)bh*NC + c)*MF + t];
    __syncthreads();
    if (t < 128) {
        float dc = 0.f;
        for (int m = 0; m < 128; m++)
            dc += (__bfloat162float(sQh[t*CP + m]) + __bfloat162float(sQl[t*CP + m]))*s_ks[m];
        s_dc[t] = g_den[(size_t)bh*SS + c*CHUNK + t] + dc + 1e-6f;
    }
    __syncthreads();

    float acc[2][4][4] = {};
    #pragma unroll
    for (int ks = 0; ks < 8; ks++) {
        int kcol = ks*16 + lcol8;
        uint32_t ah[2][4], al[2][4];
        #pragma unroll
        for (int mt = 0; mt < 2; mt++) {
            int arow = wm*32 + mt*16 + lrow;
            ldsm4(ah[mt], s2u(sQh + arow*CP + kcol));
            ldsm4(al[mt], s2u(sQl + arow*CP + kcol));
        }
        #pragma unroll
        for (int nt2 = 0; nt2 < 2; nt2++) {
            int nbase = wn*32 + nt2*16;
            uint32_t dh[4], dl[4];
            ldsm4t(dh, taddr(sPh, CP, ks*16, nbase, lane));
            ldsm4t(dl, taddr(sPl, CP, ks*16, nbase, lane));
            uint32_t b0h[2] = {dh[0], dh[2]}, b1h[2] = {dh[1], dh[3]};
            uint32_t b0l[2] = {dl[0], dl[2]}, b1l[2] = {dl[1], dl[3]};
            #pragma unroll
            for (int mt = 0; mt < 2; mt++)
                MMA3x2(acc[mt][nt2*2], acc[mt][nt2*2+1], ah[mt], al[mt], b0h, b0l, b1h, b1l);
        }
    }
    #pragma unroll
    for (int mt = 0; mt < 2; mt++)
        #pragma unroll
        for (int h2 = 0; h2 < 2; h2++) {
            int i = wm*32 + mt*16 + rl4 + h2*8;
            float inv = 1.0f / s_dc[i];
            size_t base = ((size_t)(b*SS + c*CHUNK + i)*HH + hh)*DHD;
            #pragma unroll
            for (int nt = 0; nt < 4; nt++) {
                size_t idx = base + wn*32 + nt*8 + cl2;
                float2 nn = *(float2*)(g_o + idx);
                float v0 = (nn.x + acc[mt][nt][h2*2])   * inv;
                float v1 = (nn.y + acc[mt][nt][h2*2+1]) * inv;
                __nv_bfloat16 h0,l0,h1,l1;
                split_bf16(v0,h0,l0); split_bf16(v1,h1,l1);
                __nv_bfloat162 hp, lp;
                hp.x = h0; hp.y = h1; lp.x = l0; lp.y = l1;
                *(__nv_bfloat162*)(g_oh + idx) = hp;
                *(__nv_bfloat162*)(g_ol + idx) = lp;
            }
        }
}

// ---------------- pooling ----------------
__global__ void k_pool()
{
    int b = blockIdx.x, seg = blockIdx.y, t = threadIdx.x;
    float acc = 0.f;
    for (int s = seg*128; s < (seg+1)*128; s++) acc += g_h[((size_t)b*SS + s)*DIMC + t];
    g_pp[(b*16 + seg)*DIMC + t] = acc;
}

__global__ void k_final(const float* __restrict__ fw, const float* __restrict__ fb,
                        float* __restrict__ out)
{
    __shared__ float pooled[BB*DIMC];
    int t = threadIdx.x;
    for (int b = 0; b < BB; b++) {
        float a = 0.f;
        #pragma unroll
        for (int s = 0; s < 16; s++) a += g_pp[(b*16 + s)*DIMC + t];
        pooled[b*DIMC + t] = a * (1.0f/SS);
    }
    __syncthreads();
    if (t < BB*NCLS) {
        int b = t / NCLS, c = t % NCLS;
        float acc = fb[c];
        for (int d = 0; d < DIMC; d++) acc += pooled[b*DIMC + d]*fw[d*NCLS + c];
        out[t] = acc;
    }
}

// ---------------- host driver ----------------
static void* sym(const void* s) { void* p = nullptr; cudaGetSymbolAddress(&p, s); return p; }

extern "C" void kernel_launch(void* const* d_in, const int* in_sizes, int n_in,
                              void* d_out, int out_size)
{
    const float* x     = (const float*)d_in[0];
    const float* lin_w = (const float*)d_in[1];
    const float* lin_b = (const float*)d_in[2];
    const float* pe    = (const float*)d_in[3];
    const float* proj  = (const float*)d_in[4];
    const float* ln1_g = (const float*)d_in[5];
    const float* ln1_b = (const float*)d_in[6];
    const float* wq    = (const float*)d_in[7];
    const float* wk    = (const float*)d_in[8];
    const float* wv    = (const float*)d_in[9];
    const float* wo    = (const float*)d_in[10];
    const float* wo_b  = (const float*)d_in[11];
    const float* ln2_g = (const float*)d_in[12];
    const float* ln2_b = (const float*)d_in[13];
    const float* ff1_w = (const float*)d_in[14];
    const float* ff1_b = (const float*)d_in[15];
    const float* ff2_w = (const float*)d_in[16];
    const float* ff2_b = (const float*)d_in[17];
    const float* fin_w = (const float*)d_in[18];
    const float* fin_b = (const float*)d_in[19];
    float* out = (float*)d_out;

    float* ph   = (float*)sym(g_h);
    float* pkp  = (float*)sym(g_kp);
    float* pdq  = (float*)sym(g_diagq);
    float* pdk  = (float*)sym(g_diagk);
    float* pbm  = (float*)sym(g_bmax);

    __nv_bfloat16* yh  = (__nv_bfloat16*)sym(g_yh);
    __nv_bfloat16* yl  = (__nv_bfloat16*)sym(g_yl);
    __nv_bfloat16* wth = (__nv_bfloat16*)sym(g_wth);
    __nv_bfloat16* wtl = (__nv_bfloat16*)sym(g_wtl);
    __nv_bfloat16* qnh = (__nv_bfloat16*)sym(g_qnh);
    __nv_bfloat16* qnl = (__nv_bfloat16*)sym(g_qnl);
    __nv_bfloat16* knh = (__nv_bfloat16*)sym(g_knh);
    __nv_bfloat16* knl = (__nv_bfloat16*)sym(g_knl);
    __nv_bfloat16* qp_h = (__nv_bfloat16*)sym(g_qph);
    __nv_bfloat16* qp_l = (__nv_bfloat16*)sym(g_qpl);
    __nv_bfloat16* kp_h = (__nv_bfloat16*)sym(g_kph);
    __nv_bfloat16* kp_l = (__nv_bfloat16*)sym(g_kpl);
    __nv_bfloat16* oh  = (__nv_bfloat16*)sym(g_oh);
    __nv_bfloat16* ol  = (__nv_bfloat16*)sym(g_ol);
    __nv_bfloat16* fh  = (__nv_bfloat16*)sym(g_fh);
    __nv_bfloat16* fl  = (__nv_bfloat16*)sym(g_fl);

    const int SMEM_MMA   = 4*128*KP*2;           // 139264
    const int SMEM_MMA64 = 2*BUFSZ*2;            // 110592
    const int SMEM_CHUNK = 6*128*CP*2;           // 208896
    const int SMEM_CROSS = 4*128*CP*2;           // 139264
    cudaFuncSetAttribute(k_mma<1>, cudaFuncAttributeMaxDynamicSharedMemorySize, SMEM_MMA);
    cudaFuncSetAttribute(k_mma<3>, cudaFuncAttributeMaxDynamicSharedMemorySize, SMEM_MMA);
    cudaFuncSetAttribute(k_mma<4>, cudaFuncAttributeMaxDynamicSharedMemorySize, SMEM_MMA);
    cudaFuncSetAttribute(k_mmaqkv, cudaFuncAttributeMaxDynamicSharedMemorySize, SMEM_MMA);
    cudaFuncSetAttribute(k_mma64, cudaFuncAttributeMaxDynamicSharedMemorySize, SMEM_MMA64);
    cudaFuncSetAttribute(k_chunk, cudaFuncAttributeMaxDynamicSharedMemorySize, SMEM_CHUNK);
    cudaFuncSetAttribute(k_cross, cudaFuncAttributeMaxDynamicSharedMemorySize, SMEM_CROSS);

    k_embed<<<BSR/8, 256>>>(x, lin_w, lin_b, pe);

    for (int l = 0; l < DEPTH; l++) {
        size_t wb = (size_t)l*WT_LAYER;
        k_wt<<<dim3(INNER/32, DIMC/32), 256>>>(wq + (size_t)l*DIMC*INNER, wth+wb+WT_Q, wtl+wb+WT_Q, DIMC, INNER);
        k_wt<<<dim3(INNER/32, DIMC/32), 256>>>(wk + (size_t)l*DIMC*INNER, wth+wb+WT_K, wtl+wb+WT_K, DIMC, INNER);
        k_wt<<<dim3(INNER/32, DIMC/32), 256>>>(wv + (size_t)l*DIMC*INNER, wth+wb+WT_V, wtl+wb+WT_V, DIMC, INNER);
        k_wt<<<dim3(DIMC/32, INNER/32), 256>>>(wo + (size_t)l*INNER*DIMC, wth+wb+WT_O, wtl+wb+WT_O, INNER, DIMC);
        k_wt<<<dim3(FFD/32, DIMC/32), 256>>>(ff1_w + (size_t)l*DIMC*FFD, wth+wb+WT_F1, wtl+wb+WT_F1, DIMC, FFD);
        k_wt<<<dim3(DIMC/32, FFD/32), 256>>>(ff2_w + (size_t)l*FFD*DIMC, wth+wb+WT_F2, wtl+wb+WT_F2, FFD, DIMC);
        k_cvt<<<16, 256>>>(proj + (size_t)l*MF*DHD, wth+wb+WT_PJ, wtl+wb+WT_PJ, MF*DHD/4);
    }

    for (int l = 0; l < DEPTH; l++) {
        size_t wb = (size_t)l*WT_LAYER;

        k_ln<<<BSR/8, 256>>>(ph, ln1_g + l*DIMC, ln1_b + l*DIMC, yh, yl);

        // fused QKV with fully fused epilogue (qn/kn scaled+transposed+split+diag, v split)
        k_mmaqkv<<<dim3(24,64), 256, SMEM_MMA>>>(yh, yl, wth+wb+WT_Q, wtl+wb+WT_Q);

        k_mma<4><<<dim3(1,512), 256, SMEM_MMA>>>(knh, knl, wth+wb+WT_PJ, wtl+wb+WT_PJ, MF,
                                                 nullptr, pkp, nullptr, nullptr, nullptr, pbm);
        k_stab2<<<1, 32>>>();
        k_fek<<<BHS/8, 256>>>(pkp, pdk, kp_h, kp_l);
        k_mma<3><<<dim3(1,512), 256, SMEM_MMA>>>(qnh, qnl, wth+wb+WT_PJ, wtl+wb+WT_PJ, MF,
                                                 nullptr, nullptr, qp_h, qp_l, pdq, nullptr);

        k_chunk<<<NBH*NC, 512, SMEM_CHUNK>>>(qp_h, qp_l, kp_h, kp_l);
        k_prefix<<<dim3(NBH, 8), 256>>>();
        k_cross<<<NBH*NC, 512, SMEM_CROSS>>>(qp_h, qp_l);

        k_mma64<<<dim3(1,BSR/64), 256, SMEM_MMA64>>>(oh, ol, INNER, wth+wb+WT_O, wtl+wb+WT_O, INNER,
                                                     wo_b + l*DIMC, ph);

        k_ln<<<BSR/8, 256>>>(ph, ln2_g + l*DIMC, ln2_b + l*DIMC, yh, yl);
        k_mma<1><<<dim3(4,64), 256, SMEM_MMA>>>(yh, yl, wth+wb+WT_F1, wtl+wb+WT_F1, FFD,
                                                ff1_b + l*FFD, nullptr, fh, fl, nullptr, nullptr);
        k_mma64<<<dim3(1,BSR/64), 256, SMEM_MMA64>>>(fh, fl, FFD, wth+wb+WT_F2, wtl+wb+WT_F2, FFD,
                                                     ff2_b + l*DIMC, ph);
    }

    k_pool<<<dim3(BB, 16), 128>>>();
    k_final<<<1, 128>>>(fin_w, fin_b, out);
}

// round 8
// speedup vs baseline: 2.2331x; 1.0418x over previous
#include <cuda_runtime.h>
#include <cuda_bf16.h>
#include <math.h>
#include <stdint.h>

// ---------------- problem constants ----------------
#define BB 4
#define SS 2048
#define DIMC 128
#define HH 8
#define DHD 128
#define DEPTH 2
#define NCLS 10
#define MF 128
#define CHUNK 128
#define NC 16
#define INNER 1024
#define FFD 512
#define BSR 8192
#define BHS 65536
#define NBH 32

#define NORMC 0.29730177875068026f
#define RATIOC 0.08838834764831845f

// ---------------- device scratch (fp32) ----------------
__device__ float g_h  [BSR*DIMC];
__device__ float g_kp [(size_t)NBH*SS*MF];       // K features dd (pre-exp)
__device__ float g_diagk[BHS];
__device__ float g_bmax[NBH*16];
__device__ float g_o  [BSR*INNER];               // local num, [B,S,H,DH]
__device__ float g_den[BHS];
__device__ float g_kvc[(size_t)NBH*NC*MF*DHD];
__device__ float g_ksc[NBH*NC*MF];
__device__ float g_ksp[NBH*NC*MF];
__device__ float g_pp [BB*16*DIMC];

// ---------------- device scratch (bf16 hi/lo) ----------------
__device__ __align__(256) __nv_bfloat16 g_yh [BSR*DIMC];
__device__ __align__(256) __nv_bfloat16 g_yl [BSR*DIMC];
__device__ __align__(256) __nv_bfloat16 g_wth[2*672000];
__device__ __align__(256) __nv_bfloat16 g_wtl[2*672000];
__device__ __align__(256) __nv_bfloat16 g_qnh[(size_t)BHS*DHD];
__device__ __align__(256) __nv_bfloat16 g_qnl[(size_t)BHS*DHD];
__device__ __align__(256) __nv_bfloat16 g_knh[(size_t)BHS*DHD];
__device__ __align__(256) __nv_bfloat16 g_knl[(size_t)BHS*DHD];
__device__ __align__(256) __nv_bfloat16 g_vh [(size_t)BSR*INNER];
__device__ __align__(256) __nv_bfloat16 g_vl [(size_t)BSR*INNER];
__device__ __align__(256) __nv_bfloat16 g_qph[(size_t)NBH*SS*MF];
__device__ __align__(256) __nv_bfloat16 g_qpl[(size_t)NBH*SS*MF];
__device__ __align__(256) __nv_bfloat16 g_kvph[(size_t)NBH*NC*MF*DHD];
__device__ __align__(256) __nv_bfloat16 g_kvpl[(size_t)NBH*NC*MF*DHD];
__device__ __align__(256) __nv_bfloat16 g_oh [(size_t)BSR*INNER];
__device__ __align__(256) __nv_bfloat16 g_ol [(size_t)BSR*INNER];
__device__ __align__(256) __nv_bfloat16 g_fh [(size_t)BSR*FFD];
__device__ __align__(256) __nv_bfloat16 g_fl [(size_t)BSR*FFD];

#define WT_Q  0
#define WT_K  131072
#define WT_V  262144
#define WT_O  393216
#define WT_F1 524288
#define WT_F2 589824
#define WT_PJ 655360
#define WT_LAYER 672000

// ---------------- warp MMA helpers ----------------
__device__ __forceinline__ uint32_t s2u(const void* p){
    uint32_t a;
    asm("{ .reg .u64 t; cvta.to.shared.u64 t, %1; cvt.u32.u64 %0, t; }" : "=r"(a) : "l"(p));
    return a;
}
__device__ __forceinline__ void ldsm4(uint32_t* r, uint32_t addr){
    asm volatile("ldmatrix.sync.aligned.m8n8.x4.shared.b16 {%0,%1,%2,%3}, [%4];"
                 : "=r"(r[0]),"=r"(r[1]),"=r"(r[2]),"=r"(r[3]) : "r"(addr));
}
__device__ __forceinline__ void ldsm4t(uint32_t* r, uint32_t addr){
    asm volatile("ldmatrix.sync.aligned.m8n8.x4.trans.shared.b16 {%0,%1,%2,%3}, [%4];"
                 : "=r"(r[0]),"=r"(r[1]),"=r"(r[2]),"=r"(r[3]) : "r"(addr));
}
__device__ __forceinline__ void mma_bf16(float* c, const uint32_t* a, const uint32_t* b){
    asm volatile("mma.sync.aligned.m16n8k16.row.col.f32.bf16.bf16.f32 "
                 "{%0,%1,%2,%3}, {%4,%5,%6,%7}, {%8,%9}, {%0,%1,%2,%3};"
                 : "+f"(c[0]),"+f"(c[1]),"+f"(c[2]),"+f"(c[3])
                 : "r"(a[0]),"r"(a[1]),"r"(a[2]),"r"(a[3]), "r"(b[0]),"r"(b[1]));
}
__device__ __forceinline__ void split_bf16(float v, __nv_bfloat16& h, __nv_bfloat16& l){
    h = __float2bfloat16(v);
    l = __float2bfloat16(v - __bfloat162float(h));
}
__device__ __forceinline__ float gelu(float xx){
    return 0.5f*xx*(1.0f + tanhf(0.7978845608028654f*(xx + 0.044715f*xx*xx*xx)));
}
__device__ __forceinline__ uint32_t taddr(const __nv_bfloat16* S, int P, int kbase, int nbase, int lane){
    int kk = (lane & 7) + ((lane >> 4) << 3);
    int nn = ((lane >> 3) & 1) << 3;
    return s2u(S + (size_t)(kbase + kk)*P + nbase + nn);
}
#define MMA3x2(accA, accB, ah_, al_, b0h_, b0l_, b1h_, b1l_) \
    do { mma_bf16(accA, ah_, b0h_); mma_bf16(accA, ah_, b0l_); mma_bf16(accA, al_, b0h_); \
         mma_bf16(accB, ah_, b1h_); mma_bf16(accB, ah_, b1l_); mma_bf16(accB, al_, b1h_); } while(0)

#define KP 136

// ======== feature GEMM (128x128, K=128): MODE 3 = Q (exp fused), MODE 4 = K (dd+bmax+diag)
template<int MODE>
__global__ __launch_bounds__(256) void k_mmaF(
    const __nv_bfloat16* __restrict__ Ah, const __nv_bfloat16* __restrict__ Al,
    const __nv_bfloat16* __restrict__ Bh, const __nv_bfloat16* __restrict__ Bl,
    float* __restrict__ out,
    __nv_bfloat16* __restrict__ outH, __nv_bfloat16* __restrict__ outL,
    float* __restrict__ bmax)
{
    extern __shared__ __align__(16) char dsm[];
    __nv_bfloat16* sAh = (__nv_bfloat16*)dsm;
    __nv_bfloat16* sAl = sAh + 128*KP;
    __nv_bfloat16* sBh = sAl + 128*KP;
    __nv_bfloat16* sBl = sBh + 128*KP;
    __shared__ float s_rm[2][128];
    __shared__ float s_red[256];
    __shared__ float s_dg[128];

    const int t = threadIdx.x, w = t >> 5, lane = t & 31;
    const int wm = w & 3, wn = w >> 2;
    const int row0 = blockIdx.y*128;

    float acc[2][8][4] = {};
    const int lrow = (lane & 15), lcol8 = (lane >> 4)*8;

    #pragma unroll
    for (int i = 0; i < 8; i++) {
        int f = i*256 + t;
        int r = f >> 4, c8 = (f & 15) << 3;
        *(uint4*)(sAh + r*KP + c8) = *(const uint4*)(Ah + (size_t)(row0+r)*128 + c8);
        *(uint4*)(sAl + r*KP + c8) = *(const uint4*)(Al + (size_t)(row0+r)*128 + c8);
        *(uint4*)(sBh + r*KP + c8) = *(const uint4*)(Bh + (size_t)r*128 + c8);
        *(uint4*)(sBl + r*KP + c8) = *(const uint4*)(Bl + (size_t)r*128 + c8);
    }
    __syncthreads();

    // diag = 0.5*sum((ah+al)^2) computed from the smem-resident A tile
    if (t < 128) {
        float dacc = 0.f;
        #pragma unroll
        for (int k8 = 0; k8 < 16; k8++) {
            uint4 uh = *(uint4*)(sAh + t*KP + k8*8);
            uint4 ul = *(uint4*)(sAl + t*KP + k8*8);
            const __nv_bfloat16* ph = (const __nv_bfloat16*)&uh;
            const __nv_bfloat16* pl = (const __nv_bfloat16*)&ul;
            #pragma unroll
            for (int j = 0; j < 8; j++) {
                float av = __bfloat162float(ph[j]) + __bfloat162float(pl[j]);
                dacc += av*av;
            }
        }
        if (MODE == 4) g_diagk[row0 + t] = 0.5f*dacc;
        else           s_dg[t] = 0.5f*dacc;
    }

    #pragma unroll
    for (int ks = 0; ks < 8; ks++) {
        int kcol = ks*16 + lcol8;
        uint32_t ah[2][4], al[2][4];
        #pragma unroll
        for (int mt = 0; mt < 2; mt++) {
            int arow = wm*32 + mt*16 + lrow;
            ldsm4(ah[mt], s2u(sAh + arow*KP + kcol));
            ldsm4(al[mt], s2u(sAl + arow*KP + kcol));
        }
        #pragma unroll
        for (int nt2 = 0; nt2 < 4; nt2++) {
            int brow = wn*64 + nt2*16 + lrow;
            uint32_t rh[4], rl[4];
            ldsm4(rh, s2u(sBh + brow*KP + kcol));
            ldsm4(rl, s2u(sBl + brow*KP + kcol));
            uint32_t b0h[2] = {rh[0], rh[2]}, b1h[2] = {rh[1], rh[3]};
            uint32_t b0l[2] = {rl[0], rl[2]}, b1l[2] = {rl[1], rl[3]};
            #pragma unroll
            for (int mt = 0; mt < 2; mt++)
                MMA3x2(acc[mt][nt2*2], acc[mt][nt2*2+1], ah[mt], al[mt], b0h, b0l, b1h, b1l);
        }
    }

    const int rl4 = lane >> 2, cl2 = (lane & 3)*2;

    if (MODE == 4) {
        float bm = -1e30f;
        #pragma unroll
        for (int mt = 0; mt < 2; mt++)
            #pragma unroll
            for (int h = 0; h < 2; h++) {
                int gr = row0 + wm*32 + mt*16 + rl4 + h*8;
                #pragma unroll
                for (int nt = 0; nt < 8; nt++) {
                    float2 v = {acc[mt][nt][h*2], acc[mt][nt][h*2+1]};
                    *(float2*)(out + (size_t)gr*MF + wn*64 + nt*8 + cl2) = v;
                    bm = fmaxf(bm, fmaxf(v.x, v.y));
                }
            }
        s_red[t] = bm; __syncthreads();
        #pragma unroll
        for (int o = 128; o > 0; o >>= 1) { if (t < o) s_red[t] = fmaxf(s_red[t], s_red[t+o]); __syncthreads(); }
        if (t == 0) bmax[blockIdx.y] = s_red[0];
    } else { // MODE 3
        float rm[2][2];
        #pragma unroll
        for (int mt = 0; mt < 2; mt++)
            #pragma unroll
            for (int h = 0; h < 2; h++) {
                float m = -1e30f;
                #pragma unroll
                for (int nt = 0; nt < 8; nt++)
                    m = fmaxf(m, fmaxf(acc[mt][nt][h*2], acc[mt][nt][h*2+1]));
                m = fmaxf(m, __shfl_xor_sync(0xffffffffu, m, 1));
                m = fmaxf(m, __shfl_xor_sync(0xffffffffu, m, 2));
                rm[mt][h] = m;
            }
        if ((lane & 3) == 0) {
            #pragma unroll
            for (int mt = 0; mt < 2; mt++)
                #pragma unroll
                for (int h = 0; h < 2; h++)
                    s_rm[wn][wm*32 + mt*16 + rl4 + h*8] = rm[mt][h];
        }
        __syncthreads();
        #pragma unroll
        for (int mt = 0; mt < 2; mt++)
            #pragma unroll
            for (int h = 0; h < 2; h++) {
                int lr = wm*32 + mt*16 + rl4 + h*8;
                int gr = row0 + lr;
                float rmax = fmaxf(s_rm[0][lr], s_rm[1][lr]);
                float dg = s_dg[lr];
                #pragma unroll
                for (int nt = 0; nt < 8; nt++) {
                    int gc = wn*64 + nt*8 + cl2;
                    float v0 = RATIOC*(expf(acc[mt][nt][h*2]  -dg-rmax) + 1e-4f);
                    float v1 = RATIOC*(expf(acc[mt][nt][h*2+1]-dg-rmax) + 1e-4f);
                    __nv_bfloat16 h0,l0,h1,l1;
                    split_bf16(v0,h0,l0); split_bf16(v1,h1,l1);
                    __nv_bfloat162 hp, lp;
                    hp.x = h0; hp.y = h1; lp.x = l0; lp.y = l1;
                    *(__nv_bfloat162*)(outH + (size_t)gr*MF + gc) = hp;
                    *(__nv_bfloat162*)(outL + (size_t)gr*MF + gc) = lp;
                }
            }
    }
}

// ======== 128x64-tile K=128 mainloop (2 CTAs/SM) — shared by QKV and FF1 ========
#define QKV_SMEM ((2*128 + 2*64)*KP*2)
#define MAINLOOP_64COL(sAh, sAl, sBh, sBl, Ah, Al, Bh, Bl, row0, col0, acc) \
    {   \
        _Pragma("unroll")                                                        \
        for (int i = 0; i < 8; i++) {                                            \
            int f = i*256 + threadIdx.x;                                         \
            int r = f >> 4, c8 = (f & 15) << 3;                                  \
            *(uint4*)(sAh + r*KP + c8) = *(const uint4*)(Ah + (size_t)(row0+r)*128 + c8); \
            *(uint4*)(sAl + r*KP + c8) = *(const uint4*)(Al + (size_t)(row0+r)*128 + c8); \
        }                                                                        \
        _Pragma("unroll")                                                        \
        for (int i = 0; i < 4; i++) {                                            \
            int f = i*256 + threadIdx.x;                                         \
            int r = f >> 4, c8 = (f & 15) << 3;                                  \
            *(uint4*)(sBh + r*KP + c8) = *(const uint4*)(Bh + (size_t)(col0+r)*128 + c8); \
            *(uint4*)(sBl + r*KP + c8) = *(const uint4*)(Bl + (size_t)(col0+r)*128 + c8); \
        }                                                                        \
        __syncthreads();                                                         \
        _Pragma("unroll")                                                        \
        for (int ks = 0; ks < 8; ks++) {                                         \
            int kcol = ks*16 + lcol8;                                            \
            uint32_t ah[2][4], al[2][4];                                         \
            _Pragma("unroll")                                                    \
            for (int mt = 0; mt < 2; mt++) {                                     \
                int arow = wm*32 + mt*16 + lrow;                                 \
                ldsm4(ah[mt], s2u(sAh + arow*KP + kcol));                        \
                ldsm4(al[mt], s2u(sAl + arow*KP + kcol));                        \
            }                                                                    \
            _Pragma("unroll")                                                    \
            for (int nt2 = 0; nt2 < 2; nt2++) {                                  \
                int brow = wn*32 + nt2*16 + lrow;                                \
                uint32_t rh[4], rl[4];                                           \
                ldsm4(rh, s2u(sBh + brow*KP + kcol));                            \
                ldsm4(rl, s2u(sBl + brow*KP + kcol));                            \
                uint32_t b0h[2] = {rh[0], rh[2]}, b1h[2] = {rh[1], rh[3]};       \
                uint32_t b0l[2] = {rl[0], rl[2]}, b1l[2] = {rl[1], rl[3]};       \
                _Pragma("unroll")                                                \
                for (int mt = 0; mt < 2; mt++)                                   \
                    MMA3x2(acc[mt][nt2*2], acc[mt][nt2*2+1], ah[mt], al[mt], b0h, b0l, b1h, b1l); \
            }                                                                    \
        }                                                                        \
    }

// QKV: grid (48, 64); col block = 64 wide; epilogue scatters per part/head
__global__ __launch_bounds__(256) void k_mmaqkv64(
    const __nv_bfloat16* __restrict__ Ah, const __nv_bfloat16* __restrict__ Al,
    const __nv_bfloat16* __restrict__ Bh, const __nv_bfloat16* __restrict__ Bl)
{
    extern __shared__ __align__(16) char dsm[];
    __nv_bfloat16* sAh = (__nv_bfloat16*)dsm;
    __nv_bfloat16* sAl = sAh + 128*KP;
    __nv_bfloat16* sBh = sAl + 128*KP;
    __nv_bfloat16* sBl = sBh + 64*KP;
    const int t = threadIdx.x, w = t >> 5, lane = t & 31;
    const int wm = w & 3, wn = w >> 2;
    const int row0 = blockIdx.y*128, col0 = blockIdx.x*64;
    const int lrow = (lane & 15), lcol8 = (lane >> 4)*8;
    float acc[2][4][4] = {};

    MAINLOOP_64COL(sAh, sAl, sBh, sBl, Ah, Al, Bh, Bl, row0, col0, acc);

    const int rl4 = lane >> 2, cl2 = (lane & 3)*2;
    const int part = col0 >> 10;
    const int h = (col0 >> 7) & 7;
    const int d0 = col0 & 127;

    if (part < 2) {
        __nv_bfloat16* dH = part ? g_knh : g_qnh;
        __nv_bfloat16* dL = part ? g_knl : g_qnl;
        #pragma unroll
        for (int mt = 0; mt < 2; mt++)
            #pragma unroll
            for (int h2 = 0; h2 < 2; h2++) {
                int gr = row0 + wm*32 + mt*16 + rl4 + h2*8;
                int b = gr >> 11, s = gr & 2047;
                size_t base = ((size_t)(b*HH + h)*SS + s)*DHD + d0;
                #pragma unroll
                for (int nt = 0; nt < 4; nt++) {
                    float v0 = acc[mt][nt][h2*2]   * NORMC;
                    float v1 = acc[mt][nt][h2*2+1] * NORMC;
                    __nv_bfloat16 h0,l0,h1,l1;
                    split_bf16(v0,h0,l0); split_bf16(v1,h1,l1);
                    __nv_bfloat162 hp, lp;
                    hp.x = h0; hp.y = h1; lp.x = l0; lp.y = l1;
                    *(__nv_bfloat162*)(dH + base + wn*32 + nt*8 + cl2) = hp;
                    *(__nv_bfloat162*)(dL + base + wn*32 + nt*8 + cl2) = lp;
                }
            }
    } else {
        #pragma unroll
        for (int mt = 0; mt < 2; mt++)
            #pragma unroll
            for (int h2 = 0; h2 < 2; h2++) {
                int gr = row0 + wm*32 + mt*16 + rl4 + h2*8;
                size_t base = (size_t)gr*INNER + h*DHD + d0;
                #pragma unroll
                for (int nt = 0; nt < 4; nt++) {
                    __nv_bfloat16 h0,l0,h1,l1;
                    split_bf16(acc[mt][nt][h2*2],   h0, l0);
                    split_bf16(acc[mt][nt][h2*2+1], h1, l1);
                    __nv_bfloat162 hp, lp;
                    hp.x = h0; hp.y = h1; lp.x = l0; lp.y = l1;
                    *(__nv_bfloat162*)(g_vh + base + wn*32 + nt*8 + cl2) = hp;
                    *(__nv_bfloat162*)(g_vl + base + wn*32 + nt*8 + cl2) = lp;
                }
            }
    }
}

// FF1: grid (8, 64); gelu epilogue -> fh/fl
__global__ __launch_bounds__(256) void k_ff1(
    const __nv_bfloat16* __restrict__ Ah, const __nv_bfloat16* __restrict__ Al,
    const __nv_bfloat16* __restrict__ Bh, const __nv_bfloat16* __restrict__ Bl,
    const float* __restrict__ bias)
{
    extern __shared__ __align__(16) char dsm[];
    __nv_bfloat16* sAh = (__nv_bfloat16*)dsm;
    __nv_bfloat16* sAl = sAh + 128*KP;
    __nv_bfloat16* sBh = sAl + 128*KP;
    __nv_bfloat16* sBl = sBh + 64*KP;
    const int t = threadIdx.x, w = t >> 5, lane = t & 31;
    const int wm = w & 3, wn = w >> 2;
    const int row0 = blockIdx.y*128, col0 = blockIdx.x*64;
    const int lrow = (lane & 15), lcol8 = (lane >> 4)*8;
    float acc[2][4][4] = {};

    MAINLOOP_64COL(sAh, sAl, sBh, sBl, Ah, Al, Bh, Bl, row0, col0, acc);

    const int rl4 = lane >> 2, cl2 = (lane & 3)*2;
    #pragma unroll
    for (int mt = 0; mt < 2; mt++)
        #pragma unroll
        for (int h2 = 0; h2 < 2; h2++) {
            int gr = row0 + wm*32 + mt*16 + rl4 + h2*8;
            #pragma unroll
            for (int nt = 0; nt < 4; nt++) {
                int gc = col0 + wn*32 + nt*8 + cl2;
                float v0 = gelu(acc[mt][nt][h2*2]   + bias[gc]);
                float v1 = gelu(acc[mt][nt][h2*2+1] + bias[gc+1]);
                __nv_bfloat16 h0,l0,h1,l1;
                split_bf16(v0,h0,l0); split_bf16(v1,h1,l1);
                __nv_bfloat162 hp, lp;
                hp.x = h0; hp.y = h1; lp.x = l0; lp.y = l1;
                *(__nv_bfloat162*)(g_fh + (size_t)gr*FFD + gc) = hp;
                *(__nv_bfloat162*)(g_fl + (size_t)gr*FFD + gc) = lp;
            }
        }
}

// ============ HMMA GEMM 64x128 tile, double-buffered (WO/FF2 residual) ============
#define SROW 72
#define BUFSZ (384*SROW)
__global__ __launch_bounds__(256) void k_mma64(
    const __nv_bfloat16* __restrict__ Ah, const __nv_bfloat16* __restrict__ Al, int lda,
    const __nv_bfloat16* __restrict__ Bh, const __nv_bfloat16* __restrict__ Bl,
    int Ktot,
    const float* __restrict__ bias,
    float* __restrict__ out)
{
    extern __shared__ __align__(16) __nv_bfloat16 sb[];
    const int t = threadIdx.x, w = t >> 5, lane = t & 31;
    const int wm = w & 1, wn = w >> 1;
    const int row0 = blockIdx.y*64;
    float acc[2][4][4] = {};
    const int lrow = (lane & 15), lcol8 = (lane >> 4)*8;

    {
        #pragma unroll
        for (int i = 0; i < 2; i++) {
            int f = i*256 + t;
            int r = f >> 3, c8 = (f & 7) << 3;
            *(uint4*)(sb + r*SROW + c8)            = *(const uint4*)(Ah + (size_t)(row0+r)*lda + c8);
            *(uint4*)(sb + 64*SROW + r*SROW + c8)  = *(const uint4*)(Al + (size_t)(row0+r)*lda + c8);
        }
        #pragma unroll
        for (int i = 0; i < 4; i++) {
            int f = i*256 + t;
            int r = f >> 3, c8 = (f & 7) << 3;
            *(uint4*)(sb + 128*SROW + r*SROW + c8) = *(const uint4*)(Bh + (size_t)r*Ktot + c8);
            *(uint4*)(sb + 256*SROW + r*SROW + c8) = *(const uint4*)(Bl + (size_t)r*Ktot + c8);
        }
    }
    __syncthreads();
    int buf = 0;

    for (int kc = 64; kc <= Ktot; kc += 64) {
        uint4 ra[2][2], rb[2][4];
        if (kc < Ktot) {
            #pragma unroll
            for (int i = 0; i < 2; i++) {
                int f = i*256 + t;
                int r = f >> 3, c8 = (f & 7) << 3;
                ra[0][i] = *(const uint4*)(Ah + (size_t)(row0+r)*lda + kc + c8);
                ra[1][i] = *(const uint4*)(Al + (size_t)(row0+r)*lda + kc + c8);
            }
            #pragma unroll
            for (int i = 0; i < 4; i++) {
                int f = i*256 + t;
                int r = f >> 3, c8 = (f & 7) << 3;
                rb[0][i] = *(const uint4*)(Bh + (size_t)r*Ktot + kc + c8);
                rb[1][i] = *(const uint4*)(Bl + (size_t)r*Ktot + kc + c8);
            }
        }
        const __nv_bfloat16* cb = sb + buf*BUFSZ;
        #pragma unroll
        for (int ks = 0; ks < 4; ks++) {
            int kcol = ks*16 + lcol8;
            uint32_t ah[2][4], al[2][4];
            #pragma unroll
            for (int mt = 0; mt < 2; mt++) {
                int arow = wm*32 + mt*16 + lrow;
                ldsm4(ah[mt], s2u(cb + arow*SROW + kcol));
                ldsm4(al[mt], s2u(cb + 64*SROW + arow*SROW + kcol));
            }
            #pragma unroll
            for (int nt2 = 0; nt2 < 2; nt2++) {
                int brow = wn*32 + nt2*16 + lrow;
                uint32_t rh[4], rl[4];
                ldsm4(rh, s2u(cb + 128*SROW + brow*SROW + kcol));
                ldsm4(rl, s2u(cb + 256*SROW + brow*SROW + kcol));
                uint32_t b0h[2] = {rh[0], rh[2]}, b1h[2] = {rh[1], rh[3]};
                uint32_t b0l[2] = {rl[0], rl[2]}, b1l[2] = {rl[1], rl[3]};
                #pragma unroll
                for (int mt = 0; mt < 2; mt++)
                    MMA3x2(acc[mt][nt2*2], acc[mt][nt2*2+1], ah[mt], al[mt], b0h, b0l, b1h, b1l);
            }
        }
        if (kc < Ktot) {
            __nv_bfloat16* nb = sb + (buf^1)*BUFSZ;
            #pragma unroll
            for (int i = 0; i < 2; i++) {
                int f = i*256 + t;
                int r = f >> 3, c8 = (f & 7) << 3;
                *(uint4*)(nb + r*SROW + c8)           = ra[0][i];
                *(uint4*)(nb + 64*SROW + r*SROW + c8) = ra[1][i];
            }
            #pragma unroll
            for (int i = 0; i < 4; i++) {
                int f = i*256 + t;
                int r = f >> 3, c8 = (f & 7) << 3;
                *(uint4*)(nb + 128*SROW + r*SROW + c8) = rb[0][i];
                *(uint4*)(nb + 256*SROW + r*SROW + c8) = rb[1][i];
            }
            __syncthreads();
            buf ^= 1;
        }
    }

    const int rl4 = lane >> 2, cl2 = (lane & 3)*2;
    #pragma unroll
    for (int mt = 0; mt < 2; mt++)
        #pragma unroll
        for (int h2 = 0; h2 < 2; h2++) {
            int gr = row0 + wm*32 + mt*16 + rl4 + h2*8;
            #pragma unroll
            for (int nt = 0; nt < 4; nt++) {
                int gc = wn*32 + nt*8 + cl2;
                size_t idx = (size_t)gr*DIMC + gc;
                float2 v = *(float2*)(out + idx);
                v.x += acc[mt][nt][h2*2]   + bias[gc];
                v.y += acc[mt][nt][h2*2+1] + bias[gc+1];
                *(float2*)(out + idx) = v;
            }
        }
}

// ---------------- embed ----------------
__global__ void k_embed(const float* __restrict__ x, const float* __restrict__ lw,
                        const float* __restrict__ lb, const float* __restrict__ pe)
{
    int warp = threadIdx.x >> 5, lane = threadIdx.x & 31;
    int r = blockIdx.x*8 + warp;
    float xv = x[r];
    float4 l4 = ((const float4*)lw)[lane];
    float4 b4 = ((const float4*)lb)[lane];
    float4 p4 = ((const float4*)(pe + (size_t)(r % SS)*DIMC))[lane];
    float4 o4 = { xv*l4.x + b4.x + p4.x, xv*l4.y + b4.y + p4.y,
                  xv*l4.z + b4.z + p4.z, xv*l4.w + b4.w + p4.w };
    ((float4*)(g_h + (size_t)r*DIMC))[lane] = o4;
}

// ---------------- layernorm -> bf16 hi/lo ----------------
__global__ void k_ln(const float* __restrict__ in, const float* __restrict__ g,
                     const float* __restrict__ b,
                     __nv_bfloat16* __restrict__ outH, __nv_bfloat16* __restrict__ outL)
{
    int warp = threadIdx.x >> 5, lane = threadIdx.x & 31;
    int r = blockIdx.x*8 + warp;
    float4 v = ((const float4*)(in + (size_t)r*DIMC))[lane];
    float s = v.x + v.y + v.z + v.w;
    #pragma unroll
    for (int o = 16; o > 0; o >>= 1) s += __shfl_xor_sync(0xffffffffu, s, o);
    float mu = s * (1.0f/DIMC);
    float dx = v.x-mu, dy = v.y-mu, dz = v.z-mu, dw = v.w-mu;
    float q = dx*dx + dy*dy + dz*dz + dw*dw;
    #pragma unroll
    for (int o = 16; o > 0; o >>= 1) q += __shfl_xor_sync(0xffffffffu, q, o);
    float inv = rsqrtf(q*(1.0f/DIMC) + 1e-5f);
    float4 gv = ((const float4*)g)[lane];
    float4 bv = ((const float4*)b)[lane];
    float o4[4] = { dx*inv*gv.x + bv.x, dy*inv*gv.y + bv.y,
                    dz*inv*gv.z + bv.z, dw*inv*gv.w + bv.w };
    __nv_bfloat16 hh[4], ll[4];
    #pragma unroll
    for (int j = 0; j < 4; j++) split_bf16(o4[j], hh[j], ll[j]);
    size_t base = (size_t)r*DIMC + lane*4;
    *(uint2*)(outH+base) = *(uint2*)hh;
    *(uint2*)(outL+base) = *(uint2*)ll;
}

// -------- weight transpose+split --------
__global__ __launch_bounds__(256) void k_wt(const float* __restrict__ W,
                                            __nv_bfloat16* __restrict__ outH,
                                            __nv_bfloat16* __restrict__ outL, int K, int N)
{
    __shared__ float tile[32][33];
    int n0 = blockIdx.x*32, k0 = blockIdx.y*32;
    int tx = threadIdx.x & 31, ty = threadIdx.x >> 5;
    #pragma unroll
    for (int i = ty; i < 32; i += 8)
        tile[i][tx] = W[(size_t)(k0+i)*N + n0 + tx];
    __syncthreads();
    #pragma unroll
    for (int i = ty; i < 32; i += 8) {
        float v = tile[tx][i];
        __nv_bfloat16 hh, ll;
        split_bf16(v, hh, ll);
        outH[(size_t)(n0+i)*K + k0 + tx] = hh;
        outL[(size_t)(n0+i)*K + k0 + tx] = ll;
    }
}

// ---------------- plain split (proj) ----------------
__global__ void k_cvt(const float* __restrict__ in, __nv_bfloat16* __restrict__ outH,
                      __nv_bfloat16* __restrict__ outL, int n4)
{
    int i = blockIdx.x*256 + threadIdx.x;
    if (i >= n4) return;
    float4 v = ((const float4*)in)[i];
    __nv_bfloat16 hh[4], ll[4];
    split_bf16(v.x, hh[0], ll[0]); split_bf16(v.y, hh[1], ll[1]);
    split_bf16(v.z, hh[2], ll[2]); split_bf16(v.w, hh[3], ll[3]);
    *(uint2*)(outH + i*4) = *(uint2*)hh;
    *(uint2*)(outL + i*4) = *(uint2*)ll;
}

// ================= chunk-local attention via HMMA, 512 threads =================
// exp of K features fused into the smem fill (reads dd fp32 + diag + bmax)
#define CP 136
__global__ __launch_bounds__(512) void k_chunk(
    const __nv_bfloat16* __restrict__ qph, const __nv_bfloat16* __restrict__ qpl)
{
    extern __shared__ __align__(16) __nv_bfloat16 cs[];
    __nv_bfloat16* sQh = cs;                    // [i][m]; later attn [i][j]
    __nv_bfloat16* sQl = sQh + 128*CP;
    __nv_bfloat16* sKh = sQl + 128*CP;          // [j][m]
    __nv_bfloat16* sKl = sKh + 128*CP;
    __nv_bfloat16* sVh = sKl + 128*CP;          // [j][d]
    __nv_bfloat16* sVl = sVh + 128*CP;
    __shared__ float s_den[4][128];
    __shared__ float s_dg[128];

    int blk = blockIdx.x, bh = blk >> 4, c = blk & 15;
    int b = bh >> 3, hh = bh & 7;
    int t = threadIdx.x, w = t >> 5, lane = t & 31;
    int wm = w & 3, wn = w >> 2;
    const int lrow = lane & 15, lcol8 = (lane >> 4)*8;
    const int rl4 = lane >> 2, cl2 = (lane & 3)*2;

    const size_t qbase = ((size_t)bh*SS + c*CHUNK)*MF;
    if (t < 128) {
        float st = g_bmax[bh*16];
        #pragma unroll
        for (int i = 1; i < 16; i++) st = fmaxf(st, g_bmax[bh*16 + i]);
        s_dg[t] = g_diagk[(size_t)bh*SS + c*CHUNK + t] + st;
    }
    for (int i = t; i < 2048; i += 512) {
        int r = i >> 4, c8 = (i & 15) << 3;
        *(uint4*)(sQh + r*CP + c8) = *(const uint4*)(qph + qbase + r*MF + c8);
        *(uint4*)(sQl + r*CP + c8) = *(const uint4*)(qpl + qbase + r*MF + c8);
        size_t vsrc = (size_t)(b*SS + c*CHUNK + r)*INNER + hh*DHD + c8;
        *(uint4*)(sVh + r*CP + c8) = *(const uint4*)(g_vh + vsrc);
        *(uint4*)(sVl + r*CP + c8) = *(const uint4*)(g_vl + vsrc);
    }
    __syncthreads();
    // K fill with fused exp
    for (int f = t; f < 4096; f += 512) {
        int r = f >> 5, c4 = (f & 31) << 2;
        float4 dv = *(const float4*)(g_kp + qbase + (size_t)r*MF + c4);
        float dgv = s_dg[r];
        float o0 = RATIOC*(expf(dv.x - dgv) + 1e-4f);
        float o1 = RATIOC*(expf(dv.y - dgv) + 1e-4f);
        float o2 = RATIOC*(expf(dv.z - dgv) + 1e-4f);
        float o3 = RATIOC*(expf(dv.w - dgv) + 1e-4f);
        __nv_bfloat16 hh4[4], ll4[4];
        split_bf16(o0, hh4[0], ll4[0]); split_bf16(o1, hh4[1], ll4[1]);
        split_bf16(o2, hh4[2], ll4[2]); split_bf16(o3, hh4[3], ll4[3]);
        *(uint2*)(sKh + r*CP + c4) = *(uint2*)hh4;
        *(uint2*)(sKl + r*CP + c4) = *(uint2*)ll4;
    }
    __syncthreads();

    // ---- phase 1: attn = Q@K^T ; warps fully above the diagonal skip MMA ----
    float acc[2][4][4] = {};
    if (wn <= wm) {
        #pragma unroll
        for (int ks = 0; ks < 8; ks++) {
            int kcol = ks*16 + lcol8;
            uint32_t ah[2][4], al[2][4];
            #pragma unroll
            for (int mt = 0; mt < 2; mt++) {
                int arow = wm*32 + mt*16 + lrow;
                ldsm4(ah[mt], s2u(sQh + arow*CP + kcol));
                ldsm4(al[mt], s2u(sQl + arow*CP + kcol));
            }
            #pragma unroll
            for (int nt2 = 0; nt2 < 2; nt2++) {
                int brow = wn*32 + nt2*16 + lrow;
                uint32_t rh[4], rl[4];
                ldsm4(rh, s2u(sKh + brow*CP + kcol));
                ldsm4(rl, s2u(sKl + brow*CP + kcol));
                uint32_t b0h[2] = {rh[0], rh[2]}, b1h[2] = {rh[1], rh[3]};
                uint32_t b0l[2] = {rl[0], rl[2]}, b1l[2] = {rl[1], rl[3]};
                #pragma unroll
                for (int mt = 0; mt < 2; mt++)
                    MMA3x2(acc[mt][nt2*2], acc[mt][nt2*2+1], ah[mt], al[mt], b0h, b0l, b1h, b1l);
            }
        }
    }
    // mask + den partials
    float dp[2][2] = {};
    #pragma unroll
    for (int mt = 0; mt < 2; mt++)
        #pragma unroll
        for (int nt = 0; nt < 4; nt++)
            #pragma unroll
            for (int f = 0; f < 4; f++) {
                int i = wm*32 + mt*16 + rl4 + ((f>>1)<<3);
                int j = wn*32 + nt*8 + cl2 + (f&1);
                if (j > i) acc[mt][nt][f] = 0.f;
                dp[mt][f>>1] += acc[mt][nt][f];
            }
    #pragma unroll
    for (int o = 1; o < 4; o <<= 1)
        #pragma unroll
        for (int mt = 0; mt < 2; mt++)
            #pragma unroll
            for (int h2 = 0; h2 < 2; h2++)
                dp[mt][h2] += __shfl_xor_sync(0xffffffffu, dp[mt][h2], o);
    if ((lane & 3) == 0) {
        #pragma unroll
        for (int mt = 0; mt < 2; mt++)
            #pragma unroll
            for (int h2 = 0; h2 < 2; h2++)
                s_den[wn][wm*32 + mt*16 + rl4 + h2*8] = dp[mt][h2];
    }
    __syncthreads();

    // overwrite sQ with masked attn (hi/lo)
    #pragma unroll
    for (int mt = 0; mt < 2; mt++)
        #pragma unroll
        for (int nt = 0; nt < 4; nt++)
            #pragma unroll
            for (int f = 0; f < 4; f++) {
                int i = wm*32 + mt*16 + rl4 + ((f>>1)<<3);
                int j = wn*32 + nt*8 + cl2 + (f&1);
                __nv_bfloat16 hh2, ll2;
                split_bf16(acc[mt][nt][f], hh2, ll2);
                sQh[i*CP + j] = hh2;
                sQl[i*CP + j] = ll2;
            }
    if (t < 128) {
        g_den[(size_t)bh*SS + c*CHUNK + t] = s_den[0][t] + s_den[1][t] + s_den[2][t] + s_den[3][t];
        float kssum = 0.f;
        for (int j = 0; j < 128; j++)
            kssum += __bfloat162float(sKh[j*CP + t]) + __bfloat162float(sKl[j*CP + t]);
        g_ksc[((size_t)bh*NC + c)*MF + t] = kssum;
    }
    __syncthreads();

    // ---- phase 2: num = attn @ V ----
    #pragma unroll
    for (int mt = 0; mt < 2; mt++)
        #pragma unroll
        for (int nt = 0; nt < 4; nt++)
            #pragma unroll
            for (int f = 0; f < 4; f++) acc[mt][nt][f] = 0.f;
    #pragma unroll
    for (int ks = 0; ks < 8; ks++) {
        int kcol = ks*16 + lcol8;
        uint32_t ah[2][4], al[2][4];
        #pragma unroll
        for (int mt = 0; mt < 2; mt++) {
            int arow = wm*32 + mt*16 + lrow;
            ldsm4(ah[mt], s2u(sQh + arow*CP + kcol));
            ldsm4(al[mt], s2u(sQl + arow*CP + kcol));
        }
        #pragma unroll
        for (int nt2 = 0; nt2 < 2; nt2++) {
            int nbase = wn*32 + nt2*16;
            uint32_t dh[4], dl[4];
            ldsm4t(dh, taddr(sVh, CP, ks*16, nbase, lane));
            ldsm4t(dl, taddr(sVl, CP, ks*16, nbase, lane));
            uint32_t b0h[2] = {dh[0], dh[2]}, b1h[2] = {dh[1], dh[3]};
            uint32_t b0l[2] = {dl[0], dl[2]}, b1l[2] = {dl[1], dl[3]};
            #pragma unroll
            for (int mt = 0; mt < 2; mt++)
                MMA3x2(acc[mt][nt2*2], acc[mt][nt2*2+1], ah[mt], al[mt], b0h, b0l, b1h, b1l);
        }
    }
    #pragma unroll
    for (int mt = 0; mt < 2; mt++)
        #pragma unroll
        for (int h2 = 0; h2 < 2; h2++) {
            int i = wm*32 + mt*16 + rl4 + h2*8;
            size_t base = ((size_t)(b*SS + c*CHUNK + i)*HH + hh)*DHD;
            #pragma unroll
            for (int nt = 0; nt < 4; nt++) {
                float2 vv = {acc[mt][nt][h2*2], acc[mt][nt][h2*2+1]};
                *(float2*)(g_o + base + wn*32 + nt*8 + cl2) = vv;
            }
        }

    // ---- phase 3: kv = K^T @ V ----
    #pragma unroll
    for (int mt = 0; mt < 2; mt++)
        #pragma unroll
        for (int nt = 0; nt < 4; nt++)
            #pragma unroll
            for (int f = 0; f < 4; f++) acc[mt][nt][f] = 0.f;
    #pragma unroll
    for (int ks = 0; ks < 8; ks++) {
        uint32_t ah[2][4], al[2][4];
        #pragma unroll
        for (int mt = 0; mt < 2; mt++) {
            int mbase = wm*32 + mt*16;
            ldsm4t(ah[mt], taddr(sKh, CP, ks*16, mbase, lane));
            ldsm4t(al[mt], taddr(sKl, CP, ks*16, mbase, lane));
        }
        #pragma unroll
        for (int nt2 = 0; nt2 < 2; nt2++) {
            int nbase = wn*32 + nt2*16;
            uint32_t dh[4], dl[4];
            ldsm4t(dh, taddr(sVh, CP, ks*16, nbase, lane));
            ldsm4t(dl, taddr(sVl, CP, ks*16, nbase, lane));
            uint32_t b0h[2] = {dh[0], dh[2]}, b1h[2] = {dh[1], dh[3]};
            uint32_t b0l[2] = {dl[0], dl[2]}, b1l[2] = {dl[1], dl[3]};
            #pragma unroll
            for (int mt = 0; mt < 2; mt++)
                MMA3x2(acc[mt][nt2*2], acc[mt][nt2*2+1], ah[mt], al[mt], b0h, b0l, b1h, b1l);
        }
    }
    {
        size_t kvbase = ((size_t)bh*NC + c)*(MF*DHD);
        #pragma unroll
        for (int mt = 0; mt < 2; mt++)
            #pragma unroll
            for (int h2 = 0; h2 < 2; h2++) {
                int m = wm*32 + mt*16 + rl4 + h2*8;
                #pragma unroll
                for (int nt = 0; nt < 4; nt++) {
                    float2 vv = {acc[mt][nt][h2*2], acc[mt][nt][h2*2+1]};
                    *(float2*)(g_kvc + kvbase + (size_t)m*DHD + wn*32 + nt*8 + cl2) = vv;
                }
            }
    }
}

// ---------------- exclusive prefix over chunks (emits bf16 hi/lo) ----------------
__global__ void k_prefix()
{
    int bh = blockIdx.x, seg = blockIdx.y, t = threadIdx.x;
    for (int e = seg*2048 + t; e < (seg+1)*2048; e += 256) {
        float run = 0.f;
        #pragma unroll
        for (int c = 0; c < NC; c++) {
            size_t idx = ((size_t)bh*NC + c)*(MF*DHD) + e;
            __nv_bfloat16 hh, ll;
            split_bf16(run, hh, ll);
            g_kvph[idx] = hh; g_kvpl[idx] = ll;
            run += g_kvc[idx];
        }
    }
    if (seg == 0) {
        for (int e = t; e < MF; e += 256) {
            float run = 0.f;
            #pragma unroll
            for (int c = 0; c < NC; c++) {
                size_t idx = ((size_t)bh*NC + c)*MF + e;
                g_ksp[idx] = run; run += g_ksc[idx];
            }
        }
    }
}

// ========== cross = qp @ kvp, + num, normalize -> oh/ol (HMMA, 512 thr) ==========
__global__ __launch_bounds__(512) void k_cross(
    const __nv_bfloat16* __restrict__ qph, const __nv_bfloat16* __restrict__ qpl)
{
    extern __shared__ __align__(16) __nv_bfloat16 cs[];
    __nv_bfloat16* sQh = cs;
    __nv_bfloat16* sQl = sQh + 128*CP;
    __nv_bfloat16* sPh = sQl + 128*CP;
    __nv_bfloat16* sPl = sPh + 128*CP;
    __shared__ float s_ks[128];
    __shared__ float s_dc[128];

    int blk = blockIdx.x, bh = blk >> 4, c = blk & 15;
    int b = bh >> 3, hh = bh & 7;
    int t = threadIdx.x, w = t >> 5, lane = t & 31;
    int wm = w & 3, wn = w >> 2;
    const int lrow = lane & 15, lcol8 = (lane >> 4)*8;
    const int rl4 = lane >> 2, cl2 = (lane & 3)*2;

    const size_t qbase = ((size_t)bh*SS + c*CHUNK)*MF;
    const size_t pbase = ((size_t)bh*NC + c)*(MF*DHD);
    for (int i = t; i < 2048; i += 512) {
        int r = i >> 4, c8 = (i & 15) << 3;
        *(uint4*)(sQh + r*CP + c8) = *(const uint4*)(qph + qbase + r*MF + c8);
        *(uint4*)(sQl + r*CP + c8) = *(const uint4*)(qpl + qbase + r*MF + c8);
        *(uint4*)(sPh + r*CP + c8) = *(const uint4*)(g_kvph + pbase + r*DHD + c8);
        *(uint4*)(sPl + r*CP + c8) = *(const uint4*)(g_kvpl + pbase + r*DHD + c8);
    }
    if (t < 128) s_ks[t] = g_ksp[((size_t)bh*NC + c)*MF + t];
    __syncthreads();
    if (t < 128) {
        float dc = 0.f;
        for (int m = 0; m < 128; m++)
            dc += (__bfloat162float(sQh[t*CP + m]) + __bfloat162float(sQl[t*CP + m]))*s_ks[m];
        s_dc[t] = g_den[(size_t)bh*SS + c*CHUNK + t] + dc + 1e-6f;
    }
    __syncthreads();

    float acc[2][4][4] = {};
    #pragma unroll
    for (int ks = 0; ks < 8; ks++) {
        int kcol = ks*16 + lcol8;
        uint32_t ah[2][4], al[2][4];
        #pragma unroll
        for (int mt = 0; mt < 2; mt++) {
            int arow = wm*32 + mt*16 + lrow;
            ldsm4(ah[mt], s2u(sQh + arow*CP + kcol));
            ldsm4(al[mt], s2u(sQl + arow*CP + kcol));
        }
        #pragma unroll
        for (int nt2 = 0; nt2 < 2; nt2++) {
            int nbase = wn*32 + nt2*16;
            uint32_t dh[4], dl[4];
            ldsm4t(dh, taddr(sPh, CP, ks*16, nbase, lane));
            ldsm4t(dl, taddr(sPl, CP, ks*16, nbase, lane));
            uint32_t b0h[2] = {dh[0], dh[2]}, b1h[2] = {dh[1], dh[3]};
            uint32_t b0l[2] = {dl[0], dl[2]}, b1l[2] = {dl[1], dl[3]};
            #pragma unroll
            for (int mt = 0; mt < 2; mt++)
                MMA3x2(acc[mt][nt2*2], acc[mt][nt2*2+1], ah[mt], al[mt], b0h, b0l, b1h, b1l);
        }
    }
    #pragma unroll
    for (int mt = 0; mt < 2; mt++)
        #pragma unroll
        for (int h2 = 0; h2 < 2; h2++) {
            int i = wm*32 + mt*16 + rl4 + h2*8;
            float inv = 1.0f / s_dc[i];
            size_t base = ((size_t)(b*SS + c*CHUNK + i)*HH + hh)*DHD;
            #pragma unroll
            for (int nt = 0; nt < 4; nt++) {
                size_t idx = base + wn*32 + nt*8 + cl2;
                float2 nn = *(float2*)(g_o + idx);
                float v0 = (nn.x + acc[mt][nt][h2*2])   * inv;
                float v1 = (nn.y + acc[mt][nt][h2*2+1]) * inv;
                __nv_bfloat16 h0,l0,h1,l1;
                split_bf16(v0,h0,l0); split_bf16(v1,h1,l1);
                __nv_bfloat162 hp, lp;
                hp.x = h0; hp.y = h1; lp.x = l0; lp.y = l1;
                *(__nv_bfloat162*)(g_oh + idx) = hp;
                *(__nv_bfloat162*)(g_ol + idx) = lp;
            }
        }
}

// ---------------- pooling ----------------
__global__ void k_pool()
{
    int b = blockIdx.x, seg = blockIdx.y, t = threadIdx.x;
    float acc = 0.f;
    for (int s = seg*128; s < (seg+1)*128; s++) acc += g_h[((size_t)b*SS + s)*DIMC + t];
    g_pp[(b*16 + seg)*DIMC + t] = acc;
}

__global__ void k_final(const float* __restrict__ fw, const float* __restrict__ fb,
                        float* __restrict__ out)
{
    __shared__ float pooled[BB*DIMC];
    int t = threadIdx.x;
    for (int b = 0; b < BB; b++) {
        float a = 0.f;
        #pragma unroll
        for (int s = 0; s < 16; s++) a += g_pp[(b*16 + s)*DIMC + t];
        pooled[b*DIMC + t] = a * (1.0f/SS);
    }
    __syncthreads();
    if (t < BB*NCLS) {
        int b = t / NCLS, c = t % NCLS;
        float acc = fb[c];
        for (int d = 0; d < DIMC; d++) acc += pooled[b*DIMC + d]*fw[d*NCLS + c];
        out[t] = acc;
    }
}

// ---------------- host driver ----------------
static void* sym(const void* s) { void* p = nullptr; cudaGetSymbolAddress(&p, s); return p; }

extern "C" void kernel_launch(void* const* d_in, const int* in_sizes, int n_in,
                              void* d_out, int out_size)
{
    const float* x     = (const float*)d_in[0];
    const float* lin_w = (const float*)d_in[1];
    const float* lin_b = (const float*)d_in[2];
    const float* pe    = (const float*)d_in[3];
    const float* proj  = (const float*)d_in[4];
    const float* ln1_g = (const float*)d_in[5];
    const float* ln1_b = (const float*)d_in[6];
    const float* wq    = (const float*)d_in[7];
    const float* wk    = (const float*)d_in[8];
    const float* wv    = (const float*)d_in[9];
    const float* wo    = (const float*)d_in[10];
    const float* wo_b  = (const float*)d_in[11];
    const float* ln2_g = (const float*)d_in[12];
    const float* ln2_b = (const float*)d_in[13];
    const float* ff1_w = (const float*)d_in[14];
    const float* ff1_b = (const float*)d_in[15];
    const float* ff2_w = (const float*)d_in[16];
    const float* ff2_b = (const float*)d_in[17];
    const float* fin_w = (const float*)d_in[18];
    const float* fin_b = (const float*)d_in[19];
    float* out = (float*)d_out;

    float* ph   = (float*)sym(g_h);
    float* pkp  = (float*)sym(g_kp);
    float* pbm  = (float*)sym(g_bmax);

    __nv_bfloat16* yh  = (__nv_bfloat16*)sym(g_yh);
    __nv_bfloat16* yl  = (__nv_bfloat16*)sym(g_yl);
    __nv_bfloat16* wth = (__nv_bfloat16*)sym(g_wth);
    __nv_bfloat16* wtl = (__nv_bfloat16*)sym(g_wtl);
    __nv_bfloat16* qnh = (__nv_bfloat16*)sym(g_qnh);
    __nv_bfloat16* qnl = (__nv_bfloat16*)sym(g_qnl);
    __nv_bfloat16* knh = (__nv_bfloat16*)sym(g_knh);
    __nv_bfloat16* knl = (__nv_bfloat16*)sym(g_knl);
    __nv_bfloat16* qp_h = (__nv_bfloat16*)sym(g_qph);
    __nv_bfloat16* qp_l = (__nv_bfloat16*)sym(g_qpl);
    __nv_bfloat16* oh  = (__nv_bfloat16*)sym(g_oh);
    __nv_bfloat16* ol  = (__nv_bfloat16*)sym(g_ol);
    __nv_bfloat16* fh  = (__nv_bfloat16*)sym(g_fh);
    __nv_bfloat16* fl  = (__nv_bfloat16*)sym(g_fl);

    const int SMEM_MMA   = 4*128*KP*2;           // 139264 (features)
    const int SMEM_QKVFF = QKV_SMEM;             // 104448 (2 CTAs/SM)
    const int SMEM_MMA64 = 2*BUFSZ*2;            // 110592
    const int SMEM_CHUNK = 6*128*CP*2;           // 208896
    const int SMEM_CROSS = 4*128*CP*2;           // 139264
    cudaFuncSetAttribute(k_mmaF<3>, cudaFuncAttributeMaxDynamicSharedMemorySize, SMEM_MMA);
    cudaFuncSetAttribute(k_mmaF<4>, cudaFuncAttributeMaxDynamicSharedMemorySize, SMEM_MMA);
    cudaFuncSetAttribute(k_mmaqkv64, cudaFuncAttributeMaxDynamicSharedMemorySize, SMEM_QKVFF);
    cudaFuncSetAttribute(k_ff1, cudaFuncAttributeMaxDynamicSharedMemorySize, SMEM_QKVFF);
    cudaFuncSetAttribute(k_mma64, cudaFuncAttributeMaxDynamicSharedMemorySize, SMEM_MMA64);
    cudaFuncSetAttribute(k_chunk, cudaFuncAttributeMaxDynamicSharedMemorySize, SMEM_CHUNK);
    cudaFuncSetAttribute(k_cross, cudaFuncAttributeMaxDynamicSharedMemorySize, SMEM_CROSS);

    k_embed<<<BSR/8, 256>>>(x, lin_w, lin_b, pe);

    for (int l = 0; l < DEPTH; l++) {
        size_t wb = (size_t)l*WT_LAYER;
        k_wt<<<dim3(INNER/32, DIMC/32), 256>>>(wq + (size_t)l*DIMC*INNER, wth+wb+WT_Q, wtl+wb+WT_Q, DIMC, INNER);
        k_wt<<<dim3(INNER/32, DIMC/32), 256>>>(wk + (size_t)l*DIMC*INNER, wth+wb+WT_K, wtl+wb+WT_K, DIMC, INNER);
        k_wt<<<dim3(INNER/32, DIMC/32), 256>>>(wv + (size_t)l*DIMC*INNER, wth+wb+WT_V, wtl+wb+WT_V, DIMC, INNER);
        k_wt<<<dim3(DIMC/32, INNER/32), 256>>>(wo + (size_t)l*INNER*DIMC, wth+wb+WT_O, wtl+wb+WT_O, INNER, DIMC);
        k_wt<<<dim3(FFD/32, DIMC/32), 256>>>(ff1_w + (size_t)l*DIMC*FFD, wth+wb+WT_F1, wtl+wb+WT_F1, DIMC, FFD);
        k_wt<<<dim3(DIMC/32, FFD/32), 256>>>(ff2_w + (size_t)l*FFD*DIMC, wth+wb+WT_F2, wtl+wb+WT_F2, FFD, DIMC);
        k_cvt<<<16, 256>>>(proj + (size_t)l*MF*DHD, wth+wb+WT_PJ, wtl+wb+WT_PJ, MF*DHD/4);
    }

    for (int l = 0; l < DEPTH; l++) {
        size_t wb = (size_t)l*WT_LAYER;

        k_ln<<<BSR/8, 256>>>(ph, ln1_g + l*DIMC, ln1_b + l*DIMC, yh, yl);

        // fused QKV, 128x64 tiles (2 CTAs/SM)
        k_mmaqkv64<<<dim3(48,64), 256, SMEM_QKVFF>>>(yh, yl, wth+wb+WT_Q, wtl+wb+WT_Q);

        // K features: dd + blockmax + diag; Q features: fully fused exp
        k_mmaF<4><<<dim3(1,512), 256, SMEM_MMA>>>(knh, knl, wth+wb+WT_PJ, wtl+wb+WT_PJ,
                                                  pkp, nullptr, nullptr, pbm);
        k_mmaF<3><<<dim3(1,512), 256, SMEM_MMA>>>(qnh, qnl, wth+wb+WT_PJ, wtl+wb+WT_PJ,
                                                  nullptr, qp_h, qp_l, nullptr);

        // chunked causal linear attention (K exp fused into chunk)
        k_chunk<<<NBH*NC, 512, SMEM_CHUNK>>>(qp_h, qp_l);
        k_prefix<<<dim3(NBH, 8), 256>>>();
        k_cross<<<NBH*NC, 512, SMEM_CROSS>>>(qp_h, qp_l);

        k_mma64<<<dim3(1,BSR/64), 256, SMEM_MMA64>>>(oh, ol, INNER, wth+wb+WT_O, wtl+wb+WT_O, INNER,
                                                     wo_b + l*DIMC, ph);

        k_ln<<<BSR/8, 256>>>(ph, ln2_g + l*DIMC, ln2_b + l*DIMC, yh, yl);
        k_ff1<<<dim3(8,64), 256, SMEM_QKVFF>>>(yh, yl, wth+wb+WT_F1, wtl+wb+WT_F1, ff1_b + l*FFD);
        k_mma64<<<dim3(1,BSR/64), 256, SMEM_MMA64>>>(fh, fl, FFD, wth+wb+WT_F2, wtl+wb+WT_F2, FFD,
                                                     ff2_b + l*DIMC, ph);
    }

    k_pool<<<dim3(BB, 16), 128>>>();
    k_final<<<1, 128>>>(fin_w, fin_b, out);
}

// round 10
// speedup vs baseline: 2.3291x; 1.0430x over previous
#include <cuda_runtime.h>
#include <cuda_bf16.h>
#include <math.h>
#include <stdint.h>

// ---------------- problem constants ----------------
#define BB 4
#define SS 2048
#define DIMC 128
#define HH 8
#define DHD 128
#define DEPTH 2
#define NCLS 10
#define MF 128
#define CHUNK 128
#define NC 16
#define INNER 1024
#define FFD 512
#define BSR 8192
#define BHS 65536
#define NBH 32

#define NORMC 0.29730177875068026f
#define RATIOC 0.08838834764831845f

// ---------------- device scratch (fp32) ----------------
__device__ float g_h  [BSR*DIMC];
__device__ float g_kp [(size_t)NBH*SS*MF];
__device__ float g_diagk[BHS];
__device__ float g_bmax[NBH*16];
__device__ float g_o  [BSR*INNER];
__device__ float g_den[BHS];
__device__ float g_kvc[(size_t)NBH*NC*MF*DHD];
__device__ float g_ksc[NBH*NC*MF];
__device__ float g_ksp[NBH*NC*MF];
__device__ float g_pp [BB*16*DIMC];

// ---------------- device scratch (bf16 hi/lo) ----------------
__device__ __align__(256) __nv_bfloat16 g_yh [BSR*DIMC];
__device__ __align__(256) __nv_bfloat16 g_yl [BSR*DIMC];
__device__ __align__(256) __nv_bfloat16 g_wth[2*672000];
__device__ __align__(256) __nv_bfloat16 g_wtl[2*672000];
__device__ __align__(256) __nv_bfloat16 g_qnh[(size_t)BHS*DHD];
__device__ __align__(256) __nv_bfloat16 g_qnl[(size_t)BHS*DHD];
__device__ __align__(256) __nv_bfloat16 g_knh[(size_t)BHS*DHD];
__device__ __align__(256) __nv_bfloat16 g_knl[(size_t)BHS*DHD];
__device__ __align__(256) __nv_bfloat16 g_vh [(size_t)BSR*INNER];
__device__ __align__(256) __nv_bfloat16 g_vl [(size_t)BSR*INNER];
__device__ __align__(256) __nv_bfloat16 g_qph[(size_t)NBH*SS*MF];
__device__ __align__(256) __nv_bfloat16 g_qpl[(size_t)NBH*SS*MF];
__device__ __align__(256) __nv_bfloat16 g_kvph[(size_t)NBH*NC*MF*DHD];
__device__ __align__(256) __nv_bfloat16 g_kvpl[(size_t)NBH*NC*MF*DHD];
__device__ __align__(256) __nv_bfloat16 g_oh [(size_t)BSR*INNER];
__device__ __align__(256) __nv_bfloat16 g_ol [(size_t)BSR*INNER];
__device__ __align__(256) __nv_bfloat16 g_fh [(size_t)BSR*FFD];
__device__ __align__(256) __nv_bfloat16 g_fl [(size_t)BSR*FFD];

#define WT_Q  0
#define WT_K  131072
#define WT_V  262144
#define WT_O  393216
#define WT_F1 524288
#define WT_F2 589824
#define WT_PJ 655360
#define WT_LAYER 672000

// ---------------- warp MMA helpers ----------------
__device__ __forceinline__ uint32_t s2u(const void* p){
    uint32_t a;
    asm("{ .reg .u64 t; cvta.to.shared.u64 t, %1; cvt.u32.u64 %0, t; }" : "=r"(a) : "l"(p));
    return a;
}
__device__ __forceinline__ void ldsm4(uint32_t* r, uint32_t addr){
    asm volatile("ldmatrix.sync.aligned.m8n8.x4.shared.b16 {%0,%1,%2,%3}, [%4];"
                 : "=r"(r[0]),"=r"(r[1]),"=r"(r[2]),"=r"(r[3]) : "r"(addr));
}
__device__ __forceinline__ void ldsm4t(uint32_t* r, uint32_t addr){
    asm volatile("ldmatrix.sync.aligned.m8n8.x4.trans.shared.b16 {%0,%1,%2,%3}, [%4];"
                 : "=r"(r[0]),"=r"(r[1]),"=r"(r[2]),"=r"(r[3]) : "r"(addr));
}
__device__ __forceinline__ void mma_bf16(float* c, const uint32_t* a, const uint32_t* b){
    asm volatile("mma.sync.aligned.m16n8k16.row.col.f32.bf16.bf16.f32 "
                 "{%0,%1,%2,%3}, {%4,%5,%6,%7}, {%8,%9}, {%0,%1,%2,%3};"
                 : "+f"(c[0]),"+f"(c[1]),"+f"(c[2]),"+f"(c[3])
                 : "r"(a[0]),"r"(a[1]),"r"(a[2]),"r"(a[3]), "r"(b[0]),"r"(b[1]));
}
__device__ __forceinline__ void split_bf16(float v, __nv_bfloat16& h, __nv_bfloat16& l){
    h = __float2bfloat16(v);
    l = __float2bfloat16(v - __bfloat162float(h));
}
__device__ __forceinline__ float gelu(float xx){
    return 0.5f*xx*(1.0f + tanhf(0.7978845608028654f*(xx + 0.044715f*xx*xx*xx)));
}
__device__ __forceinline__ uint32_t taddr(const __nv_bfloat16* S, int P, int kbase, int nbase, int lane){
    int kk = (lane & 7) + ((lane >> 4) << 3);
    int nn = ((lane >> 3) & 1) << 3;
    return s2u(S + (size_t)(kbase + kk)*P + nbase + nn);
}
#define MMA3x2(accA, accB, ah_, al_, b0h_, b0l_, b1h_, b1l_) \
    do { mma_bf16(accA, ah_, b0h_); mma_bf16(accA, ah_, b0l_); mma_bf16(accA, al_, b0h_); \
         mma_bf16(accB, ah_, b1h_); mma_bf16(accB, ah_, b1l_); mma_bf16(accB, al_, b1h_); } while(0)

#define KP 136

// ======== merged feature GEMM: blockIdx.x==0 -> K features (dd+bmax+diag),
//          blockIdx.x==1 -> Q features (exp fused -> qp hi/lo) ========
__global__ __launch_bounds__(256) void k_mmaF(
    const __nv_bfloat16* __restrict__ Kh, const __nv_bfloat16* __restrict__ Kl,
    const __nv_bfloat16* __restrict__ Qh, const __nv_bfloat16* __restrict__ Ql,
    const __nv_bfloat16* __restrict__ Bh, const __nv_bfloat16* __restrict__ Bl,
    float* __restrict__ out,
    __nv_bfloat16* __restrict__ outH, __nv_bfloat16* __restrict__ outL,
    float* __restrict__ bmax)
{
    extern __shared__ __align__(16) char dsm[];
    __nv_bfloat16* sAh = (__nv_bfloat16*)dsm;
    __nv_bfloat16* sAl = sAh + 128*KP;
    __nv_bfloat16* sBh = sAl + 128*KP;
    __nv_bfloat16* sBl = sBh + 128*KP;
    __shared__ float s_rm[2][128];
    __shared__ float s_red[256];
    __shared__ float s_dg[128];

    const int MODE = (blockIdx.x == 0) ? 4 : 3;
    const __nv_bfloat16* Ah = (MODE == 4) ? Kh : Qh;
    const __nv_bfloat16* Al = (MODE == 4) ? Kl : Ql;

    const int t = threadIdx.x, w = t >> 5, lane = t & 31;
    const int wm = w & 3, wn = w >> 2;
    const int row0 = blockIdx.y*128;

    float acc[2][8][4] = {};
    const int lrow = (lane & 15), lcol8 = (lane >> 4)*8;

    #pragma unroll
    for (int i = 0; i < 8; i++) {
        int f = i*256 + t;
        int r = f >> 4, c8 = (f & 15) << 3;
        *(uint4*)(sAh + r*KP + c8) = *(const uint4*)(Ah + (size_t)(row0+r)*128 + c8);
        *(uint4*)(sAl + r*KP + c8) = *(const uint4*)(Al + (size_t)(row0+r)*128 + c8);
        *(uint4*)(sBh + r*KP + c8) = *(const uint4*)(Bh + (size_t)r*128 + c8);
        *(uint4*)(sBl + r*KP + c8) = *(const uint4*)(Bl + (size_t)r*128 + c8);
    }
    __syncthreads();

    if (t < 128) {
        float dacc = 0.f;
        #pragma unroll
        for (int k8 = 0; k8 < 16; k8++) {
            uint4 uh = *(uint4*)(sAh + t*KP + k8*8);
            uint4 ul = *(uint4*)(sAl + t*KP + k8*8);
            const __nv_bfloat16* ph = (const __nv_bfloat16*)&uh;
            const __nv_bfloat16* pl = (const __nv_bfloat16*)&ul;
            #pragma unroll
            for (int j = 0; j < 8; j++) {
                float av = __bfloat162float(ph[j]) + __bfloat162float(pl[j]);
                dacc += av*av;
            }
        }
        if (MODE == 4) g_diagk[row0 + t] = 0.5f*dacc;
        else           s_dg[t] = 0.5f*dacc;
    }

    #pragma unroll
    for (int ks = 0; ks < 8; ks++) {
        int kcol = ks*16 + lcol8;
        uint32_t ah[2][4], al[2][4];
        #pragma unroll
        for (int mt = 0; mt < 2; mt++) {
            int arow = wm*32 + mt*16 + lrow;
            ldsm4(ah[mt], s2u(sAh + arow*KP + kcol));
            ldsm4(al[mt], s2u(sAl + arow*KP + kcol));
        }
        #pragma unroll
        for (int nt2 = 0; nt2 < 4; nt2++) {
            int brow = wn*64 + nt2*16 + lrow;
            uint32_t rh[4], rl[4];
            ldsm4(rh, s2u(sBh + brow*KP + kcol));
            ldsm4(rl, s2u(sBl + brow*KP + kcol));
            uint32_t b0h[2] = {rh[0], rh[2]}, b1h[2] = {rh[1], rh[3]};
            uint32_t b0l[2] = {rl[0], rl[2]}, b1l[2] = {rl[1], rl[3]};
            #pragma unroll
            for (int mt = 0; mt < 2; mt++)
                MMA3x2(acc[mt][nt2*2], acc[mt][nt2*2+1], ah[mt], al[mt], b0h, b0l, b1h, b1l);
        }
    }

    const int rl4 = lane >> 2, cl2 = (lane & 3)*2;

    if (MODE == 4) {
        float bm = -1e30f;
        #pragma unroll
        for (int mt = 0; mt < 2; mt++)
            #pragma unroll
            for (int h = 0; h < 2; h++) {
                int gr = row0 + wm*32 + mt*16 + rl4 + h*8;
                #pragma unroll
                for (int nt = 0; nt < 8; nt++) {
                    float2 v = {acc[mt][nt][h*2], acc[mt][nt][h*2+1]};
                    *(float2*)(out + (size_t)gr*MF + wn*64 + nt*8 + cl2) = v;
                    bm = fmaxf(bm, fmaxf(v.x, v.y));
                }
            }
        s_red[t] = bm; __syncthreads();
        #pragma unroll
        for (int o = 128; o > 0; o >>= 1) { if (t < o) s_red[t] = fmaxf(s_red[t], s_red[t+o]); __syncthreads(); }
        if (t == 0) bmax[blockIdx.y] = s_red[0];
    } else {
        float rm[2][2];
        #pragma unroll
        for (int mt = 0; mt < 2; mt++)
            #pragma unroll
            for (int h = 0; h < 2; h++) {
                float m = -1e30f;
                #pragma unroll
                for (int nt = 0; nt < 8; nt++)
                    m = fmaxf(m, fmaxf(acc[mt][nt][h*2], acc[mt][nt][h*2+1]));
                m = fmaxf(m, __shfl_xor_sync(0xffffffffu, m, 1));
                m = fmaxf(m, __shfl_xor_sync(0xffffffffu, m, 2));
                rm[mt][h] = m;
            }
        if ((lane & 3) == 0) {
            #pragma unroll
            for (int mt = 0; mt < 2; mt++)
                #pragma unroll
                for (int h = 0; h < 2; h++)
                    s_rm[wn][wm*32 + mt*16 + rl4 + h*8] = rm[mt][h];
        }
        __syncthreads();
        #pragma unroll
        for (int mt = 0; mt < 2; mt++)
            #pragma unroll
            for (int h = 0; h < 2; h++) {
                int lr = wm*32 + mt*16 + rl4 + h*8;
                int gr = row0 + lr;
                float rmax = fmaxf(s_rm[0][lr], s_rm[1][lr]);
                float dg = s_dg[lr];
                #pragma unroll
                for (int nt = 0; nt < 8; nt++) {
                    int gc = wn*64 + nt*8 + cl2;
                    float v0 = RATIOC*(expf(acc[mt][nt][h*2]  -dg-rmax) + 1e-4f);
                    float v1 = RATIOC*(expf(acc[mt][nt][h*2+1]-dg-rmax) + 1e-4f);
                    __nv_bfloat16 h0,l0,h1,l1;
                    split_bf16(v0,h0,l0); split_bf16(v1,h1,l1);
                    __nv_bfloat162 hp, lp;
                    hp.x = h0; hp.y = h1; lp.x = l0; lp.y = l1;
                    *(__nv_bfloat162*)(outH + (size_t)gr*MF + gc) = hp;
                    *(__nv_bfloat162*)(outL + (size_t)gr*MF + gc) = lp;
                }
            }
    }
}

// ======== 128x64-tile K=128 mainloop (2 CTAs/SM) — shared by QKV and FF1 ========
#define QKV_SMEM ((2*128 + 2*64)*KP*2)
#define MAINLOOP_64COL(sAh, sAl, sBh, sBl, Ah, Al, Bh, Bl, row0, col0, acc) \
    {   \
        _Pragma("unroll")                                                        \
        for (int i = 0; i < 8; i++) {                                            \
            int f = i*256 + threadIdx.x;                                         \
            int r = f >> 4, c8 = (f & 15) << 3;                                  \
            *(uint4*)(sAh + r*KP + c8) = *(const uint4*)(Ah + (size_t)(row0+r)*128 + c8); \
            *(uint4*)(sAl + r*KP + c8) = *(const uint4*)(Al + (size_t)(row0+r)*128 + c8); \
        }                                                                        \
        _Pragma("unroll")                                                        \
        for (int i = 0; i < 4; i++) {                                            \
            int f = i*256 + threadIdx.x;                                         \
            int r = f >> 4, c8 = (f & 15) << 3;                                  \
            *(uint4*)(sBh + r*KP + c8) = *(const uint4*)(Bh + (size_t)(col0+r)*128 + c8); \
            *(uint4*)(sBl + r*KP + c8) = *(const uint4*)(Bl + (size_t)(col0+r)*128 + c8); \
        }                                                                        \
        __syncthreads();                                                         \
        _Pragma("unroll")                                                        \
        for (int ks = 0; ks < 8; ks++) {                                         \
            int kcol = ks*16 + lcol8;                                            \
            uint32_t ah[2][4], al[2][4];                                         \
            _Pragma("unroll")                                                    \
            for (int mt = 0; mt < 2; mt++) {                                     \
                int arow = wm*32 + mt*16 + lrow;                                 \
                ldsm4(ah[mt], s2u(sAh + arow*KP + kcol));                        \
                ldsm4(al[mt], s2u(sAl + arow*KP + kcol));                        \
            }                                                                    \
            _Pragma("unroll")                                                    \
            for (int nt2 = 0; nt2 < 2; nt2++) {                                  \
                int brow = wn*32 + nt2*16 + lrow;                                \
                uint32_t rh[4], rl[4];                                           \
                ldsm4(rh, s2u(sBh + brow*KP + kcol));                            \
                ldsm4(rl, s2u(sBl + brow*KP + kcol));                            \
                uint32_t b0h[2] = {rh[0], rh[2]}, b1h[2] = {rh[1], rh[3]};       \
                uint32_t b0l[2] = {rl[0], rl[2]}, b1l[2] = {rl[1], rl[3]};       \
                _Pragma("unroll")                                                \
                for (int mt = 0; mt < 2; mt++)                                   \
                    MMA3x2(acc[mt][nt2*2], acc[mt][nt2*2+1], ah[mt], al[mt], b0h, b0l, b1h, b1l); \
            }                                                                    \
        }                                                                        \
    }

// QKV: grid (48, 64); epilogue scatters per part/head
__global__ __launch_bounds__(256) void k_mmaqkv64(
    const __nv_bfloat16* __restrict__ Ah, const __nv_bfloat16* __restrict__ Al,
    const __nv_bfloat16* __restrict__ Bh, const __nv_bfloat16* __restrict__ Bl)
{
    extern __shared__ __align__(16) char dsm[];
    __nv_bfloat16* sAh = (__nv_bfloat16*)dsm;
    __nv_bfloat16* sAl = sAh + 128*KP;
    __nv_bfloat16* sBh = sAl + 128*KP;
    __nv_bfloat16* sBl = sBh + 64*KP;
    const int t = threadIdx.x, w = t >> 5, lane = t & 31;
    const int wm = w & 3, wn = w >> 2;
    const int row0 = blockIdx.y*128, col0 = blockIdx.x*64;
    const int lrow = (lane & 15), lcol8 = (lane >> 4)*8;
    float acc[2][4][4] = {};

    MAINLOOP_64COL(sAh, sAl, sBh, sBl, Ah, Al, Bh, Bl, row0, col0, acc);

    const int rl4 = lane >> 2, cl2 = (lane & 3)*2;
    const int part = col0 >> 10;
    const int h = (col0 >> 7) & 7;
    const int d0 = col0 & 127;

    if (part < 2) {
        __nv_bfloat16* dH = part ? g_knh : g_qnh;
        __nv_bfloat16* dL = part ? g_knl : g_qnl;
        #pragma unroll
        for (int mt = 0; mt < 2; mt++)
            #pragma unroll
            for (int h2 = 0; h2 < 2; h2++) {
                int gr = row0 + wm*32 + mt*16 + rl4 + h2*8;
                int b = gr >> 11, s = gr & 2047;
                size_t base = ((size_t)(b*HH + h)*SS + s)*DHD + d0;
                #pragma unroll
                for (int nt = 0; nt < 4; nt++) {
                    float v0 = acc[mt][nt][h2*2]   * NORMC;
                    float v1 = acc[mt][nt][h2*2+1] * NORMC;
                    __nv_bfloat16 h0,l0,h1,l1;
                    split_bf16(v0,h0,l0); split_bf16(v1,h1,l1);
                    __nv_bfloat162 hp, lp;
                    hp.x = h0; hp.y = h1; lp.x = l0; lp.y = l1;
                    *(__nv_bfloat162*)(dH + base + wn*32 + nt*8 + cl2) = hp;
                    *(__nv_bfloat162*)(dL + base + wn*32 + nt*8 + cl2) = lp;
                }
            }
    } else {
        #pragma unroll
        for (int mt = 0; mt < 2; mt++)
            #pragma unroll
            for (int h2 = 0; h2 < 2; h2++) {
                int gr = row0 + wm*32 + mt*16 + rl4 + h2*8;
                size_t base = (size_t)gr*INNER + h*DHD + d0;
                #pragma unroll
                for (int nt = 0; nt < 4; nt++) {
                    __nv_bfloat16 h0,l0,h1,l1;
                    split_bf16(acc[mt][nt][h2*2],   h0, l0);
                    split_bf16(acc[mt][nt][h2*2+1], h1, l1);
                    __nv_bfloat162 hp, lp;
                    hp.x = h0; hp.y = h1; lp.x = l0; lp.y = l1;
                    *(__nv_bfloat162*)(g_vh + base + wn*32 + nt*8 + cl2) = hp;
                    *(__nv_bfloat162*)(g_vl + base + wn*32 + nt*8 + cl2) = lp;
                }
            }
    }
}

// FF1: grid (8, 64); gelu epilogue -> fh/fl
__global__ __launch_bounds__(256) void k_ff1(
    const __nv_bfloat16* __restrict__ Ah, const __nv_bfloat16* __restrict__ Al,
    const __nv_bfloat16* __restrict__ Bh, const __nv_bfloat16* __restrict__ Bl,
    const float* __restrict__ bias)
{
    extern __shared__ __align__(16) char dsm[];
    __nv_bfloat16* sAh = (__nv_bfloat16*)dsm;
    __nv_bfloat16* sAl = sAh + 128*KP;
    __nv_bfloat16* sBh = sAl + 128*KP;
    __nv_bfloat16* sBl = sBh + 64*KP;
    const int t = threadIdx.x, w = t >> 5, lane = t & 31;
    const int wm = w & 3, wn = w >> 2;
    const int row0 = blockIdx.y*128, col0 = blockIdx.x*64;
    const int lrow = (lane & 15), lcol8 = (lane >> 4)*8;
    float acc[2][4][4] = {};

    MAINLOOP_64COL(sAh, sAl, sBh, sBl, Ah, Al, Bh, Bl, row0, col0, acc);

    const int rl4 = lane >> 2, cl2 = (lane & 3)*2;
    #pragma unroll
    for (int mt = 0; mt < 2; mt++)
        #pragma unroll
        for (int h2 = 0; h2 < 2; h2++) {
            int gr = row0 + wm*32 + mt*16 + rl4 + h2*8;
            #pragma unroll
            for (int nt = 0; nt < 4; nt++) {
                int gc = col0 + wn*32 + nt*8 + cl2;
                float v0 = gelu(acc[mt][nt][h2*2]   + bias[gc]);
                float v1 = gelu(acc[mt][nt][h2*2+1] + bias[gc+1]);
                __nv_bfloat16 h0,l0,h1,l1;
                split_bf16(v0,h0,l0); split_bf16(v1,h1,l1);
                __nv_bfloat162 hp, lp;
                hp.x = h0; hp.y = h1; lp.x = l0; lp.y = l1;
                *(__nv_bfloat162*)(g_fh + (size_t)gr*FFD + gc) = hp;
                *(__nv_bfloat162*)(g_fl + (size_t)gr*FFD + gc) = lp;
            }
        }
}

// ============ HMMA GEMM 64x128 tile, double-buffered (WO/FF2 residual) ============
// SROW must be a multiple of 8 elements (16B) for uint4/ldmatrix alignment.
#define SROW 72
#define BUFSZ (384*SROW)
__global__ __launch_bounds__(256) void k_mma64(
    const __nv_bfloat16* __restrict__ Ah, const __nv_bfloat16* __restrict__ Al, int lda,
    const __nv_bfloat16* __restrict__ Bh, const __nv_bfloat16* __restrict__ Bl,
    int Ktot,
    const float* __restrict__ bias,
    float* __restrict__ out)
{
    extern __shared__ __align__(16) __nv_bfloat16 sb[];
    const int t = threadIdx.x, w = t >> 5, lane = t & 31;
    const int wm = w & 1, wn = w >> 1;
    const int row0 = blockIdx.y*64;
    float acc[2][4][4] = {};
    const int lrow = (lane & 15), lcol8 = (lane >> 4)*8;

    {
        #pragma unroll
        for (int i = 0; i < 2; i++) {
            int f = i*256 + t;
            int r = f >> 3, c8 = (f & 7) << 3;
            *(uint4*)(sb + r*SROW + c8)            = *(const uint4*)(Ah + (size_t)(row0+r)*lda + c8);
            *(uint4*)(sb + 64*SROW + r*SROW + c8)  = *(const uint4*)(Al + (size_t)(row0+r)*lda + c8);
        }
        #pragma unroll
        for (int i = 0; i < 4; i++) {
            int f = i*256 + t;
            int r = f >> 3, c8 = (f & 7) << 3;
            *(uint4*)(sb + 128*SROW + r*SROW + c8) = *(const uint4*)(Bh + (size_t)r*Ktot + c8);
            *(uint4*)(sb + 256*SROW + r*SROW + c8) = *(const uint4*)(Bl + (size_t)r*Ktot + c8);
        }
    }
    __syncthreads();
    int buf = 0;

    for (int kc = 64; kc <= Ktot; kc += 64) {
        uint4 ra[2][2], rb[2][4];
        if (kc < Ktot) {
            #pragma unroll
            for (int i = 0; i < 2; i++) {
                int f = i*256 + t;
                int r = f >> 3, c8 = (f & 7) << 3;
                ra[0][i] = *(const uint4*)(Ah + (size_t)(row0+r)*lda + kc + c8);
                ra[1][i] = *(const uint4*)(Al + (size_t)(row0+r)*lda + kc + c8);
            }
            #pragma unroll
            for (int i = 0; i < 4; i++) {
                int f = i*256 + t;
                int r = f >> 3, c8 = (f & 7) << 3;
                rb[0][i] = *(const uint4*)(Bh + (size_t)r*Ktot + kc + c8);
                rb[1][i] = *(const uint4*)(Bl + (size_t)r*Ktot + kc + c8);
            }
        }
        const __nv_bfloat16* cb = sb + buf*BUFSZ;
        #pragma unroll
        for (int ks = 0; ks < 4; ks++) {
            int kcol = ks*16 + lcol8;
            uint32_t ah[2][4], al[2][4];
            #pragma unroll
            for (int mt = 0; mt < 2; mt++) {
                int arow = wm*32 + mt*16 + lrow;
                ldsm4(ah[mt], s2u(cb + arow*SROW + kcol));
                ldsm4(al[mt], s2u(cb + 64*SROW + arow*SROW + kcol));
            }
            #pragma unroll
            for (int nt2 = 0; nt2 < 2; nt2++) {
                int brow = wn*32 + nt2*16 + lrow;
                uint32_t rh[4], rl[4];
                ldsm4(rh, s2u(cb + 128*SROW + brow*SROW + kcol));
                ldsm4(rl, s2u(cb + 256*SROW + brow*SROW + kcol));
                uint32_t b0h[2] = {rh[0], rh[2]}, b1h[2] = {rh[1], rh[3]};
                uint32_t b0l[2] = {rl[0], rl[2]}, b1l[2] = {rl[1], rl[3]};
                #pragma unroll
                for (int mt = 0; mt < 2; mt++)
                    MMA3x2(acc[mt][nt2*2], acc[mt][nt2*2+1], ah[mt], al[mt], b0h, b0l, b1h, b1l);
            }
        }
        if (kc < Ktot) {
            __nv_bfloat16* nb = sb + (buf^1)*BUFSZ;
            #pragma unroll
            for (int i = 0; i < 2; i++) {
                int f = i*256 + t;
                int r = f >> 3, c8 = (f & 7) << 3;
                *(uint4*)(nb + r*SROW + c8)           = ra[0][i];
                *(uint4*)(nb + 64*SROW + r*SROW + c8) = ra[1][i];
            }
            #pragma unroll
            for (int i = 0; i < 4; i++) {
                int f = i*256 + t;
                int r = f >> 3, c8 = (f & 7) << 3;
                *(uint4*)(nb + 128*SROW + r*SROW + c8) = rb[0][i];
                *(uint4*)(nb + 256*SROW + r*SROW + c8) = rb[1][i];
            }
            __syncthreads();
            buf ^= 1;
        }
    }

    const int rl4 = lane >> 2, cl2 = (lane & 3)*2;
    #pragma unroll
    for (int mt = 0; mt < 2; mt++)
        #pragma unroll
        for (int h2 = 0; h2 < 2; h2++) {
            int gr = row0 + wm*32 + mt*16 + rl4 + h2*8;
            #pragma unroll
            for (int nt = 0; nt < 4; nt++) {
                int gc = wn*32 + nt*8 + cl2;
                size_t idx = (size_t)gr*DIMC + gc;
                float2 v = *(float2*)(out + idx);
                v.x += acc[mt][nt][h2*2]   + bias[gc];
                v.y += acc[mt][nt][h2*2+1] + bias[gc+1];
                *(float2*)(out + idx) = v;
            }
        }
}

// ---------------- embed ----------------
__global__ void k_embed(const float* __restrict__ x, const float* __restrict__ lw,
                        const float* __restrict__ lb, const float* __restrict__ pe)
{
    int warp = threadIdx.x >> 5, lane = threadIdx.x & 31;
    int r = blockIdx.x*8 + warp;
    float xv = x[r];
    float4 l4 = ((const float4*)lw)[lane];
    float4 b4 = ((const float4*)lb)[lane];
    float4 p4 = ((const float4*)(pe + (size_t)(r % SS)*DIMC))[lane];
    float4 o4 = { xv*l4.x + b4.x + p4.x, xv*l4.y + b4.y + p4.y,
                  xv*l4.z + b4.z + p4.z, xv*l4.w + b4.w + p4.w };
    ((float4*)(g_h + (size_t)r*DIMC))[lane] = o4;
}

// ---------------- layernorm -> bf16 hi/lo ----------------
__global__ void k_ln(const float* __restrict__ in, const float* __restrict__ g,
                     const float* __restrict__ b,
                     __nv_bfloat16* __restrict__ outH, __nv_bfloat16* __restrict__ outL)
{
    int warp = threadIdx.x >> 5, lane = threadIdx.x & 31;
    int r = blockIdx.x*8 + warp;
    float4 v = ((const float4*)(in + (size_t)r*DIMC))[lane];
    float s = v.x + v.y + v.z + v.w;
    #pragma unroll
    for (int o = 16; o > 0; o >>= 1) s += __shfl_xor_sync(0xffffffffu, s, o);
    float mu = s * (1.0f/DIMC);
    float dx = v.x-mu, dy = v.y-mu, dz = v.z-mu, dw = v.w-mu;
    float q = dx*dx + dy*dy + dz*dz + dw*dw;
    #pragma unroll
    for (int o = 16; o > 0; o >>= 1) q += __shfl_xor_sync(0xffffffffu, q, o);
    float inv = rsqrtf(q*(1.0f/DIMC) + 1e-5f);
    float4 gv = ((const float4*)g)[lane];
    float4 bv = ((const float4*)b)[lane];
    float o4[4] = { dx*inv*gv.x + bv.x, dy*inv*gv.y + bv.y,
                    dz*inv*gv.z + bv.z, dw*inv*gv.w + bv.w };
    __nv_bfloat16 hh[4], ll[4];
    #pragma unroll
    for (int j = 0; j < 4; j++) split_bf16(o4[j], hh[j], ll[j]);
    size_t base = (size_t)r*DIMC + lane*4;
    *(uint2*)(outH+base) = *(uint2*)hh;
    *(uint2*)(outL+base) = *(uint2*)ll;
}

// -------- unified weight prep: one launch, all weights, both layers --------
__global__ __launch_bounds__(256) void k_wprep(
    const float* __restrict__ wq, const float* __restrict__ wk,
    const float* __restrict__ wv, const float* __restrict__ wo,
    const float* __restrict__ ff1_w, const float* __restrict__ ff2_w,
    const float* __restrict__ proj)
{
    __shared__ float tile[32][33];
    int bid = blockIdx.x;
    int l = (bid >= 656) ? 1 : 0;
    bid -= l*656;
    size_t wb = (size_t)l*WT_LAYER;
    __nv_bfloat16* wth = g_wth + wb;
    __nv_bfloat16* wtl = g_wtl + wb;

    const float* W; __nv_bfloat16 *oH, *oL; int K, N, tidx;
    if (bid < 384) {
        int which = bid >> 7; tidx = bid & 127;
        W = (which == 0 ? wq : which == 1 ? wk : wv) + (size_t)l*DIMC*INNER;
        oH = wth + (which == 0 ? WT_Q : which == 1 ? WT_K : WT_V);
        oL = wtl + (which == 0 ? WT_Q : which == 1 ? WT_K : WT_V);
        K = DIMC; N = INNER;
    } else if (bid < 512) {
        tidx = bid - 384;
        W = wo + (size_t)l*INNER*DIMC;
        oH = wth + WT_O; oL = wtl + WT_O;
        K = INNER; N = DIMC;
    } else if (bid < 576) {
        tidx = bid - 512;
        W = ff1_w + (size_t)l*DIMC*FFD;
        oH = wth + WT_F1; oL = wtl + WT_F1;
        K = DIMC; N = FFD;
    } else if (bid < 640) {
        tidx = bid - 576;
        W = ff2_w + (size_t)l*FFD*DIMC;
        oH = wth + WT_F2; oL = wtl + WT_F2;
        K = FFD; N = DIMC;
    } else {
        int e4 = (bid - 640)*256 + threadIdx.x;
        float4 v = ((const float4*)(proj + (size_t)l*MF*DHD))[e4];
        __nv_bfloat16 hh[4], ll[4];
        split_bf16(v.x, hh[0], ll[0]); split_bf16(v.y, hh[1], ll[1]);
        split_bf16(v.z, hh[2], ll[2]); split_bf16(v.w, hh[3], ll[3]);
        *(uint2*)(wth + WT_PJ + e4*4) = *(uint2*)hh;
        *(uint2*)(wtl + WT_PJ + e4*4) = *(uint2*)ll;
        return;
    }
    int ntiles = N >> 5;
    int n0 = (tidx % ntiles)*32, k0 = (tidx / ntiles)*32;
    int tx = threadIdx.x & 31, ty = threadIdx.x >> 5;
    #pragma unroll
    for (int i = ty; i < 32; i += 8)
        tile[i][tx] = W[(size_t)(k0+i)*N + n0 + tx];
    __syncthreads();
    #pragma unroll
    for (int i = ty; i < 32; i += 8) {
        float v = tile[tx][i];
        __nv_bfloat16 hh, ll;
        split_bf16(v, hh, ll);
        oH[(size_t)(n0+i)*K + k0 + tx] = hh;
        oL[(size_t)(n0+i)*K + k0 + tx] = ll;
    }
}

// ================= chunk-local attention via HMMA, 512 threads =================
#define CP 136
__global__ __launch_bounds__(512) void k_chunk(
    const __nv_bfloat16* __restrict__ qph, const __nv_bfloat16* __restrict__ qpl)
{
    extern __shared__ __align__(16) __nv_bfloat16 cs[];
    __nv_bfloat16* sQh = cs;
    __nv_bfloat16* sQl = sQh + 128*CP;
    __nv_bfloat16* sKh = sQl + 128*CP;
    __nv_bfloat16* sKl = sKh + 128*CP;
    __nv_bfloat16* sVh = sKl + 128*CP;
    __nv_bfloat16* sVl = sVh + 128*CP;
    __shared__ float s_den[4][128];
    __shared__ float s_dg[128];

    int blk = blockIdx.x, bh = blk >> 4, c = blk & 15;
    int b = bh >> 3, hh = bh & 7;
    int t = threadIdx.x, w = t >> 5, lane = t & 31;
    int wm = w & 3, wn = w >> 2;
    const int lrow = lane & 15, lcol8 = (lane >> 4)*8;
    const int rl4 = lane >> 2, cl2 = (lane & 3)*2;

    const size_t qbase = ((size_t)bh*SS + c*CHUNK)*MF;
    if (t < 128) {
        float st = g_bmax[bh*16];
        #pragma unroll
        for (int i = 1; i < 16; i++) st = fmaxf(st, g_bmax[bh*16 + i]);
        s_dg[t] = g_diagk[(size_t)bh*SS + c*CHUNK + t] + st;
    }
    for (int i = t; i < 2048; i += 512) {
        int r = i >> 4, c8 = (i & 15) << 3;
        *(uint4*)(sQh + r*CP + c8) = *(const uint4*)(qph + qbase + r*MF + c8);
        *(uint4*)(sQl + r*CP + c8) = *(const uint4*)(qpl + qbase + r*MF + c8);
        size_t vsrc = (size_t)(b*SS + c*CHUNK + r)*INNER + hh*DHD + c8;
        *(uint4*)(sVh + r*CP + c8) = *(const uint4*)(g_vh + vsrc);
        *(uint4*)(sVl + r*CP + c8) = *(const uint4*)(g_vl + vsrc);
    }
    __syncthreads();
    for (int f = t; f < 4096; f += 512) {
        int r = f >> 5, c4 = (f & 31) << 2;
        float4 dv = *(const float4*)(g_kp + qbase + (size_t)r*MF + c4);
        float dgv = s_dg[r];
        float o0 = RATIOC*(expf(dv.x - dgv) + 1e-4f);
        float o1 = RATIOC*(expf(dv.y - dgv) + 1e-4f);
        float o2 = RATIOC*(expf(dv.z - dgv) + 1e-4f);
        float o3 = RATIOC*(expf(dv.w - dgv) + 1e-4f);
        __nv_bfloat16 hh4[4], ll4[4];
        split_bf16(o0, hh4[0], ll4[0]); split_bf16(o1, hh4[1], ll4[1]);
        split_bf16(o2, hh4[2], ll4[2]); split_bf16(o3, hh4[3], ll4[3]);
        *(uint2*)(sKh + r*CP + c4) = *(uint2*)hh4;
        *(uint2*)(sKl + r*CP + c4) = *(uint2*)ll4;
    }
    __syncthreads();

    float acc[2][4][4] = {};
    if (wn <= wm) {
        #pragma unroll
        for (int ks = 0; ks < 8; ks++) {
            int kcol = ks*16 + lcol8;
            uint32_t ah[2][4], al[2][4];
            #pragma unroll
            for (int mt = 0; mt < 2; mt++) {
                int arow = wm*32 + mt*16 + lrow;
                ldsm4(ah[mt], s2u(sQh + arow*CP + kcol));
                ldsm4(al[mt], s2u(sQl + arow*CP + kcol));
            }
            #pragma unroll
            for (int nt2 = 0; nt2 < 2; nt2++) {
                int brow = wn*32 + nt2*16 + lrow;
                uint32_t rh[4], rl[4];
                ldsm4(rh, s2u(sKh + brow*CP + kcol));
                ldsm4(rl, s2u(sKl + brow*CP + kcol));
                uint32_t b0h[2] = {rh[0], rh[2]}, b1h[2] = {rh[1], rh[3]};
                uint32_t b0l[2] = {rl[0], rl[2]}, b1l[2] = {rl[1], rl[3]};
                #pragma unroll
                for (int mt = 0; mt < 2; mt++)
                    MMA3x2(acc[mt][nt2*2], acc[mt][nt2*2+1], ah[mt], al[mt], b0h, b0l, b1h, b1l);
            }
        }
    }
    float dp[2][2] = {};
    #pragma unroll
    for (int mt = 0; mt < 2; mt++)
        #pragma unroll
        for (int nt = 0; nt < 4; nt++)
            #pragma unroll
            for (int f = 0; f < 4; f++) {
                int i = wm*32 + mt*16 + rl4 + ((f>>1)<<3);
                int j = wn*32 + nt*8 + cl2 + (f&1);
                if (j > i) acc[mt][nt][f] = 0.f;
                dp[mt][f>>1] += acc[mt][nt][f];
            }
    #pragma unroll
    for (int o = 1; o < 4; o <<= 1)
        #pragma unroll
        for (int mt = 0; mt < 2; mt++)
            #pragma unroll
            for (int h2 = 0; h2 < 2; h2++)
                dp[mt][h2] += __shfl_xor_sync(0xffffffffu, dp[mt][h2], o);
    if ((lane & 3) == 0) {
        #pragma unroll
        for (int mt = 0; mt < 2; mt++)
            #pragma unroll
            for (int h2 = 0; h2 < 2; h2++)
                s_den[wn][wm*32 + mt*16 + rl4 + h2*8] = dp[mt][h2];
    }
    __syncthreads();

    #pragma unroll
    for (int mt = 0; mt < 2; mt++)
        #pragma unroll
        for (int nt = 0; nt < 4; nt++)
            #pragma unroll
            for (int f = 0; f < 4; f++) {
                int i = wm*32 + mt*16 + rl4 + ((f>>1)<<3);
                int j = wn*32 + nt*8 + cl2 + (f&1);
                __nv_bfloat16 hh2, ll2;
                split_bf16(acc[mt][nt][f], hh2, ll2);
                sQh[i*CP + j] = hh2;
                sQl[i*CP + j] = ll2;
            }
    if (t < 128) {
        g_den[(size_t)bh*SS + c*CHUNK + t] = s_den[0][t] + s_den[1][t] + s_den[2][t] + s_den[3][t];
        float kssum = 0.f;
        for (int j = 0; j < 128; j++)
            kssum += __bfloat162float(sKh[j*CP + t]) + __bfloat162float(sKl[j*CP + t]);
        g_ksc[((size_t)bh*NC + c)*MF + t] = kssum;
    }
    __syncthreads();

    #pragma unroll
    for (int mt = 0; mt < 2; mt++)
        #pragma unroll
        for (int nt = 0; nt < 4; nt++)
            #pragma unroll
            for (int f = 0; f < 4; f++) acc[mt][nt][f] = 0.f;
    #pragma unroll
    for (int ks = 0; ks < 8; ks++) {
        int kcol = ks*16 + lcol8;
        uint32_t ah[2][4], al[2][4];
        #pragma unroll
        for (int mt = 0; mt < 2; mt++) {
            int arow = wm*32 + mt*16 + lrow;
            ldsm4(ah[mt], s2u(sQh + arow*CP + kcol));
            ldsm4(al[mt], s2u(sQl + arow*CP + kcol));
        }
        #pragma unroll
        for (int nt2 = 0; nt2 < 2; nt2++) {
            int nbase = wn*32 + nt2*16;
            uint32_t dh[4], dl[4];
            ldsm4t(dh, taddr(sVh, CP, ks*16, nbase, lane));
            ldsm4t(dl, taddr(sVl, CP, ks*16, nbase, lane));
            uint32_t b0h[2] = {dh[0], dh[2]}, b1h[2] = {dh[1], dh[3]};
            uint32_t b0l[2] = {dl[0], dl[2]}, b1l[2] = {dl[1], dl[3]};
            #pragma unroll
            for (int mt = 0; mt < 2; mt++)
                MMA3x2(acc[mt][nt2*2], acc[mt][nt2*2+1], ah[mt], al[mt], b0h, b0l, b1h, b1l);
        }
    }
    #pragma unroll
    for (int mt = 0; mt < 2; mt++)
        #pragma unroll
        for (int h2 = 0; h2 < 2; h2++) {
            int i = wm*32 + mt*16 + rl4 + h2*8;
            size_t base = ((size_t)(b*SS + c*CHUNK + i)*HH + hh)*DHD;
            #pragma unroll
            for (int nt = 0; nt < 4; nt++) {
                float2 vv = {acc[mt][nt][h2*2], acc[mt][nt][h2*2+1]};
                *(float2*)(g_o + base + wn*32 + nt*8 + cl2) = vv;
            }
        }

    #pragma unroll
    for (int mt = 0; mt < 2; mt++)
        #pragma unroll
        for (int nt = 0; nt < 4; nt++)
            #pragma unroll
            for (int f = 0; f < 4; f++) acc[mt][nt][f] = 0.f;
    #pragma unroll
    for (int ks = 0; ks < 8; ks++) {
        uint32_t ah[2][4], al[2][4];
        #pragma unroll
        for (int mt = 0; mt < 2; mt++) {
            int mbase = wm*32 + mt*16;
            ldsm4t(ah[mt], taddr(sKh, CP, ks*16, mbase, lane));
            ldsm4t(al[mt], taddr(sKl, CP, ks*16, mbase, lane));
        }
        #pragma unroll
        for (int nt2 = 0; nt2 < 2; nt2++) {
            int nbase = wn*32 + nt2*16;
            uint32_t dh[4], dl[4];
            ldsm4t(dh, taddr(sVh, CP, ks*16, nbase, lane));
            ldsm4t(dl, taddr(sVl, CP, ks*16, nbase, lane));
            uint32_t b0h[2] = {dh[0], dh[2]}, b1h[2] = {dh[1], dh[3]};
            uint32_t b0l[2] = {dl[0], dl[2]}, b1l[2] = {dl[1], dl[3]};
            #pragma unroll
            for (int mt = 0; mt < 2; mt++)
                MMA3x2(acc[mt][nt2*2], acc[mt][nt2*2+1], ah[mt], al[mt], b0h, b0l, b1h, b1l);
        }
    }
    {
        size_t kvbase = ((size_t)bh*NC + c)*(MF*DHD);
        #pragma unroll
        for (int mt = 0; mt < 2; mt++)
            #pragma unroll
            for (int h2 = 0; h2 < 2; h2++) {
                int m = wm*32 + mt*16 + rl4 + h2*8;
                #pragma unroll
                for (int nt = 0; nt < 4; nt++) {
                    float2 vv = {acc[mt][nt][h2*2], acc[mt][nt][h2*2+1]};
                    *(float2*)(g_kvc + kvbase + (size_t)m*DHD + wn*32 + nt*8 + cl2) = vv;
                }
            }
    }
}

// ---------------- exclusive prefix over chunks (emits bf16 hi/lo) ----------------
__global__ void k_prefix()
{
    int bh = blockIdx.x, seg = blockIdx.y, t = threadIdx.x;
    for (int e = seg*2048 + t; e < (seg+1)*2048; e += 256) {
        float run = 0.f;
        #pragma unroll
        for (int c = 0; c < NC; c++) {
            size_t idx = ((size_t)bh*NC + c)*(MF*DHD) + e;
            __nv_bfloat16 hh, ll;
            split_bf16(run, hh, ll);
            g_kvph[idx] = hh; g_kvpl[idx] = ll;
            run += g_kvc[idx];
        }
    }
    if (seg == 0) {
        for (int e = t; e < MF; e += 256) {
            float run = 0.f;
            #pragma unroll
            for (int c = 0; c < NC; c++) {
                size_t idx = ((size_t)bh*NC + c)*MF + e;
                g_ksp[idx] = run; run += g_ksc[idx];
            }
        }
    }
}

// ========== cross = qp @ kvp, + num, normalize -> oh/ol (HMMA, 512 thr) ==========
__global__ __launch_bounds__(512) void k_cross(
    const __nv_bfloat16* __restrict__ qph, const __nv_bfloat16* __restrict__ qpl)
{
    extern __shared__ __align__(16) __nv_bfloat16 cs[];
    __nv_bfloat16* sQh = cs;
    __nv_bfloat16* sQl = sQh + 128*CP;
    __nv_bfloat16* sPh = sQl + 128*CP;
    __nv_bfloat16* sPl = sPh + 128*CP;
    __shared__ float s_ks[128];
    __shared__ float s_dc[128];

    int blk = blockIdx.x, bh = blk >> 4, c = blk & 15;
    int b = bh >> 3, hh = bh & 7;
    int t = threadIdx.x, w = t >> 5, lane = t & 31;
    int wm = w & 3, wn = w >> 2;
    const int lrow = lane & 15, lcol8 = (lane >> 4)*8;
    const int rl4 = lane >> 2, cl2 = (lane & 3)*2;

    const size_t qbase = ((size_t)bh*SS + c*CHUNK)*MF;
    const size_t pbase = ((size_t)bh*NC + c)*(MF*DHD);
    for (int i = t; i < 2048; i += 512) {
        int r = i >> 4, c8 = (i & 15) << 3;
        *(uint4*)(sQh + r*CP + c8) = *(const uint4*)(qph + qbase + r*MF + c8);
        *(uint4*)(sQl + r*CP + c8) = *(const uint4*)(qpl + qbase + r*MF + c8);
        *(uint4*)(sPh + r*CP + c8) = *(const uint4*)(g_kvph + pbase + r*DHD + c8);
        *(uint4*)(sPl + r*CP + c8) = *(const uint4*)(g_kvpl + pbase + r*DHD + c8);
    }
    if (t < 128) s_ks[t] = g_ksp[((size_t)bh*NC + c)*MF + t];
    __syncthreads();
    if (t < 128) {
        float dc = 0.f;
        for (int m = 0; m < 128; m++)
            dc += (__bfloat162float(sQh[t*CP + m]) + __bfloat162float(sQl[t*CP + m]))*s_ks[m];
        s_dc[t] = g_den[(size_t)bh*SS + c*CHUNK + t] + dc + 1e-6f;
    }
    __syncthreads();

    float acc[2][4][4] = {};
    #pragma unroll
    for (int ks = 0; ks < 8; ks++) {
        int kcol = ks*16 + lcol8;
        uint32_t ah[2][4], al[2][4];
        #pragma unroll
        for (int mt = 0; mt < 2; mt++) {
            int arow = wm*32 + mt*16 + lrow;
            ldsm4(ah[mt], s2u(sQh + arow*CP + kcol));
            ldsm4(al[mt], s2u(sQl + arow*CP + kcol));
        }
        #pragma unroll
        for (int nt2 = 0; nt2 < 2; nt2++) {
            int nbase = wn*32 + nt2*16;
            uint32_t dh[4], dl[4];
            ldsm4t(dh, taddr(sPh, CP, ks*16, nbase, lane));
            ldsm4t(dl, taddr(sPl, CP, ks*16, nbase, lane));
            uint32_t b0h[2] = {dh[0], dh[2]}, b1h[2] = {dh[1], dh[3]};
            uint32_t b0l[2] = {dl[0], dl[2]}, b1l[2] = {dl[1], dl[3]};
            #pragma unroll
            for (int mt = 0; mt < 2; mt++)
                MMA3x2(acc[mt][nt2*2], acc[mt][nt2*2+1], ah[mt], al[mt], b0h, b0l, b1h, b1l);
        }
    }
    #pragma unroll
    for (int mt = 0; mt < 2; mt++)
        #pragma unroll
        for (int h2 = 0; h2 < 2; h2++) {
            int i = wm*32 + mt*16 + rl4 + h2*8;
            float inv = 1.0f / s_dc[i];
            size_t base = ((size_t)(b*SS + c*CHUNK + i)*HH + hh)*DHD;
            #pragma unroll
            for (int nt = 0; nt < 4; nt++) {
                size_t idx = base + wn*32 + nt*8 + cl2;
                float2 nn = *(float2*)(g_o + idx);
                float v0 = (nn.x + acc[mt][nt][h2*2])   * inv;
                float v1 = (nn.y + acc[mt][nt][h2*2+1]) * inv;
                __nv_bfloat16 h0,l0,h1,l1;
                split_bf16(v0,h0,l0); split_bf16(v1,h1,l1);
                __nv_bfloat162 hp, lp;
                hp.x = h0; hp.y = h1; lp.x = l0; lp.y = l1;
                *(__nv_bfloat162*)(g_oh + idx) = hp;
                *(__nv_bfloat162*)(g_ol + idx) = lp;
            }
        }
}

// ---------------- pooling ----------------
__global__ void k_pool()
{
    int b = blockIdx.x, seg = blockIdx.y, t = threadIdx.x;
    float acc = 0.f;
    for (int s = seg*128; s < (seg+1)*128; s++) acc += g_h[((size_t)b*SS + s)*DIMC + t];
    g_pp[(b*16 + seg)*DIMC + t] = acc;
}

__global__ void k_final(const float* __restrict__ fw, const float* __restrict__ fb,
                        float* __restrict__ out)
{
    __shared__ float pooled[BB*DIMC];
    int t = threadIdx.x;
    for (int b = 0; b < BB; b++) {
        float a = 0.f;
        #pragma unroll
        for (int s = 0; s < 16; s++) a += g_pp[(b*16 + s)*DIMC + t];
        pooled[b*DIMC + t] = a * (1.0f/SS);
    }
    __syncthreads();
    if (t < BB*NCLS) {
        int b = t / NCLS, c = t % NCLS;
        float acc = fb[c];
        for (int d = 0; d < DIMC; d++) acc += pooled[b*DIMC + d]*fw[d*NCLS + c];
        out[t] = acc;
    }
}

// ---------------- host driver ----------------
static void* sym(const void* s) { void* p = nullptr; cudaGetSymbolAddress(&p, s); return p; }

extern "C" void kernel_launch(void* const* d_in, const int* in_sizes, int n_in,
                              void* d_out, int out_size)
{
    const float* x     = (const float*)d_in[0];
    const float* lin_w = (const float*)d_in[1];
    const float* lin_b = (const float*)d_in[2];
    const float* pe    = (const float*)d_in[3];
    const float* proj  = (const float*)d_in[4];
    const float* ln1_g = (const float*)d_in[5];
    const float* ln1_b = (const float*)d_in[6];
    const float* wq    = (const float*)d_in[7];
    const float* wk    = (const float*)d_in[8];
    const float* wv    = (const float*)d_in[9];
    const float* wo    = (const float*)d_in[10];
    const float* wo_b  = (const float*)d_in[11];
    const float* ln2_g = (const float*)d_in[12];
    const float* ln2_b = (const float*)d_in[13];
    const float* ff1_w = (const float*)d_in[14];
    const float* ff1_b = (const float*)d_in[15];
    const float* ff2_w = (const float*)d_in[16];
    const float* ff2_b = (const float*)d_in[17];
    const float* fin_w = (const float*)d_in[18];
    const float* fin_b = (const float*)d_in[19];
    float* out = (float*)d_out;

    float* ph   = (float*)sym(g_h);
    float* pkp  = (float*)sym(g_kp);
    float* pbm  = (float*)sym(g_bmax);

    __nv_bfloat16* yh  = (__nv_bfloat16*)sym(g_yh);
    __nv_bfloat16* yl  = (__nv_bfloat16*)sym(g_yl);
    __nv_bfloat16* wth = (__nv_bfloat16*)sym(g_wth);
    __nv_bfloat16* wtl = (__nv_bfloat16*)sym(g_wtl);
    __nv_bfloat16* qnh = (__nv_bfloat16*)sym(g_qnh);
    __nv_bfloat16* qnl = (__nv_bfloat16*)sym(g_qnl);
    __nv_bfloat16* knh = (__nv_bfloat16*)sym(g_knh);
    __nv_bfloat16* knl = (__nv_bfloat16*)sym(g_knl);
    __nv_bfloat16* qp_h = (__nv_bfloat16*)sym(g_qph);
    __nv_bfloat16* qp_l = (__nv_bfloat16*)sym(g_qpl);
    __nv_bfloat16* oh  = (__nv_bfloat16*)sym(g_oh);
    __nv_bfloat16* ol  = (__nv_bfloat16*)sym(g_ol);
    __nv_bfloat16* fh  = (__nv_bfloat16*)sym(g_fh);
    __nv_bfloat16* fl  = (__nv_bfloat16*)sym(g_fl);

    const int SMEM_MMA   = 4*128*KP*2;           // 139264 (features)
    const int SMEM_QKVFF = QKV_SMEM;             // 104448 (2 CTAs/SM)
    const int SMEM_MMA64 = 2*BUFSZ*2;            // 110592 (1 CTA/SM, aligned)
    const int SMEM_CHUNK = 6*128*CP*2;           // 208896
    const int SMEM_CROSS = 4*128*CP*2;           // 139264
    cudaFuncSetAttribute(k_mmaF, cudaFuncAttributeMaxDynamicSharedMemorySize, SMEM_MMA);
    cudaFuncSetAttribute(k_mmaqkv64, cudaFuncAttributeMaxDynamicSharedMemorySize, SMEM_QKVFF);
    cudaFuncSetAttribute(k_ff1, cudaFuncAttributeMaxDynamicSharedMemorySize, SMEM_QKVFF);
    cudaFuncSetAttribute(k_mma64, cudaFuncAttributeMaxDynamicSharedMemorySize, SMEM_MMA64);
    cudaFuncSetAttribute(k_chunk, cudaFuncAttributeMaxDynamicSharedMemorySize, SMEM_CHUNK);
    cudaFuncSetAttribute(k_cross, cudaFuncAttributeMaxDynamicSharedMemorySize, SMEM_CROSS);

    k_embed<<<BSR/8, 256>>>(x, lin_w, lin_b, pe);

    // unified weight prep: one launch for everything
    k_wprep<<<2*656, 256>>>(wq, wk, wv, wo, ff1_w, ff2_w, proj);

    for (int l = 0; l < DEPTH; l++) {
        size_t wb = (size_t)l*WT_LAYER;

        k_ln<<<BSR/8, 256>>>(ph, ln1_g + l*DIMC, ln1_b + l*DIMC, yh, yl);

        k_mmaqkv64<<<dim3(48,64), 256, SMEM_QKVFF>>>(yh, yl, wth+wb+WT_Q, wtl+wb+WT_Q);

        // merged Q/K feature GEMMs (x==0: K, x==1: Q)
        k_mmaF<<<dim3(2,512), 256, SMEM_MMA>>>(knh, knl, qnh, qnl,
                                               wth+wb+WT_PJ, wtl+wb+WT_PJ,
                                               pkp, qp_h, qp_l, pbm);

        k_chunk<<<NBH*NC, 512, SMEM_CHUNK>>>(qp_h, qp_l);
        k_prefix<<<dim3(NBH, 8), 256>>>();
        k_cross<<<NBH*NC, 512, SMEM_CROSS>>>(qp_h, qp_l);

        k_mma64<<<dim3(1,BSR/64), 256, SMEM_MMA64>>>(oh, ol, INNER, wth+wb+WT_O, wtl+wb+WT_O, INNER,
                                                     wo_b + l*DIMC, ph);

        k_ln<<<BSR/8, 256>>>(ph, ln2_g + l*DIMC, ln2_b + l*DIMC, yh, yl);
        k_ff1<<<dim3(8,64), 256, SMEM_QKVFF>>>(yh, yl, wth+wb+WT_F1, wtl+wb+WT_F1, ff1_b + l*FFD);
        k_mma64<<<dim3(1,BSR/64), 256, SMEM_MMA64>>>(fh, fl, FFD, wth+wb+WT_F2, wtl+wb+WT_F2, FFD,
                                                     ff2_b + l*DIMC, ph);
    }

    k_pool<<<dim3(BB, 16), 128>>>();
    k_final<<<1, 128>>>(fin_w, fin_b, out);
}